// round 3
// baseline (speedup 1.0000x reference)
#include <cuda_runtime.h>
#include <cuda_bf16.h>
#include <math.h>
#include <stdint.h>

#define Bn 4
#define Cn 512
#define Ln 4096
#define CKn 64
#define CGn 256

// Scratch (allocation-free rule: static __device__ arrays)
__device__ __nv_bfloat16 g_th_hi[Bn * Ln * CKn];
__device__ __nv_bfloat16 g_th_lo[Bn * Ln * CKn];
__device__ __nv_bfloat16 g_ph_hi[Bn * Ln * CKn];
__device__ __nv_bfloat16 g_ph_lo[Bn * Ln * CKn];
__device__ float g_gv[Bn * Ln * CGn];
__device__ __nv_bfloat16 g_gt_hi[Bn * CGn * Ln];
__device__ __nv_bfloat16 g_gt_lo[Bn * CGn * Ln];
__device__ float g_S[(size_t)Bn * Ln * Ln];              // fp32 scores
__device__ __nv_bfloat16 g_P_hi[(size_t)Bn * Ln * Ln];   // exp(S-max) hi
__device__ __nv_bfloat16 g_P_lo[(size_t)Bn * Ln * Ln];   // exp(S-max) lo
__device__ float g_colmax[Bn * 32 * Ln];
__device__ float g_colinv[Bn * Ln];
__device__ float g_ag[Bn * Ln * CGn];

__device__ __forceinline__ uint32_t smem_u32(const void* p) {
    uint32_t a;
    asm("{ .reg .u64 t; cvta.to.shared.u64 t, %1; cvt.u32.u64 %0, t; }" : "=r"(a) : "l"(p));
    return a;
}

#define LDSM_X4(r0, r1, r2, r3, addr) \
    asm volatile("ldmatrix.sync.aligned.m8n8.x4.shared.b16 {%0,%1,%2,%3}, [%4];" \
                 : "=r"(r0), "=r"(r1), "=r"(r2), "=r"(r3) : "r"(addr))

#define MMA_BF16(d, a, b0, b1) \
    asm volatile("mma.sync.aligned.m16n8k16.row.col.f32.bf16.bf16.f32 " \
                 "{%0,%1,%2,%3},{%4,%5,%6,%7},{%8,%9},{%0,%1,%2,%3};" \
                 : "+f"((d)[0]), "+f"((d)[1]), "+f"((d)[2]), "+f"((d)[3]) \
                 : "r"((a)[0]), "r"((a)[1]), "r"((a)[2]), "r"((a)[3]), "r"(b0), "r"(b1))

__device__ __forceinline__ void split_bf16(float f, __nv_bfloat16& hi, __nv_bfloat16& lo) {
    hi = __float2bfloat16(f);
    lo = __float2bfloat16(f - __bfloat162float(hi));
}

// ===========================================================================
// K1: fused theta/phi/g projections. theta/phi -> bf16 hi/lo, g -> fp32.
// ===========================================================================
__global__ void proj_kernel(const float* __restrict__ x,
                            const float* __restrict__ Wt, const float* __restrict__ bt,
                            const float* __restrict__ Wp, const float* __restrict__ bp,
                            const float* __restrict__ Wg, const float* __restrict__ bg) {
    int m0 = blockIdx.x * 64;
    int grp = blockIdx.y;
    int b = blockIdx.z;
    int tid = threadIdx.x;
    int tx = tid & 15, ty = tid >> 4;

    const float* W; const float* bias;
    if (grp == 0)      { W = Wt; bias = bt; }
    else if (grp == 1) { W = Wp; bias = bp; }
    else { W = Wg + (size_t)(grp - 2) * 64 * Cn; bias = bg + (grp - 2) * 64; }

    __shared__ float xs[32][64];
    __shared__ float ws[64][33];

    float acc[4][4];
#pragma unroll
    for (int i = 0; i < 4; i++)
#pragma unroll
        for (int j = 0; j < 4; j++) acc[i][j] = 0.f;

    const float* xb = x + (size_t)b * Cn * Ln;

    for (int k0 = 0; k0 < Cn; k0 += 32) {
#pragma unroll
        for (int i = 0; i < 8; i++) {
            int idx = tid + i * 256;
            int r = idx >> 6, c = idx & 63;
            xs[r][c] = xb[(size_t)(k0 + r) * Ln + m0 + c];
        }
#pragma unroll
        for (int i = 0; i < 8; i++) {
            int idx = tid + i * 256;
            int r = idx >> 5, c = idx & 31;
            ws[r][c] = W[(size_t)r * Cn + k0 + c];
        }
        __syncthreads();
#pragma unroll
        for (int kk = 0; kk < 32; kk++) {
            float a[4], w[4];
#pragma unroll
            for (int i = 0; i < 4; i++) a[i] = xs[kk][ty * 4 + i];
#pragma unroll
            for (int j = 0; j < 4; j++) w[j] = ws[tx * 4 + j][kk];
#pragma unroll
            for (int i = 0; i < 4; i++)
#pragma unroll
                for (int j = 0; j < 4; j++) acc[i][j] += a[i] * w[j];
        }
        __syncthreads();
    }

    if (grp <= 1) {
        __nv_bfloat16* ohi = (grp == 0 ? g_th_hi : g_ph_hi) + (size_t)b * Ln * CKn;
        __nv_bfloat16* olo = (grp == 0 ? g_th_lo : g_ph_lo) + (size_t)b * Ln * CKn;
#pragma unroll
        for (int j = 0; j < 4; j++) {
            float bv = bias[tx * 4 + j];
#pragma unroll
            for (int i = 0; i < 4; i++) {
                float v = tanhf(acc[i][j] + bv);
                __nv_bfloat16 hi, lo;
                split_bf16(v, hi, lo);
                size_t o = (size_t)(m0 + ty * 4 + i) * CKn + tx * 4 + j;
                ohi[o] = hi; olo[o] = lo;
            }
        }
    } else {
        float* outp = g_gv + (size_t)b * Ln * CGn;
        int ob = (grp - 2) * 64;
#pragma unroll
        for (int j = 0; j < 4; j++) {
            float bv = bias[tx * 4 + j];
#pragma unroll
            for (int i = 0; i < 4; i++)
                outp[(size_t)(m0 + ty * 4 + i) * CGn + ob + tx * 4 + j] = acc[i][j] + bv;
        }
    }
}

// ===========================================================================
// K2: scores via bf16x3 mma.sync. 128(l) x 128(m) tile, K=64 one-shot.
// smem rows padded to 144B (conflict-free ldmatrix). Epilogue stages through
// smem for coalesced fp32 S writes + per-tile column max.
// ===========================================================================
#define SC_A_HI 0
#define SC_A_LO 18432
#define SC_B_HI 36864
#define SC_B_LO 55296
#define SC_SMEM 73728

__global__ void __launch_bounds__(256, 1) scores_mma() {
    extern __shared__ char sm[];
    uint32_t sb = smem_u32(sm);
    int tid = threadIdx.x;
    int lane = tid & 31, wid = tid >> 5;
    int warp_m = wid & 3, warp_n = wid >> 2;      // 4x2 warps, each 32(m) x 64(n)
    int m0 = blockIdx.x * 128, l0 = blockIdx.y * 128, b = blockIdx.z;

    // Load theta(A, rows=l) and phi(B, rows=m), bf16 hi/lo, 64 k per row.
    const __nv_bfloat16* thh = g_th_hi + (size_t)b * Ln * CKn;
    const __nv_bfloat16* thl = g_th_lo + (size_t)b * Ln * CKn;
    const __nv_bfloat16* phh = g_ph_hi + (size_t)b * Ln * CKn;
    const __nv_bfloat16* phl = g_ph_lo + (size_t)b * Ln * CKn;
#pragma unroll
    for (int t = 0; t < 4; t++) {
        int idx = tid + t * 256;
        int r = idx >> 3, q = idx & 7;
        uint32_t so = r * 144 + q * 16;
        size_t ga = (size_t)(l0 + r) * CKn + q * 8;
        size_t gb = (size_t)(m0 + r) * CKn + q * 8;
        *(uint4*)(sm + SC_A_HI + so) = *(const uint4*)(thh + ga);
        *(uint4*)(sm + SC_A_LO + so) = *(const uint4*)(thl + ga);
        *(uint4*)(sm + SC_B_HI + so) = *(const uint4*)(phh + gb);
        *(uint4*)(sm + SC_B_LO + so) = *(const uint4*)(phl + gb);
    }
    __syncthreads();

    float acc[2][8][4];
#pragma unroll
    for (int mt = 0; mt < 2; mt++)
#pragma unroll
        for (int nt = 0; nt < 8; nt++)
#pragma unroll
            for (int j = 0; j < 4; j++) acc[mt][nt][j] = 0.f;

    int a_row_off = ((lane >> 3) & 1) * 8 + (lane & 7);
    int a_half = (lane >> 4) * 16;
    int b_row_off = (lane >> 4) * 8 + (lane & 7);
    int b_half = ((lane >> 3) & 1) * 16;

#pragma unroll
    for (int ks = 0; ks < 4; ks++) {
        int koff = ks * 32;
        uint32_t ah[2][4], al[2][4], bh[4][4], bl[4][4];
#pragma unroll
        for (int mt = 0; mt < 2; mt++) {
            uint32_t row = warp_m * 32 + mt * 16 + a_row_off;
            uint32_t ad = sb + row * 144 + koff + a_half;
            LDSM_X4(ah[mt][0], ah[mt][1], ah[mt][2], ah[mt][3], ad + SC_A_HI);
            LDSM_X4(al[mt][0], al[mt][1], al[mt][2], al[mt][3], ad + SC_A_LO);
        }
#pragma unroll
        for (int np = 0; np < 4; np++) {
            uint32_t row = warp_n * 64 + np * 16 + b_row_off;
            uint32_t ad = sb + row * 144 + koff + b_half;
            LDSM_X4(bh[np][0], bh[np][1], bh[np][2], bh[np][3], ad + SC_B_HI);
            LDSM_X4(bl[np][0], bl[np][1], bl[np][2], bl[np][3], ad + SC_B_LO);
        }
#pragma unroll
        for (int mt = 0; mt < 2; mt++)
#pragma unroll
            for (int np = 0; np < 4; np++) {
                MMA_BF16(acc[mt][2 * np],     ah[mt], bh[np][0], bh[np][1]);
                MMA_BF16(acc[mt][2 * np],     ah[mt], bl[np][0], bl[np][1]);
                MMA_BF16(acc[mt][2 * np],     al[mt], bh[np][0], bh[np][1]);
                MMA_BF16(acc[mt][2 * np + 1], ah[mt], bh[np][2], bh[np][3]);
                MMA_BF16(acc[mt][2 * np + 1], ah[mt], bl[np][2], bl[np][3]);
                MMA_BF16(acc[mt][2 * np + 1], al[mt], bh[np][2], bh[np][3]);
            }
    }
    __syncthreads();   // operands consumed; reuse smem for staging

    float* stg = (float*)sm;   // [128][132]
#pragma unroll
    for (int mt = 0; mt < 2; mt++)
#pragma unroll
        for (int nt = 0; nt < 8; nt++) {
            int r = warp_m * 32 + mt * 16 + (lane >> 2);
            int c = warp_n * 64 + nt * 8 + 2 * (lane & 3);
            stg[r * 132 + c] = acc[mt][nt][0];
            stg[r * 132 + c + 1] = acc[mt][nt][1];
            stg[(r + 8) * 132 + c] = acc[mt][nt][2];
            stg[(r + 8) * 132 + c + 1] = acc[mt][nt][3];
        }
    __syncthreads();

    int c = tid & 127, h = tid >> 7;
    float mx = -1e30f;
    float* Sb = g_S + (size_t)b * Ln * Ln + (size_t)l0 * Ln + m0;
    for (int rr = 0; rr < 64; rr++) {
        int r = h * 64 + rr;
        float v = stg[r * 132 + c];
        mx = fmaxf(mx, v);
        Sb[(size_t)r * Ln + c] = v;
    }
    float* mxbuf = (float*)(sm + 67584);
    mxbuf[h * 128 + c] = mx;
    __syncthreads();
    if (tid < 128) {
        float m2 = fmaxf(mxbuf[tid], mxbuf[128 + tid]);
        g_colmax[((size_t)b * 32 + blockIdx.y) * Ln + m0 + tid] = m2;
    }
}

// ===========================================================================
// K3: column softmax: reduce partial maxes, exp, write P as bf16 hi/lo.
// ===========================================================================
__global__ void colstats2_kernel() {
    int b = blockIdx.y;
    int m = blockIdx.x * 256 + threadIdx.x;
    float mx = -1e30f;
#pragma unroll
    for (int i = 0; i < 32; i++)
        mx = fmaxf(mx, g_colmax[((size_t)b * 32 + i) * Ln + m]);
    const float* Sb = g_S + (size_t)b * Ln * Ln;
    __nv_bfloat16* Ph = g_P_hi + (size_t)b * Ln * Ln;
    __nv_bfloat16* Pl = g_P_lo + (size_t)b * Ln * Ln;
    float sum = 0.f;
    for (int l = 0; l < Ln; l += 4) {
        size_t base = (size_t)l * Ln + m;
#pragma unroll
        for (int j = 0; j < 4; j++) {
            float e = __expf(Sb[base + (size_t)j * Ln] - mx);
            sum += e;
            __nv_bfloat16 hi, lo;
            split_bf16(e, hi, lo);
            Ph[base + (size_t)j * Ln] = hi;
            Pl[base + (size_t)j * Ln] = lo;
        }
    }
    g_colinv[b * Ln + m] = 1.0f / sum;
}

// ===========================================================================
// K3b: gT[c][m] = g[m][c] * colinv[m], split to bf16 hi/lo.
// ===========================================================================
__global__ void transpose_scale_kernel() {
    __shared__ float t[32][33];
    int m0 = blockIdx.x * 32, c0 = blockIdx.y * 32, b = blockIdx.z;
    int tx = threadIdx.x, ty = threadIdx.y;
#pragma unroll
    for (int i = 0; i < 32; i += 8) {
        int m = m0 + ty + i;
        t[ty + i][tx] = g_gv[((size_t)b * Ln + m) * CGn + c0 + tx] * g_colinv[b * Ln + m];
    }
    __syncthreads();
#pragma unroll
    for (int i = 0; i < 32; i += 8) {
        float v = t[tx][ty + i];
        __nv_bfloat16 hi, lo;
        split_bf16(v, hi, lo);
        size_t o = ((size_t)b * CGn + c0 + ty + i) * Ln + m0 + tx;
        g_gt_hi[o] = hi;
        g_gt_lo[o] = lo;
    }
}

// ===========================================================================
// K4: AG = P @ gT' via bf16x3 mma.sync, K=4096 double-buffered (chunks of 32).
// Tile 128(l) x 128(c). smem rows padded to 80B. grid (2, 32, 4).
// ===========================================================================
#define AG_BUF 40960
#define AG_A_HI 0
#define AG_A_LO 10240
#define AG_B_HI 20480
#define AG_B_LO 30720
#define AG_SMEM (2 * AG_BUF)

__global__ void __launch_bounds__(256, 1) attng_mma() {
    extern __shared__ char sm[];
    uint32_t sb = smem_u32(sm);
    int tid = threadIdx.x;
    int lane = tid & 31, wid = tid >> 5;
    int warp_m = wid & 3, warp_n = wid >> 2;
    int c0 = blockIdx.x * 128, l0 = blockIdx.y * 128, b = blockIdx.z;

    const __nv_bfloat16* Ph = g_P_hi + (size_t)b * Ln * Ln + (size_t)l0 * Ln;
    const __nv_bfloat16* Pl = g_P_lo + (size_t)b * Ln * Ln + (size_t)l0 * Ln;
    const __nv_bfloat16* Gh = g_gt_hi + ((size_t)b * CGn + c0) * Ln;
    const __nv_bfloat16* Gl = g_gt_lo + ((size_t)b * CGn + c0) * Ln;

    int r_ld = 0, q_ld = 0;
    // each thread loads 2 uint4 per array per chunk: idx = tid + t*256
    uint4 rAh[2], rAl[2], rBh[2], rBl[2];

    // prologue: chunk 0 -> regs -> buf0 ; chunk 1 -> regs
#pragma unroll
    for (int t = 0; t < 2; t++) {
        int idx = tid + t * 256;
        int r = idx >> 2, q = idx & 3;
        size_t ga = (size_t)r * Ln + q * 8;
        rAh[t] = *(const uint4*)(Ph + ga); rAl[t] = *(const uint4*)(Pl + ga);
        rBh[t] = *(const uint4*)(Gh + ga); rBl[t] = *(const uint4*)(Gl + ga);
        uint32_t so = r * 80 + q * 16;
        *(uint4*)(sm + AG_A_HI + so) = rAh[t];
        *(uint4*)(sm + AG_A_LO + so) = rAl[t];
        *(uint4*)(sm + AG_B_HI + so) = rBh[t];
        *(uint4*)(sm + AG_B_LO + so) = rBl[t];
    }
#pragma unroll
    for (int t = 0; t < 2; t++) {
        int idx = tid + t * 256;
        int r = idx >> 2, q = idx & 3;
        size_t ga = (size_t)r * Ln + 32 + q * 8;
        rAh[t] = *(const uint4*)(Ph + ga); rAl[t] = *(const uint4*)(Pl + ga);
        rBh[t] = *(const uint4*)(Gh + ga); rBl[t] = *(const uint4*)(Gl + ga);
    }
    __syncthreads();

    float acc[2][8][4];
#pragma unroll
    for (int mt = 0; mt < 2; mt++)
#pragma unroll
        for (int nt = 0; nt < 8; nt++)
#pragma unroll
            for (int j = 0; j < 4; j++) acc[mt][nt][j] = 0.f;

    int a_row_off = ((lane >> 3) & 1) * 8 + (lane & 7);
    int a_half = (lane >> 4) * 16;
    int b_row_off = (lane >> 4) * 8 + (lane & 7);
    int b_half = ((lane >> 3) & 1) * 16;

    for (int k = 0; k < Ln / 32; k++) {
        int s = k & 1;
        uint32_t cur = sb + (uint32_t)s * AG_BUF;
        // stage chunk k+1 into other buffer (regs already loaded)
        if (k + 1 < Ln / 32) {
            uint32_t nxt = (uint32_t)((1 - s) * AG_BUF);
#pragma unroll
            for (int t = 0; t < 2; t++) {
                int idx = tid + t * 256;
                int r = idx >> 2, q = idx & 3;
                uint32_t so = nxt + r * 80 + q * 16;
                *(uint4*)(sm + AG_A_HI + so) = rAh[t];
                *(uint4*)(sm + AG_A_LO + so) = rAl[t];
                *(uint4*)(sm + AG_B_HI + so) = rBh[t];
                *(uint4*)(sm + AG_B_LO + so) = rBl[t];
            }
        }
        // prefetch chunk k+2 into regs
        if (k + 2 < Ln / 32) {
            int k0 = (k + 2) * 32;
#pragma unroll
            for (int t = 0; t < 2; t++) {
                int idx = tid + t * 256;
                int r = idx >> 2, q = idx & 3;
                size_t ga = (size_t)r * Ln + k0 + q * 8;
                rAh[t] = *(const uint4*)(Ph + ga); rAl[t] = *(const uint4*)(Pl + ga);
                rBh[t] = *(const uint4*)(Gh + ga); rBl[t] = *(const uint4*)(Gl + ga);
            }
        }
        // consume buffer s (chunk k): 2 k16 steps
#pragma unroll
        for (int ks = 0; ks < 2; ks++) {
            int koff = ks * 32;
            uint32_t ah[2][4], al[2][4], bh[4][4], bl[4][4];
#pragma unroll
            for (int mt = 0; mt < 2; mt++) {
                uint32_t row = warp_m * 32 + mt * 16 + a_row_off;
                uint32_t ad = cur + row * 80 + koff + a_half;
                LDSM_X4(ah[mt][0], ah[mt][1], ah[mt][2], ah[mt][3], ad + AG_A_HI);
                LDSM_X4(al[mt][0], al[mt][1], al[mt][2], al[mt][3], ad + AG_A_LO);
            }
#pragma unroll
            for (int np = 0; np < 4; np++) {
                uint32_t row = warp_n * 64 + np * 16 + b_row_off;
                uint32_t ad = cur + row * 80 + koff + b_half;
                LDSM_X4(bh[np][0], bh[np][1], bh[np][2], bh[np][3], ad + AG_B_HI);
                LDSM_X4(bl[np][0], bl[np][1], bl[np][2], bl[np][3], ad + AG_B_LO);
            }
#pragma unroll
            for (int mt = 0; mt < 2; mt++)
#pragma unroll
                for (int np = 0; np < 4; np++) {
                    MMA_BF16(acc[mt][2 * np],     ah[mt], bh[np][0], bh[np][1]);
                    MMA_BF16(acc[mt][2 * np],     ah[mt], bl[np][0], bl[np][1]);
                    MMA_BF16(acc[mt][2 * np],     al[mt], bh[np][0], bh[np][1]);
                    MMA_BF16(acc[mt][2 * np + 1], ah[mt], bh[np][2], bh[np][3]);
                    MMA_BF16(acc[mt][2 * np + 1], ah[mt], bl[np][2], bl[np][3]);
                    MMA_BF16(acc[mt][2 * np + 1], al[mt], bh[np][2], bh[np][3]);
                }
        }
        __syncthreads();
    }

    float* ag = g_ag + (size_t)b * Ln * CGn;
#pragma unroll
    for (int mt = 0; mt < 2; mt++)
#pragma unroll
        for (int nt = 0; nt < 8; nt++) {
            int r = l0 + warp_m * 32 + mt * 16 + (lane >> 2);
            int c = c0 + warp_n * 64 + nt * 8 + 2 * (lane & 3);
            float2 v0 = make_float2(acc[mt][nt][0], acc[mt][nt][1]);
            float2 v1 = make_float2(acc[mt][nt][2], acc[mt][nt][3]);
            *(float2*)&ag[(size_t)r * CGn + c] = v0;
            *(float2*)&ag[(size_t)(r + 8) * CGn + c] = v1;
        }
}

// ===========================================================================
// K5: out-projection + residual blend (SIMT, unchanged)
// ===========================================================================
__global__ void final_kernel(const float* __restrict__ x,
                             const float* __restrict__ Wo, const float* __restrict__ bo,
                             const float* __restrict__ gamma, float* __restrict__ out) {
    int l0 = blockIdx.x * 64;
    int c0 = blockIdx.y * 64;
    int b = blockIdx.z;
    int tid = threadIdx.x;
    int tx = tid & 15, ty = tid >> 4;

    __shared__ float as_[64][65];
    __shared__ float ws[64][65];

    const float* ag = g_ag + (size_t)b * Ln * CGn;
    float acc[4][4] = {};
    for (int k0 = 0; k0 < CGn; k0 += 64) {
#pragma unroll
        for (int i = 0; i < 16; i++) {
            int idx = tid + i * 256;
            int r = idx >> 6, k = idx & 63;
            as_[r][k] = ag[(size_t)(l0 + r) * CGn + k0 + k];
            ws[r][k] = Wo[(size_t)(c0 + r) * CGn + k0 + k];
        }
        __syncthreads();
#pragma unroll
        for (int kk = 0; kk < 64; kk++) {
            float av[4], wv[4];
#pragma unroll
            for (int j = 0; j < 4; j++) av[j] = as_[tx * 4 + j][kk];
#pragma unroll
            for (int i = 0; i < 4; i++) wv[i] = ws[ty * 4 + i][kk];
#pragma unroll
            for (int i = 0; i < 4; i++)
#pragma unroll
                for (int j = 0; j < 4; j++) acc[i][j] += wv[i] * av[j];
        }
        __syncthreads();
    }
    float gv = gamma[0];
    float alpha = 1.0f / (1.0f + __expf(-gv));
    float* out1 = out;
    float* out2 = out + (size_t)Bn * Cn * Ln;
#pragma unroll
    for (int i = 0; i < 4; i++) {
        int c2 = c0 + ty * 4 + i;
        float bv = bo[c2];
        size_t base = (size_t)b * Cn * Ln + (size_t)c2 * Ln + l0 + tx * 4;
        float4 xv = *reinterpret_cast<const float4*>(&x[base]);
        float4 v;
        v.x = acc[i][0] + bv; v.y = acc[i][1] + bv;
        v.z = acc[i][2] + bv; v.w = acc[i][3] + bv;
        *reinterpret_cast<float4*>(&out2[base]) = v;
        float4 o1;
        o1.x = (1.f - alpha) * xv.x + alpha * v.x;
        o1.y = (1.f - alpha) * xv.y + alpha * v.y;
        o1.z = (1.f - alpha) * xv.z + alpha * v.z;
        o1.w = (1.f - alpha) * xv.w + alpha * v.w;
        *reinterpret_cast<float4*>(&out1[base]) = o1;
    }
}

extern "C" void kernel_launch(void* const* d_in, const int* in_sizes, int n_in,
                              void* d_out, int out_size) {
    const float* x     = (const float*)d_in[0];
    const float* Wt    = (const float*)d_in[1];
    const float* bt    = (const float*)d_in[2];
    const float* Wp    = (const float*)d_in[3];
    const float* bp    = (const float*)d_in[4];
    const float* Wg    = (const float*)d_in[5];
    const float* bg    = (const float*)d_in[6];
    const float* Wo    = (const float*)d_in[7];
    const float* bo    = (const float*)d_in[8];
    const float* gamma = (const float*)d_in[9];
    float* out = (float*)d_out;

    cudaFuncSetAttribute(scores_mma, cudaFuncAttributeMaxDynamicSharedMemorySize, SC_SMEM);
    cudaFuncSetAttribute(attng_mma, cudaFuncAttributeMaxDynamicSharedMemorySize, AG_SMEM);

    proj_kernel<<<dim3(Ln / 64, 6, Bn), 256>>>(x, Wt, bt, Wp, bp, Wg, bg);
    scores_mma<<<dim3(Ln / 128, Ln / 128, Bn), 256, SC_SMEM>>>();
    colstats2_kernel<<<dim3(Ln / 256, Bn), 256>>>();
    transpose_scale_kernel<<<dim3(Ln / 32, CGn / 32, Bn), dim3(32, 8)>>>();
    attng_mma<<<dim3(2, Ln / 128, Bn), 256, AG_SMEM>>>();
    final_kernel<<<dim3(Ln / 64, Cn / 64, Bn), 256>>>(x, Wo, bo, gamma, out);
}

// round 4
// speedup vs baseline: 2.8447x; 2.8447x over previous
#include <cuda_runtime.h>
#include <cuda_bf16.h>
#include <math.h>
#include <stdint.h>

#define Bn 4
#define Cn 512
#define Ln 4096
#define CKn 64
#define CGn 256

// Scratch (allocation-free rule: static __device__ arrays)
__device__ __nv_bfloat16 g_th_hi[Bn * Ln * CKn];
__device__ __nv_bfloat16 g_th_lo[Bn * Ln * CKn];
__device__ __nv_bfloat16 g_ph_hi[Bn * Ln * CKn];
__device__ __nv_bfloat16 g_ph_lo[Bn * Ln * CKn];
__device__ float g_gv[Bn * Ln * CGn];
__device__ __nv_bfloat16 g_gt_hi[Bn * CGn * Ln];
__device__ __nv_bfloat16 g_gt_lo[Bn * CGn * Ln];
__device__ float g_colmax[Bn * Ln];
__device__ float g_colinv[Bn * Ln];
__device__ float g_ag[Bn * Ln * CGn];

__device__ __forceinline__ uint32_t smem_u32(const void* p) {
    uint32_t a;
    asm("{ .reg .u64 t; cvta.to.shared.u64 t, %1; cvt.u32.u64 %0, t; }" : "=r"(a) : "l"(p));
    return a;
}

#define LDSM_X4(r0, r1, r2, r3, addr) \
    asm volatile("ldmatrix.sync.aligned.m8n8.x4.shared.b16 {%0,%1,%2,%3}, [%4];" \
                 : "=r"(r0), "=r"(r1), "=r"(r2), "=r"(r3) : "r"(addr))

#define MMA_BF16(d, a, b0, b1) \
    asm volatile("mma.sync.aligned.m16n8k16.row.col.f32.bf16.bf16.f32 " \
                 "{%0,%1,%2,%3},{%4,%5,%6,%7},{%8,%9},{%0,%1,%2,%3};" \
                 : "+f"((d)[0]), "+f"((d)[1]), "+f"((d)[2]), "+f"((d)[3]) \
                 : "r"((a)[0]), "r"((a)[1]), "r"((a)[2]), "r"((a)[3]), "r"(b0), "r"(b1))

#define CP_ASYNC16(smem, gptr) \
    asm volatile("cp.async.cg.shared.global [%0], [%1], 16;" :: "r"(smem), "l"(gptr))
#define CP_COMMIT() asm volatile("cp.async.commit_group;")
#define CP_WAIT0()  asm volatile("cp.async.wait_group 0;")

__device__ __forceinline__ void split_bf16(float f, __nv_bfloat16& hi, __nv_bfloat16& lo) {
    hi = __float2bfloat16(f);
    lo = __float2bfloat16(f - __bfloat162float(hi));
}

// ===========================================================================
// K1: fused theta/phi/g projections. theta/phi -> bf16 hi/lo, g -> fp32.
// ===========================================================================
__global__ void proj_kernel(const float* __restrict__ x,
                            const float* __restrict__ Wt, const float* __restrict__ bt,
                            const float* __restrict__ Wp, const float* __restrict__ bp,
                            const float* __restrict__ Wg, const float* __restrict__ bg) {
    int m0 = blockIdx.x * 64;
    int grp = blockIdx.y;
    int b = blockIdx.z;
    int tid = threadIdx.x;
    int tx = tid & 15, ty = tid >> 4;

    const float* W; const float* bias;
    if (grp == 0)      { W = Wt; bias = bt; }
    else if (grp == 1) { W = Wp; bias = bp; }
    else { W = Wg + (size_t)(grp - 2) * 64 * Cn; bias = bg + (grp - 2) * 64; }

    __shared__ float xs[32][64];
    __shared__ float ws[64][33];

    float acc[4][4];
#pragma unroll
    for (int i = 0; i < 4; i++)
#pragma unroll
        for (int j = 0; j < 4; j++) acc[i][j] = 0.f;

    const float* xb = x + (size_t)b * Cn * Ln;

    for (int k0 = 0; k0 < Cn; k0 += 32) {
#pragma unroll
        for (int i = 0; i < 8; i++) {
            int idx = tid + i * 256;
            int r = idx >> 6, c = idx & 63;
            xs[r][c] = xb[(size_t)(k0 + r) * Ln + m0 + c];
        }
#pragma unroll
        for (int i = 0; i < 8; i++) {
            int idx = tid + i * 256;
            int r = idx >> 5, c = idx & 31;
            ws[r][c] = W[(size_t)r * Cn + k0 + c];
        }
        __syncthreads();
#pragma unroll
        for (int kk = 0; kk < 32; kk++) {
            float a[4], w[4];
#pragma unroll
            for (int i = 0; i < 4; i++) a[i] = xs[kk][ty * 4 + i];
#pragma unroll
            for (int j = 0; j < 4; j++) w[j] = ws[tx * 4 + j][kk];
#pragma unroll
            for (int i = 0; i < 4; i++)
#pragma unroll
                for (int j = 0; j < 4; j++) acc[i][j] += a[i] * w[j];
        }
        __syncthreads();
    }

    if (grp <= 1) {
        __nv_bfloat16* ohi = (grp == 0 ? g_th_hi : g_ph_hi) + (size_t)b * Ln * CKn;
        __nv_bfloat16* olo = (grp == 0 ? g_th_lo : g_ph_lo) + (size_t)b * Ln * CKn;
#pragma unroll
        for (int j = 0; j < 4; j++) {
            float bv = bias[tx * 4 + j];
#pragma unroll
            for (int i = 0; i < 4; i++) {
                float v = tanhf(acc[i][j] + bv);
                __nv_bfloat16 hi, lo;
                split_bf16(v, hi, lo);
                size_t o = (size_t)(m0 + ty * 4 + i) * CKn + tx * 4 + j;
                ohi[o] = hi; olo[o] = lo;
            }
        }
    } else {
        float* outp = g_gv + (size_t)b * Ln * CGn;
        int ob = (grp - 2) * 64;
#pragma unroll
        for (int j = 0; j < 4; j++) {
            float bv = bias[tx * 4 + j];
#pragma unroll
            for (int i = 0; i < 4; i++)
                outp[(size_t)(m0 + ty * 4 + i) * CGn + ob + tx * 4 + j] = acc[i][j] + bv;
        }
    }
}

// ===========================================================================
// K2: softstats — per-column (m) online max+sum of exp over all l.
// CTA owns an m-tile of 128; loops over 32 l-chunks recomputing S via bf16x3.
// SMEM: PH_HI 0, PH_LO 18432, TH_HI 36864, TH_LO 55296, WMX 73728, WSM 75776
// ===========================================================================
#define S1_PH_HI 0
#define S1_PH_LO 18432
#define S1_TH_HI 36864
#define S1_TH_LO 55296
#define S1_WMX   73728
#define S1_WSM   75776
#define S1_SMEM  77824

__global__ void __launch_bounds__(256, 1) softstats_kernel() {
    extern __shared__ char sm[];
    uint32_t sb = smem_u32(sm);
    int tid = threadIdx.x;
    int lane = tid & 31, wid = tid >> 5;
    int warp_m = wid & 3, warp_n = wid >> 2;
    int m0 = blockIdx.x * 128, b = blockIdx.y;

    const __nv_bfloat16* thh = g_th_hi + (size_t)b * Ln * CKn;
    const __nv_bfloat16* thl = g_th_lo + (size_t)b * Ln * CKn;
    const __nv_bfloat16* phh = g_ph_hi + (size_t)b * Ln * CKn;
    const __nv_bfloat16* phl = g_ph_lo + (size_t)b * Ln * CKn;

    // phi m-tile (B operand), rows m0..m0+128, 64 k, stride 144
#pragma unroll
    for (int t = 0; t < 4; t++) {
        int idx = tid + t * 256;
        int r = idx >> 3, q = idx & 7;
        uint32_t so = r * 144 + q * 16;
        size_t ga = ((size_t)(m0 + r)) * CKn + q * 8;
        *(uint4*)(sm + S1_PH_HI + so) = *(const uint4*)(phh + ga);
        *(uint4*)(sm + S1_PH_LO + so) = *(const uint4*)(phl + ga);
    }

    float mx[16], sum[16];
#pragma unroll
    for (int i = 0; i < 16; i++) { mx[i] = -1e30f; sum[i] = 0.f; }

    int a_row_off = ((lane >> 3) & 1) * 8 + (lane & 7);
    int a_half = (lane >> 4) * 16;
    int b_row_off = (lane >> 4) * 8 + (lane & 7);
    int b_half = ((lane >> 3) & 1) * 16;

    for (int lc = 0; lc < 32; lc++) {
        int l0 = lc * 128;
#pragma unroll
        for (int t = 0; t < 4; t++) {
            int idx = tid + t * 256;
            int r = idx >> 3, q = idx & 7;
            uint32_t so = r * 144 + q * 16;
            size_t ga = ((size_t)(l0 + r)) * CKn + q * 8;
            *(uint4*)(sm + S1_TH_HI + so) = *(const uint4*)(thh + ga);
            *(uint4*)(sm + S1_TH_LO + so) = *(const uint4*)(thl + ga);
        }
        __syncthreads();

        float acc[2][8][4];
#pragma unroll
        for (int mt = 0; mt < 2; mt++)
#pragma unroll
            for (int nt = 0; nt < 8; nt++)
#pragma unroll
                for (int j = 0; j < 4; j++) acc[mt][nt][j] = 0.f;

#pragma unroll
        for (int ks = 0; ks < 4; ks++) {
            int koff = ks * 32;
            uint32_t ah[2][4], al[2][4], bh[4][4], bl[4][4];
#pragma unroll
            for (int mt = 0; mt < 2; mt++) {
                uint32_t row = warp_m * 32 + mt * 16 + a_row_off;
                uint32_t ad = sb + row * 144 + koff + a_half;
                LDSM_X4(ah[mt][0], ah[mt][1], ah[mt][2], ah[mt][3], ad + S1_TH_HI);
                LDSM_X4(al[mt][0], al[mt][1], al[mt][2], al[mt][3], ad + S1_TH_LO);
            }
#pragma unroll
            for (int np = 0; np < 4; np++) {
                uint32_t row = warp_n * 64 + np * 16 + b_row_off;
                uint32_t ad = sb + row * 144 + koff + b_half;
                LDSM_X4(bh[np][0], bh[np][1], bh[np][2], bh[np][3], ad + S1_PH_HI);
                LDSM_X4(bl[np][0], bl[np][1], bl[np][2], bl[np][3], ad + S1_PH_LO);
            }
#pragma unroll
            for (int mt = 0; mt < 2; mt++)
#pragma unroll
                for (int np = 0; np < 4; np++) {
                    MMA_BF16(acc[mt][2 * np],     ah[mt], bh[np][0], bh[np][1]);
                    MMA_BF16(acc[mt][2 * np],     ah[mt], bl[np][0], bl[np][1]);
                    MMA_BF16(acc[mt][2 * np],     al[mt], bh[np][0], bh[np][1]);
                    MMA_BF16(acc[mt][2 * np + 1], ah[mt], bh[np][2], bh[np][3]);
                    MMA_BF16(acc[mt][2 * np + 1], ah[mt], bl[np][2], bl[np][3]);
                    MMA_BF16(acc[mt][2 * np + 1], al[mt], bh[np][2], bh[np][3]);
                }
        }
        // online (max,sum) update per thread-column
#pragma unroll
        for (int nt = 0; nt < 8; nt++)
#pragma unroll
            for (int j = 0; j < 2; j++) {
                int ix = nt * 2 + j;
                float v0 = acc[0][nt][j], v1 = acc[0][nt][j + 2];
                float v2 = acc[1][nt][j], v3 = acc[1][nt][j + 2];
                float vm = fmaxf(fmaxf(v0, v1), fmaxf(v2, v3));
                float M = fmaxf(mx[ix], vm);
                sum[ix] = sum[ix] * __expf(mx[ix] - M)
                        + __expf(v0 - M) + __expf(v1 - M)
                        + __expf(v2 - M) + __expf(v3 - M);
                mx[ix] = M;
            }
        __syncthreads();
    }

    // cross-lane combine (lanes differing in lane>>2 share column)
#pragma unroll
    for (int s = 4; s <= 16; s <<= 1) {
#pragma unroll
        for (int i = 0; i < 16; i++) {
            float om = __shfl_xor_sync(0xffffffffu, mx[i], s);
            float os = __shfl_xor_sync(0xffffffffu, sum[i], s);
            float M = fmaxf(mx[i], om);
            sum[i] = sum[i] * __expf(mx[i] - M) + os * __expf(om - M);
            mx[i] = M;
        }
    }
    float* wmx = (float*)(sm + S1_WMX);
    float* wsm = (float*)(sm + S1_WSM);
    if (lane < 4) {
#pragma unroll
        for (int nt = 0; nt < 8; nt++)
#pragma unroll
            for (int j = 0; j < 2; j++) {
                int c = warp_n * 64 + nt * 8 + 2 * lane + j;
                wmx[warp_m * 128 + c] = mx[nt * 2 + j];
                wsm[warp_m * 128 + c] = sum[nt * 2 + j];
            }
    }
    __syncthreads();
    if (tid < 128) {
        float M = wmx[tid];
#pragma unroll
        for (int w = 1; w < 4; w++) M = fmaxf(M, wmx[w * 128 + tid]);
        float S = 0.f;
#pragma unroll
        for (int w = 0; w < 4; w++) S += wsm[w * 128 + tid] * __expf(wmx[w * 128 + tid] - M);
        g_colmax[b * Ln + m0 + tid] = M;
        g_colinv[b * Ln + m0 + tid] = 1.0f / S;
    }
}

// ===========================================================================
// K3: gT[c][m] = g[m][c] * colinv[m], split to bf16 hi/lo.
// ===========================================================================
__global__ void transpose_scale_kernel() {
    __shared__ float t[32][33];
    int m0 = blockIdx.x * 32, c0 = blockIdx.y * 32, b = blockIdx.z;
    int tx = threadIdx.x, ty = threadIdx.y;
#pragma unroll
    for (int i = 0; i < 32; i += 8) {
        int m = m0 + ty + i;
        t[ty + i][tx] = g_gv[((size_t)b * Ln + m) * CGn + c0 + tx] * g_colinv[b * Ln + m];
    }
    __syncthreads();
#pragma unroll
    for (int i = 0; i < 32; i += 8) {
        float v = t[tx][ty + i];
        __nv_bfloat16 hi, lo;
        split_bf16(v, hi, lo);
        size_t o = ((size_t)b * CGn + c0 + ty + i) * Ln + m0 + tx;
        g_gt_hi[o] = hi;
        g_gt_lo[o] = lo;
    }
}

// ===========================================================================
// K4: fused attention: per (l-tile 128, c-half 128): loop m-chunks:
//   GEMM1 S=theta@phi^T (bf16x3) -> exp(S - colmax) -> bf16 hi/lo in SMEM ->
//   GEMM2 AG += P @ gT^T (bf16x3), acc in registers. cp.async streams gT.
// ===========================================================================
#define F2_TH_HI 0
#define F2_TH_LO 18432
#define F2_PH_HI 36864
#define F2_PH_LO 55296
#define F2_PE_HI 73728
#define F2_PE_LO 108544
#define F2_GT_HI 143360
#define F2_GT_LO 178176
#define F2_CM    212992
#define F2_SMEM  213504

__global__ void __launch_bounds__(256, 1) attn_fused() {
    extern __shared__ char sm[];
    uint32_t sb = smem_u32(sm);
    int tid = threadIdx.x;
    int lane = tid & 31, wid = tid >> 5;
    int warp_m = wid & 3, warp_n = wid >> 2;
    int c0 = blockIdx.x * 128, l0 = blockIdx.y * 128, b = blockIdx.z;

    const __nv_bfloat16* thh = g_th_hi + (size_t)b * Ln * CKn;
    const __nv_bfloat16* thl = g_th_lo + (size_t)b * Ln * CKn;
    const __nv_bfloat16* phh = g_ph_hi + (size_t)b * Ln * CKn;
    const __nv_bfloat16* phl = g_ph_lo + (size_t)b * Ln * CKn;
    const __nv_bfloat16* Gh = g_gt_hi + ((size_t)b * CGn + c0) * Ln;
    const __nv_bfloat16* Gl = g_gt_lo + ((size_t)b * CGn + c0) * Ln;
    const float* cmax = g_colmax + b * Ln;

    // theta l-tile (A of GEMM1), loaded once
#pragma unroll
    for (int t = 0; t < 4; t++) {
        int idx = tid + t * 256;
        int r = idx >> 3, q = idx & 7;
        uint32_t so = r * 144 + q * 16;
        size_t ga = ((size_t)(l0 + r)) * CKn + q * 8;
        *(uint4*)(sm + F2_TH_HI + so) = *(const uint4*)(thh + ga);
        *(uint4*)(sm + F2_TH_LO + so) = *(const uint4*)(thl + ga);
    }

    float acc2[2][8][4];
#pragma unroll
    for (int mt = 0; mt < 2; mt++)
#pragma unroll
        for (int nt = 0; nt < 8; nt++)
#pragma unroll
            for (int j = 0; j < 4; j++) acc2[mt][nt][j] = 0.f;

    int a_row_off = ((lane >> 3) & 1) * 8 + (lane & 7);
    int a_half = (lane >> 4) * 16;
    int b_row_off = (lane >> 4) * 8 + (lane & 7);
    int b_half = ((lane >> 3) & 1) * 16;
    float* cm = (float*)(sm + F2_CM);

    for (int mc = 0; mc < 32; mc++) {
        int m0 = mc * 128;
        // cp.async gT chunk (B of GEMM2): 128 c-rows x 128 m, stride 272
#pragma unroll
        for (int t = 0; t < 8; t++) {
            int idx = tid + t * 256;
            int r = idx >> 4, q = idx & 15;
            uint32_t so = r * 272 + q * 16;
            const __nv_bfloat16* gp = Gh + (size_t)r * Ln + m0 + q * 8;
            const __nv_bfloat16* gq = Gl + (size_t)r * Ln + m0 + q * 8;
            CP_ASYNC16(sb + F2_GT_HI + so, gp);
            CP_ASYNC16(sb + F2_GT_LO + so, gq);
        }
        CP_COMMIT();
        // phi chunk (B of GEMM1)
#pragma unroll
        for (int t = 0; t < 4; t++) {
            int idx = tid + t * 256;
            int r = idx >> 3, q = idx & 7;
            uint32_t so = r * 144 + q * 16;
            size_t ga = ((size_t)(m0 + r)) * CKn + q * 8;
            *(uint4*)(sm + F2_PH_HI + so) = *(const uint4*)(phh + ga);
            *(uint4*)(sm + F2_PH_LO + so) = *(const uint4*)(phl + ga);
        }
        if (tid < 128) cm[tid] = cmax[m0 + tid];
        __syncthreads();

        // GEMM1: S tile (128l x 128m), K=64
        float acc1[2][8][4];
#pragma unroll
        for (int mt = 0; mt < 2; mt++)
#pragma unroll
            for (int nt = 0; nt < 8; nt++)
#pragma unroll
                for (int j = 0; j < 4; j++) acc1[mt][nt][j] = 0.f;

#pragma unroll
        for (int ks = 0; ks < 4; ks++) {
            int koff = ks * 32;
            uint32_t ah[2][4], al[2][4], bh[4][4], bl[4][4];
#pragma unroll
            for (int mt = 0; mt < 2; mt++) {
                uint32_t row = warp_m * 32 + mt * 16 + a_row_off;
                uint32_t ad = sb + row * 144 + koff + a_half;
                LDSM_X4(ah[mt][0], ah[mt][1], ah[mt][2], ah[mt][3], ad + F2_TH_HI);
                LDSM_X4(al[mt][0], al[mt][1], al[mt][2], al[mt][3], ad + F2_TH_LO);
            }
#pragma unroll
            for (int np = 0; np < 4; np++) {
                uint32_t row = warp_n * 64 + np * 16 + b_row_off;
                uint32_t ad = sb + row * 144 + koff + b_half;
                LDSM_X4(bh[np][0], bh[np][1], bh[np][2], bh[np][3], ad + F2_PH_HI);
                LDSM_X4(bl[np][0], bl[np][1], bl[np][2], bl[np][3], ad + F2_PH_LO);
            }
#pragma unroll
            for (int mt = 0; mt < 2; mt++)
#pragma unroll
                for (int np = 0; np < 4; np++) {
                    MMA_BF16(acc1[mt][2 * np],     ah[mt], bh[np][0], bh[np][1]);
                    MMA_BF16(acc1[mt][2 * np],     ah[mt], bl[np][0], bl[np][1]);
                    MMA_BF16(acc1[mt][2 * np],     al[mt], bh[np][0], bh[np][1]);
                    MMA_BF16(acc1[mt][2 * np + 1], ah[mt], bh[np][2], bh[np][3]);
                    MMA_BF16(acc1[mt][2 * np + 1], ah[mt], bl[np][2], bl[np][3]);
                    MMA_BF16(acc1[mt][2 * np + 1], al[mt], bh[np][2], bh[np][3]);
                }
        }

        // epilogue: e = exp(S - colmax[m]), split bf16, store to Pe (A of GEMM2)
#pragma unroll
        for (int mt = 0; mt < 2; mt++)
#pragma unroll
            for (int nt = 0; nt < 8; nt++) {
                int r = warp_m * 32 + mt * 16 + (lane >> 2);
                int c = warp_n * 64 + nt * 8 + 2 * (lane & 3);
                float M0 = cm[c], M1 = cm[c + 1];
                float e00 = __expf(acc1[mt][nt][0] - M0);
                float e01 = __expf(acc1[mt][nt][1] - M1);
                float e10 = __expf(acc1[mt][nt][2] - M0);
                float e11 = __expf(acc1[mt][nt][3] - M1);
                __nv_bfloat16 h0, l0_, h1, l1;
                split_bf16(e00, h0, l0_); split_bf16(e01, h1, l1);
                uint32_t hp = ((uint32_t)__bfloat16_as_ushort(h1) << 16) | __bfloat16_as_ushort(h0);
                uint32_t lp = ((uint32_t)__bfloat16_as_ushort(l1) << 16) | __bfloat16_as_ushort(l0_);
                *(uint32_t*)(sm + F2_PE_HI + r * 272 + c * 2) = hp;
                *(uint32_t*)(sm + F2_PE_LO + r * 272 + c * 2) = lp;
                split_bf16(e10, h0, l0_); split_bf16(e11, h1, l1);
                hp = ((uint32_t)__bfloat16_as_ushort(h1) << 16) | __bfloat16_as_ushort(h0);
                lp = ((uint32_t)__bfloat16_as_ushort(l1) << 16) | __bfloat16_as_ushort(l0_);
                *(uint32_t*)(sm + F2_PE_HI + (r + 8) * 272 + c * 2) = hp;
                *(uint32_t*)(sm + F2_PE_LO + (r + 8) * 272 + c * 2) = lp;
            }
        CP_WAIT0();
        __syncthreads();

        // GEMM2: AG += Pe(128l x 128m) @ GT^T(128m x 128c), K=128
#pragma unroll
        for (int ks = 0; ks < 8; ks++) {
            int koff = ks * 32;
            uint32_t ah[2][4], al[2][4], bh[4][4], bl[4][4];
#pragma unroll
            for (int mt = 0; mt < 2; mt++) {
                uint32_t row = warp_m * 32 + mt * 16 + a_row_off;
                uint32_t ad = sb + row * 272 + koff + a_half;
                LDSM_X4(ah[mt][0], ah[mt][1], ah[mt][2], ah[mt][3], ad + F2_PE_HI);
                LDSM_X4(al[mt][0], al[mt][1], al[mt][2], al[mt][3], ad + F2_PE_LO);
            }
#pragma unroll
            for (int np = 0; np < 4; np++) {
                uint32_t row = warp_n * 64 + np * 16 + b_row_off;
                uint32_t ad = sb + row * 272 + koff + b_half;
                LDSM_X4(bh[np][0], bh[np][1], bh[np][2], bh[np][3], ad + F2_GT_HI);
                LDSM_X4(bl[np][0], bl[np][1], bl[np][2], bl[np][3], ad + F2_GT_LO);
            }
#pragma unroll
            for (int mt = 0; mt < 2; mt++)
#pragma unroll
                for (int np = 0; np < 4; np++) {
                    MMA_BF16(acc2[mt][2 * np],     ah[mt], bh[np][0], bh[np][1]);
                    MMA_BF16(acc2[mt][2 * np],     ah[mt], bl[np][0], bl[np][1]);
                    MMA_BF16(acc2[mt][2 * np],     al[mt], bh[np][0], bh[np][1]);
                    MMA_BF16(acc2[mt][2 * np + 1], ah[mt], bh[np][2], bh[np][3]);
                    MMA_BF16(acc2[mt][2 * np + 1], ah[mt], bl[np][2], bl[np][3]);
                    MMA_BF16(acc2[mt][2 * np + 1], al[mt], bh[np][2], bh[np][3]);
                }
        }
        __syncthreads();
    }

    float* ag = g_ag + (size_t)b * Ln * CGn;
#pragma unroll
    for (int mt = 0; mt < 2; mt++)
#pragma unroll
        for (int nt = 0; nt < 8; nt++) {
            int r = l0 + warp_m * 32 + mt * 16 + (lane >> 2);
            int c = c0 + warp_n * 64 + nt * 8 + 2 * (lane & 3);
            float2 v0 = make_float2(acc2[mt][nt][0], acc2[mt][nt][1]);
            float2 v1 = make_float2(acc2[mt][nt][2], acc2[mt][nt][3]);
            *(float2*)&ag[(size_t)r * CGn + c] = v0;
            *(float2*)&ag[(size_t)(r + 8) * CGn + c] = v1;
        }
}

// ===========================================================================
// K5: out-projection + residual blend (SIMT)
// ===========================================================================
__global__ void final_kernel(const float* __restrict__ x,
                             const float* __restrict__ Wo, const float* __restrict__ bo,
                             const float* __restrict__ gamma, float* __restrict__ out) {
    int l0 = blockIdx.x * 64;
    int c0 = blockIdx.y * 64;
    int b = blockIdx.z;
    int tid = threadIdx.x;
    int tx = tid & 15, ty = tid >> 4;

    __shared__ float as_[64][65];
    __shared__ float ws[64][65];

    const float* ag = g_ag + (size_t)b * Ln * CGn;
    float acc[4][4] = {};
    for (int k0 = 0; k0 < CGn; k0 += 64) {
#pragma unroll
        for (int i = 0; i < 16; i++) {
            int idx = tid + i * 256;
            int r = idx >> 6, k = idx & 63;
            as_[r][k] = ag[(size_t)(l0 + r) * CGn + k0 + k];
            ws[r][k] = Wo[(size_t)(c0 + r) * CGn + k0 + k];
        }
        __syncthreads();
#pragma unroll
        for (int kk = 0; kk < 64; kk++) {
            float av[4], wv[4];
#pragma unroll
            for (int j = 0; j < 4; j++) av[j] = as_[tx * 4 + j][kk];
#pragma unroll
            for (int i = 0; i < 4; i++) wv[i] = ws[ty * 4 + i][kk];
#pragma unroll
            for (int i = 0; i < 4; i++)
#pragma unroll
                for (int j = 0; j < 4; j++) acc[i][j] += wv[i] * av[j];
        }
        __syncthreads();
    }
    float gv = gamma[0];
    float alpha = 1.0f / (1.0f + __expf(-gv));
    float* out1 = out;
    float* out2 = out + (size_t)Bn * Cn * Ln;
#pragma unroll
    for (int i = 0; i < 4; i++) {
        int c2 = c0 + ty * 4 + i;
        float bv = bo[c2];
        size_t base = (size_t)b * Cn * Ln + (size_t)c2 * Ln + l0 + tx * 4;
        float4 xv = *reinterpret_cast<const float4*>(&x[base]);
        float4 v;
        v.x = acc[i][0] + bv; v.y = acc[i][1] + bv;
        v.z = acc[i][2] + bv; v.w = acc[i][3] + bv;
        *reinterpret_cast<float4*>(&out2[base]) = v;
        float4 o1;
        o1.x = (1.f - alpha) * xv.x + alpha * v.x;
        o1.y = (1.f - alpha) * xv.y + alpha * v.y;
        o1.z = (1.f - alpha) * xv.z + alpha * v.z;
        o1.w = (1.f - alpha) * xv.w + alpha * v.w;
        *reinterpret_cast<float4*>(&out1[base]) = o1;
    }
}

extern "C" void kernel_launch(void* const* d_in, const int* in_sizes, int n_in,
                              void* d_out, int out_size) {
    const float* x     = (const float*)d_in[0];
    const float* Wt    = (const float*)d_in[1];
    const float* bt    = (const float*)d_in[2];
    const float* Wp    = (const float*)d_in[3];
    const float* bp    = (const float*)d_in[4];
    const float* Wg    = (const float*)d_in[5];
    const float* bg    = (const float*)d_in[6];
    const float* Wo    = (const float*)d_in[7];
    const float* bo    = (const float*)d_in[8];
    const float* gamma = (const float*)d_in[9];
    float* out = (float*)d_out;

    cudaFuncSetAttribute(softstats_kernel, cudaFuncAttributeMaxDynamicSharedMemorySize, S1_SMEM);
    cudaFuncSetAttribute(attn_fused, cudaFuncAttributeMaxDynamicSharedMemorySize, F2_SMEM);

    proj_kernel<<<dim3(Ln / 64, 6, Bn), 256>>>(x, Wt, bt, Wp, bp, Wg, bg);
    softstats_kernel<<<dim3(Ln / 128, Bn), 256, S1_SMEM>>>();
    transpose_scale_kernel<<<dim3(Ln / 32, CGn / 32, Bn), dim3(32, 8)>>>();
    attn_fused<<<dim3(2, Ln / 128, Bn), 256, F2_SMEM>>>();
    final_kernel<<<dim3(Ln / 64, Cn / 64, Bn), 256>>>(x, Wo, bo, gamma, out);
}

// round 5
// speedup vs baseline: 3.1617x; 1.1115x over previous
#include <cuda_runtime.h>
#include <cuda_bf16.h>
#include <math.h>
#include <stdint.h>

#define Bn 4
#define Cn 512
#define Ln 4096
#define CKn 64
#define CGn 256

// Scratch (allocation-free rule: static __device__ arrays)
__device__ __nv_bfloat16 g_th_hi[Bn * Ln * CKn];
__device__ __nv_bfloat16 g_th_lo[Bn * Ln * CKn];
__device__ __nv_bfloat16 g_ph_hi[Bn * Ln * CKn];
__device__ __nv_bfloat16 g_ph_lo[Bn * Ln * CKn];
__device__ float g_gv[Bn * Ln * CGn];
__device__ __nv_bfloat16 g_gt_hi[Bn * CGn * Ln];
__device__ __nv_bfloat16 g_gt_lo[Bn * CGn * Ln];
__device__ float g_colinv[Bn * Ln];
__device__ float g_ag[Bn * Ln * CGn];

__device__ __forceinline__ uint32_t smem_u32(const void* p) {
    uint32_t a;
    asm("{ .reg .u64 t; cvta.to.shared.u64 t, %1; cvt.u32.u64 %0, t; }" : "=r"(a) : "l"(p));
    return a;
}

#define LDSM_X4(r0, r1, r2, r3, addr) \
    asm volatile("ldmatrix.sync.aligned.m8n8.x4.shared.b16 {%0,%1,%2,%3}, [%4];" \
                 : "=r"(r0), "=r"(r1), "=r"(r2), "=r"(r3) : "r"(addr))

#define MMA_BF16(d, a, b0, b1) \
    asm volatile("mma.sync.aligned.m16n8k16.row.col.f32.bf16.bf16.f32 " \
                 "{%0,%1,%2,%3},{%4,%5,%6,%7},{%8,%9},{%0,%1,%2,%3};" \
                 : "+f"((d)[0]), "+f"((d)[1]), "+f"((d)[2]), "+f"((d)[3]) \
                 : "r"((a)[0]), "r"((a)[1]), "r"((a)[2]), "r"((a)[3]), "r"(b0), "r"(b1))

#define CP_ASYNC16(smem, gptr) \
    asm volatile("cp.async.cg.shared.global [%0], [%1], 16;" :: "r"(smem), "l"(gptr))
#define CP_COMMIT() asm volatile("cp.async.commit_group;")
#define CP_WAIT0()  asm volatile("cp.async.wait_group 0;")
#define CP_WAIT1()  asm volatile("cp.async.wait_group 1;")
#define CP_WAIT2()  asm volatile("cp.async.wait_group 2;")

__device__ __forceinline__ void split_bf16(float f, __nv_bfloat16& hi, __nv_bfloat16& lo) {
    hi = __float2bfloat16(f);
    lo = __float2bfloat16(f - __bfloat162float(hi));
}

// ===========================================================================
// K1: fused theta/phi/g projections. theta/phi -> bf16 hi/lo, g -> fp32.
// ===========================================================================
__global__ void proj_kernel(const float* __restrict__ x,
                            const float* __restrict__ Wt, const float* __restrict__ bt,
                            const float* __restrict__ Wp, const float* __restrict__ bp,
                            const float* __restrict__ Wg, const float* __restrict__ bg) {
    int m0 = blockIdx.x * 64;
    int grp = blockIdx.y;
    int b = blockIdx.z;
    int tid = threadIdx.x;
    int tx = tid & 15, ty = tid >> 4;

    const float* W; const float* bias;
    if (grp == 0)      { W = Wt; bias = bt; }
    else if (grp == 1) { W = Wp; bias = bp; }
    else { W = Wg + (size_t)(grp - 2) * 64 * Cn; bias = bg + (grp - 2) * 64; }

    __shared__ float xs[32][64];
    __shared__ float ws[64][33];

    float acc[4][4];
#pragma unroll
    for (int i = 0; i < 4; i++)
#pragma unroll
        for (int j = 0; j < 4; j++) acc[i][j] = 0.f;

    const float* xb = x + (size_t)b * Cn * Ln;

    for (int k0 = 0; k0 < Cn; k0 += 32) {
#pragma unroll
        for (int i = 0; i < 8; i++) {
            int idx = tid + i * 256;
            int r = idx >> 6, c = idx & 63;
            xs[r][c] = xb[(size_t)(k0 + r) * Ln + m0 + c];
        }
#pragma unroll
        for (int i = 0; i < 8; i++) {
            int idx = tid + i * 256;
            int r = idx >> 5, c = idx & 31;
            ws[r][c] = W[(size_t)r * Cn + k0 + c];
        }
        __syncthreads();
#pragma unroll
        for (int kk = 0; kk < 32; kk++) {
            float a[4], w[4];
#pragma unroll
            for (int i = 0; i < 4; i++) a[i] = xs[kk][ty * 4 + i];
#pragma unroll
            for (int j = 0; j < 4; j++) w[j] = ws[tx * 4 + j][kk];
#pragma unroll
            for (int i = 0; i < 4; i++)
#pragma unroll
                for (int j = 0; j < 4; j++) acc[i][j] += a[i] * w[j];
        }
        __syncthreads();
    }

    if (grp <= 1) {
        __nv_bfloat16* ohi = (grp == 0 ? g_th_hi : g_ph_hi) + (size_t)b * Ln * CKn;
        __nv_bfloat16* olo = (grp == 0 ? g_th_lo : g_ph_lo) + (size_t)b * Ln * CKn;
#pragma unroll
        for (int j = 0; j < 4; j++) {
            float bv = bias[tx * 4 + j];
#pragma unroll
            for (int i = 0; i < 4; i++) {
                float v = tanhf(acc[i][j] + bv);
                __nv_bfloat16 hi, lo;
                split_bf16(v, hi, lo);
                size_t o = (size_t)(m0 + ty * 4 + i) * CKn + tx * 4 + j;
                ohi[o] = hi; olo[o] = lo;
            }
        }
    } else {
        float* outp = g_gv + (size_t)b * Ln * CGn;
        int ob = (grp - 2) * 64;
#pragma unroll
        for (int j = 0; j < 4; j++) {
            float bv = bias[tx * 4 + j];
#pragma unroll
            for (int i = 0; i < 4; i++)
                outp[(size_t)(m0 + ty * 4 + i) * CGn + ob + tx * 4 + j] = acc[i][j] + bv;
        }
    }
}

// ===========================================================================
// K2: softstats — per-column (m) sum of exp(S) over all l (no max needed:
// |S| < 64 since theta/phi in (-1,1), so exp and the sum fit fp32).
// CTA owns an m-tile of 128; streams 32 l-chunks (cp.async double-buffered).
// SMEM (XOR-swizzled, no padding):
//   PH_HI 0, PH_LO 16384, TH stage s at 32768+s*32768 (HI +0, LO +16384),
//   WSM 98304. Total 100352.
// ===========================================================================
#define S_PH_HI 0
#define S_PH_LO 16384
#define S_TH(s) (32768 + (s) * 32768)
#define S_WSM   98304
#define S_SMEM  100352

__global__ void __launch_bounds__(256, 1) softstats_kernel() {
    extern __shared__ char sm[];
    uint32_t sb = smem_u32(sm);
    int tid = threadIdx.x;
    int lane = tid & 31, wid = tid >> 5;
    int warp_m = wid & 3, warp_n = wid >> 2;
    int m0 = blockIdx.x * 128, b = blockIdx.y;

    const __nv_bfloat16* thh = g_th_hi + (size_t)b * Ln * CKn;
    const __nv_bfloat16* thl = g_th_lo + (size_t)b * Ln * CKn;
    const __nv_bfloat16* phh = g_ph_hi + (size_t)b * Ln * CKn;
    const __nv_bfloat16* phl = g_ph_lo + (size_t)b * Ln * CKn;

    // prologue: cp.async theta chunks 0,1; LDG phi tile
#pragma unroll
    for (int s = 0; s < 2; s++) {
#pragma unroll
        for (int t = 0; t < 4; t++) {
            int idx = tid + t * 256;
            int r = idx >> 3, q = idx & 7;
            uint32_t so = r * 128 + ((q * 16) ^ ((r & 7) << 4));
            CP_ASYNC16(sb + S_TH(s) + so, thh + ((size_t)(s * 128 + r)) * CKn + q * 8);
            CP_ASYNC16(sb + S_TH(s) + 16384 + so, thl + ((size_t)(s * 128 + r)) * CKn + q * 8);
        }
        CP_COMMIT();
    }
#pragma unroll
    for (int t = 0; t < 4; t++) {
        int idx = tid + t * 256;
        int r = idx >> 3, q = idx & 7;
        uint32_t so = r * 128 + ((q * 16) ^ ((r & 7) << 4));
        *(uint4*)(sm + S_PH_HI + so) = *(const uint4*)(phh + ((size_t)(m0 + r)) * CKn + q * 8);
        *(uint4*)(sm + S_PH_LO + so) = *(const uint4*)(phl + ((size_t)(m0 + r)) * CKn + q * 8);
    }
    CP_WAIT1();
    __syncthreads();

    float sum[16];
#pragma unroll
    for (int i = 0; i < 16; i++) sum[i] = 0.f;

    int a_row_off = ((lane >> 3) & 1) * 8 + (lane & 7);
    int a_half = (lane >> 4) * 16;
    int b_row_off = (lane >> 4) * 8 + (lane & 7);
    int b_half = ((lane >> 3) & 1) * 16;
    uint32_t swl = (uint32_t)(lane & 7) << 4;

    for (int lc = 0; lc < 32; lc++) {
        uint32_t thb = sb + S_TH(lc & 1);
        float acc[2][8][4];
#pragma unroll
        for (int mt = 0; mt < 2; mt++)
#pragma unroll
            for (int nt = 0; nt < 8; nt++)
#pragma unroll
                for (int j = 0; j < 4; j++) acc[mt][nt][j] = 0.f;

#pragma unroll
        for (int ks = 0; ks < 4; ks++) {
            int koff = ks * 32;
            uint32_t ah[2][4], al[2][4], bh[4][4], bl[4][4];
#pragma unroll
            for (int mt = 0; mt < 2; mt++) {
                uint32_t row = warp_m * 32 + mt * 16 + a_row_off;
                uint32_t ad = thb + row * 128 + (((uint32_t)(koff + a_half)) ^ swl);
                LDSM_X4(ah[mt][0], ah[mt][1], ah[mt][2], ah[mt][3], ad);
                LDSM_X4(al[mt][0], al[mt][1], al[mt][2], al[mt][3], ad + 16384);
            }
#pragma unroll
            for (int np = 0; np < 4; np++) {
                uint32_t row = warp_n * 64 + np * 16 + b_row_off;
                uint32_t ad = sb + S_PH_HI + row * 128 + (((uint32_t)(koff + b_half)) ^ swl);
                LDSM_X4(bh[np][0], bh[np][1], bh[np][2], bh[np][3], ad);
                LDSM_X4(bl[np][0], bl[np][1], bl[np][2], bl[np][3], ad + 16384);
            }
#pragma unroll
            for (int mt = 0; mt < 2; mt++)
#pragma unroll
                for (int np = 0; np < 4; np++) {
                    MMA_BF16(acc[mt][2 * np],     ah[mt], bh[np][0], bh[np][1]);
                    MMA_BF16(acc[mt][2 * np],     ah[mt], bl[np][0], bl[np][1]);
                    MMA_BF16(acc[mt][2 * np],     al[mt], bh[np][0], bh[np][1]);
                    MMA_BF16(acc[mt][2 * np + 1], ah[mt], bh[np][2], bh[np][3]);
                    MMA_BF16(acc[mt][2 * np + 1], ah[mt], bl[np][2], bl[np][3]);
                    MMA_BF16(acc[mt][2 * np + 1], al[mt], bh[np][2], bh[np][3]);
                }
        }
        // sum of exp per column
#pragma unroll
        for (int nt = 0; nt < 8; nt++)
#pragma unroll
            for (int j = 0; j < 2; j++) {
                int ix = nt * 2 + j;
                sum[ix] += __expf(acc[0][nt][j]) + __expf(acc[0][nt][j + 2])
                         + __expf(acc[1][nt][j]) + __expf(acc[1][nt][j + 2]);
            }

        if (lc < 31) {
            __syncthreads();     // done reading stage lc&1
            if (lc + 2 < 32) {
                int l0 = (lc + 2) * 128;
#pragma unroll
                for (int t = 0; t < 4; t++) {
                    int idx = tid + t * 256;
                    int r = idx >> 3, q = idx & 7;
                    uint32_t so = r * 128 + ((q * 16) ^ ((r & 7) << 4));
                    CP_ASYNC16(sb + S_TH(lc & 1) + so, thh + ((size_t)(l0 + r)) * CKn + q * 8);
                    CP_ASYNC16(sb + S_TH(lc & 1) + 16384 + so, thl + ((size_t)(l0 + r)) * CKn + q * 8);
                }
                CP_COMMIT();
                CP_WAIT1();
            } else {
                CP_WAIT0();
            }
            __syncthreads();
        }
    }

    // cross-lane combine (lanes differing in lane>>2 share a column)
#pragma unroll
    for (int s = 4; s <= 16; s <<= 1)
#pragma unroll
        for (int i = 0; i < 16; i++)
            sum[i] += __shfl_xor_sync(0xffffffffu, sum[i], s);

    float* wsm = (float*)(sm + S_WSM);
    if (lane < 4) {
#pragma unroll
        for (int nt = 0; nt < 8; nt++)
#pragma unroll
            for (int j = 0; j < 2; j++) {
                int c = warp_n * 64 + nt * 8 + 2 * lane + j;
                wsm[warp_m * 128 + c] = sum[nt * 2 + j];
            }
    }
    __syncthreads();
    if (tid < 128) {
        float S = 0.f;
#pragma unroll
        for (int w = 0; w < 4; w++) S += wsm[w * 128 + tid];
        g_colinv[b * Ln + m0 + tid] = 1.0f / S;
    }
}

// ===========================================================================
// K3: gT[c][m] = g[m][c] * colinv[m], split to bf16 hi/lo.
// ===========================================================================
__global__ void transpose_scale_kernel() {
    __shared__ float t[32][33];
    int m0 = blockIdx.x * 32, c0 = blockIdx.y * 32, b = blockIdx.z;
    int tx = threadIdx.x, ty = threadIdx.y;
#pragma unroll
    for (int i = 0; i < 32; i += 8) {
        int m = m0 + ty + i;
        t[ty + i][tx] = g_gv[((size_t)b * Ln + m) * CGn + c0 + tx] * g_colinv[b * Ln + m];
    }
    __syncthreads();
#pragma unroll
    for (int i = 0; i < 32; i += 8) {
        float v = t[tx][ty + i];
        __nv_bfloat16 hi, lo;
        split_bf16(v, hi, lo);
        size_t o = ((size_t)b * CGn + c0 + ty + i) * Ln + m0 + tx;
        g_gt_hi[o] = hi;
        g_gt_lo[o] = lo;
    }
}

// ===========================================================================
// K4: fused attention. Per (l-tile 128, c-half 128), loop 32 m-chunks:
//   GEMM1 S=theta@phi^T (bf16x3) -> exp(S) -> bf16 hi/lo in SMEM ->
//   GEMM2 AG += P @ gT^T (bf16x3). phi double-buffered via cp.async,
//   gT overlapped via cp.async. XOR bank swizzle, no padding.
// SMEM: TH 0 (hi)/16384 (lo); PH stage s at 32768+s*32768 (hi+0, lo+16384);
//       PE 98304 (hi)/131072 (lo); GT 163840 (hi)/196608 (lo). Total 229376.
// ===========================================================================
#define AT_TH_HI 0
#define AT_PH(s) (32768 + (s) * 32768)
#define AT_PE_HI 98304
#define AT_GT_HI 163840
#define AT_SMEM  229376

__global__ void __launch_bounds__(256, 1) attn_fused() {
    extern __shared__ char sm[];
    uint32_t sb = smem_u32(sm);
    int tid = threadIdx.x;
    int lane = tid & 31, wid = tid >> 5;
    int warp_m = wid & 3, warp_n = wid >> 2;
    int c0 = blockIdx.x * 128, l0 = blockIdx.y * 128, b = blockIdx.z;

    const __nv_bfloat16* thh = g_th_hi + (size_t)b * Ln * CKn;
    const __nv_bfloat16* thl = g_th_lo + (size_t)b * Ln * CKn;
    const __nv_bfloat16* phh = g_ph_hi + (size_t)b * Ln * CKn;
    const __nv_bfloat16* phl = g_ph_lo + (size_t)b * Ln * CKn;
    const __nv_bfloat16* Gh = g_gt_hi + ((size_t)b * CGn + c0) * Ln;
    const __nv_bfloat16* Gl = g_gt_lo + ((size_t)b * CGn + c0) * Ln;

    // prologue: issue phi(0) [A0], gT(0) [B0], phi(1) [A1]; LDG theta tile.
#pragma unroll
    for (int t = 0; t < 4; t++) {
        int idx = tid + t * 256;
        int r = idx >> 3, q = idx & 7;
        uint32_t so = r * 128 + ((q * 16) ^ ((r & 7) << 4));
        CP_ASYNC16(sb + AT_PH(0) + so, phh + (size_t)r * CKn + q * 8);
        CP_ASYNC16(sb + AT_PH(0) + 16384 + so, phl + (size_t)r * CKn + q * 8);
    }
    CP_COMMIT();
#pragma unroll
    for (int t = 0; t < 8; t++) {
        int idx = tid + t * 256;
        int r = idx >> 4, q = idx & 15;
        uint32_t so = r * 256 + ((q * 16) ^ ((r & 7) << 4));
        CP_ASYNC16(sb + AT_GT_HI + so, Gh + (size_t)r * Ln + q * 8);
        CP_ASYNC16(sb + AT_GT_HI + 32768 + so, Gl + (size_t)r * Ln + q * 8);
    }
    CP_COMMIT();
#pragma unroll
    for (int t = 0; t < 4; t++) {
        int idx = tid + t * 256;
        int r = idx >> 3, q = idx & 7;
        uint32_t so = r * 128 + ((q * 16) ^ ((r & 7) << 4));
        CP_ASYNC16(sb + AT_PH(1) + so, phh + (size_t)(128 + r) * CKn + q * 8);
        CP_ASYNC16(sb + AT_PH(1) + 16384 + so, phl + (size_t)(128 + r) * CKn + q * 8);
    }
    CP_COMMIT();
    // theta l-tile (A of GEMM1) via LDG, overlapped with the cp.asyncs above
#pragma unroll
    for (int t = 0; t < 4; t++) {
        int idx = tid + t * 256;
        int r = idx >> 3, q = idx & 7;
        uint32_t so = r * 128 + ((q * 16) ^ ((r & 7) << 4));
        *(uint4*)(sm + AT_TH_HI + so) = *(const uint4*)(thh + (size_t)(l0 + r) * CKn + q * 8);
        *(uint4*)(sm + AT_TH_HI + 16384 + so) = *(const uint4*)(thl + (size_t)(l0 + r) * CKn + q * 8);
    }
    CP_WAIT2();   // phi(0) done
    __syncthreads();

    float acc2[2][8][4];
#pragma unroll
    for (int mt = 0; mt < 2; mt++)
#pragma unroll
        for (int nt = 0; nt < 8; nt++)
#pragma unroll
            for (int j = 0; j < 4; j++) acc2[mt][nt][j] = 0.f;

    int a_row_off = ((lane >> 3) & 1) * 8 + (lane & 7);
    int a_half = (lane >> 4) * 16;
    int b_row_off = (lane >> 4) * 8 + (lane & 7);
    int b_half = ((lane >> 3) & 1) * 16;
    uint32_t swl = (uint32_t)(lane & 7) << 4;
    uint32_t swe = (uint32_t)(lane >> 2) << 4;

    for (int k = 0; k < 32; k++) {
        uint32_t phb = sb + AT_PH(k & 1);

        // GEMM1: S tile (128l x 128m), K=64
        float acc1[2][8][4];
#pragma unroll
        for (int mt = 0; mt < 2; mt++)
#pragma unroll
            for (int nt = 0; nt < 8; nt++)
#pragma unroll
                for (int j = 0; j < 4; j++) acc1[mt][nt][j] = 0.f;

#pragma unroll
        for (int ks = 0; ks < 4; ks++) {
            int koff = ks * 32;
            uint32_t ah[2][4], al[2][4], bh[4][4], bl[4][4];
#pragma unroll
            for (int mt = 0; mt < 2; mt++) {
                uint32_t row = warp_m * 32 + mt * 16 + a_row_off;
                uint32_t ad = sb + AT_TH_HI + row * 128 + (((uint32_t)(koff + a_half)) ^ swl);
                LDSM_X4(ah[mt][0], ah[mt][1], ah[mt][2], ah[mt][3], ad);
                LDSM_X4(al[mt][0], al[mt][1], al[mt][2], al[mt][3], ad + 16384);
            }
#pragma unroll
            for (int np = 0; np < 4; np++) {
                uint32_t row = warp_n * 64 + np * 16 + b_row_off;
                uint32_t ad = phb + row * 128 + (((uint32_t)(koff + b_half)) ^ swl);
                LDSM_X4(bh[np][0], bh[np][1], bh[np][2], bh[np][3], ad);
                LDSM_X4(bl[np][0], bl[np][1], bl[np][2], bl[np][3], ad + 16384);
            }
#pragma unroll
            for (int mt = 0; mt < 2; mt++)
#pragma unroll
                for (int np = 0; np < 4; np++) {
                    MMA_BF16(acc1[mt][2 * np],     ah[mt], bh[np][0], bh[np][1]);
                    MMA_BF16(acc1[mt][2 * np],     ah[mt], bl[np][0], bl[np][1]);
                    MMA_BF16(acc1[mt][2 * np],     al[mt], bh[np][0], bh[np][1]);
                    MMA_BF16(acc1[mt][2 * np + 1], ah[mt], bh[np][2], bh[np][3]);
                    MMA_BF16(acc1[mt][2 * np + 1], ah[mt], bl[np][2], bl[np][3]);
                    MMA_BF16(acc1[mt][2 * np + 1], al[mt], bh[np][2], bh[np][3]);
                }
        }

        // epilogue: e = exp(S) (|S|<64, safe), split bf16, store to PE
#pragma unroll
        for (int mt = 0; mt < 2; mt++)
#pragma unroll
            for (int nt = 0; nt < 8; nt++) {
                uint32_t r = warp_m * 32 + mt * 16 + (lane >> 2);
                uint32_t c = warp_n * 64 + nt * 8 + 2 * (lane & 3);
                float e00 = __expf(acc1[mt][nt][0]);
                float e01 = __expf(acc1[mt][nt][1]);
                float e10 = __expf(acc1[mt][nt][2]);
                float e11 = __expf(acc1[mt][nt][3]);
                __nv_bfloat16 h0, l0_, h1, l1;
                split_bf16(e00, h0, l0_); split_bf16(e01, h1, l1);
                uint32_t hp = ((uint32_t)__bfloat16_as_ushort(h1) << 16) | __bfloat16_as_ushort(h0);
                uint32_t lp = ((uint32_t)__bfloat16_as_ushort(l1) << 16) | __bfloat16_as_ushort(l0_);
                uint32_t so = r * 256 + ((2 * c) ^ swe);
                *(uint32_t*)(sm + AT_PE_HI + so) = hp;
                *(uint32_t*)(sm + AT_PE_HI + 32768 + so) = lp;
                split_bf16(e10, h0, l0_); split_bf16(e11, h1, l1);
                hp = ((uint32_t)__bfloat16_as_ushort(h1) << 16) | __bfloat16_as_ushort(h0);
                lp = ((uint32_t)__bfloat16_as_ushort(l1) << 16) | __bfloat16_as_ushort(l0_);
                uint32_t so2 = (r + 8) * 256 + ((2 * c) ^ swe);
                *(uint32_t*)(sm + AT_PE_HI + so2) = hp;
                *(uint32_t*)(sm + AT_PE_HI + 32768 + so2) = lp;
            }

        if (k == 31) { CP_WAIT0(); } else { CP_WAIT1(); }   // gT(k) ready
        __syncthreads();

        // GEMM2: AG += Pe(128l x 128m) @ GT^T(128m x 128c), K=128
#pragma unroll
        for (int ks = 0; ks < 8; ks++) {
            int koff = ks * 32;
            uint32_t ah[2][4], al[2][4], bh[4][4], bl[4][4];
#pragma unroll
            for (int mt = 0; mt < 2; mt++) {
                uint32_t row = warp_m * 32 + mt * 16 + a_row_off;
                uint32_t ad = sb + AT_PE_HI + row * 256 + (((uint32_t)(koff + a_half)) ^ swl);
                LDSM_X4(ah[mt][0], ah[mt][1], ah[mt][2], ah[mt][3], ad);
                LDSM_X4(al[mt][0], al[mt][1], al[mt][2], al[mt][3], ad + 32768);
            }
#pragma unroll
            for (int np = 0; np < 4; np++) {
                uint32_t row = warp_n * 64 + np * 16 + b_row_off;
                uint32_t ad = sb + AT_GT_HI + row * 256 + (((uint32_t)(koff + b_half)) ^ swl);
                LDSM_X4(bh[np][0], bh[np][1], bh[np][2], bh[np][3], ad);
                LDSM_X4(bl[np][0], bl[np][1], bl[np][2], bl[np][3], ad + 32768);
            }
#pragma unroll
            for (int mt = 0; mt < 2; mt++)
#pragma unroll
                for (int np = 0; np < 4; np++) {
                    MMA_BF16(acc2[mt][2 * np],     ah[mt], bh[np][0], bh[np][1]);
                    MMA_BF16(acc2[mt][2 * np],     ah[mt], bl[np][0], bl[np][1]);
                    MMA_BF16(acc2[mt][2 * np],     al[mt], bh[np][0], bh[np][1]);
                    MMA_BF16(acc2[mt][2 * np + 1], ah[mt], bh[np][2], bh[np][3]);
                    MMA_BF16(acc2[mt][2 * np + 1], ah[mt], bl[np][2], bl[np][3]);
                    MMA_BF16(acc2[mt][2 * np + 1], al[mt], bh[np][2], bh[np][3]);
                }
        }

        if (k < 31) {
            __syncthreads();  // all warps done with GT(k) and PE(k)
            // issue gT(k+1) [B_{k+1}]
            {
                int m0 = (k + 1) * 128;
#pragma unroll
                for (int t = 0; t < 8; t++) {
                    int idx = tid + t * 256;
                    int r = idx >> 4, q = idx & 15;
                    uint32_t so = r * 256 + ((q * 16) ^ ((r & 7) << 4));
                    CP_ASYNC16(sb + AT_GT_HI + so, Gh + (size_t)r * Ln + m0 + q * 8);
                    CP_ASYNC16(sb + AT_GT_HI + 32768 + so, Gl + (size_t)r * Ln + m0 + q * 8);
                }
                CP_COMMIT();
            }
            CP_WAIT1();       // phi(k+1) done
            __syncthreads();
            if (k + 2 < 32) { // issue phi(k+2) [A_{k+2}] into stage k&1
                int m0 = (k + 2) * 128;
#pragma unroll
                for (int t = 0; t < 4; t++) {
                    int idx = tid + t * 256;
                    int r = idx >> 3, q = idx & 7;
                    uint32_t so = r * 128 + ((q * 16) ^ ((r & 7) << 4));
                    CP_ASYNC16(sb + AT_PH(k & 1) + so, phh + (size_t)(m0 + r) * CKn + q * 8);
                    CP_ASYNC16(sb + AT_PH(k & 1) + 16384 + so, phl + (size_t)(m0 + r) * CKn + q * 8);
                }
                CP_COMMIT();
            }
        }
    }

    float* ag = g_ag + (size_t)b * Ln * CGn;
#pragma unroll
    for (int mt = 0; mt < 2; mt++)
#pragma unroll
        for (int nt = 0; nt < 8; nt++) {
            int r = l0 + warp_m * 32 + mt * 16 + (lane >> 2);
            int c = c0 + warp_n * 64 + nt * 8 + 2 * (lane & 3);
            float2 v0 = make_float2(acc2[mt][nt][0], acc2[mt][nt][1]);
            float2 v1 = make_float2(acc2[mt][nt][2], acc2[mt][nt][3]);
            *(float2*)&ag[(size_t)r * CGn + c] = v0;
            *(float2*)&ag[(size_t)(r + 8) * CGn + c] = v1;
        }
}

// ===========================================================================
// K5: out-projection + residual blend (SIMT)
// ===========================================================================
__global__ void final_kernel(const float* __restrict__ x,
                             const float* __restrict__ Wo, const float* __restrict__ bo,
                             const float* __restrict__ gamma, float* __restrict__ out) {
    int l0 = blockIdx.x * 64;
    int c0 = blockIdx.y * 64;
    int b = blockIdx.z;
    int tid = threadIdx.x;
    int tx = tid & 15, ty = tid >> 4;

    __shared__ float as_[64][65];
    __shared__ float ws[64][65];

    const float* ag = g_ag + (size_t)b * Ln * CGn;
    float acc[4][4] = {};
    for (int k0 = 0; k0 < CGn; k0 += 64) {
#pragma unroll
        for (int i = 0; i < 16; i++) {
            int idx = tid + i * 256;
            int r = idx >> 6, k = idx & 63;
            as_[r][k] = ag[(size_t)(l0 + r) * CGn + k0 + k];
            ws[r][k] = Wo[(size_t)(c0 + r) * CGn + k0 + k];
        }
        __syncthreads();
#pragma unroll
        for (int kk = 0; kk < 64; kk++) {
            float av[4], wv[4];
#pragma unroll
            for (int j = 0; j < 4; j++) av[j] = as_[tx * 4 + j][kk];
#pragma unroll
            for (int i = 0; i < 4; i++) wv[i] = ws[ty * 4 + i][kk];
#pragma unroll
            for (int i = 0; i < 4; i++)
#pragma unroll
                for (int j = 0; j < 4; j++) acc[i][j] += wv[i] * av[j];
        }
        __syncthreads();
    }
    float gv = gamma[0];
    float alpha = 1.0f / (1.0f + __expf(-gv));
    float* out1 = out;
    float* out2 = out + (size_t)Bn * Cn * Ln;
#pragma unroll
    for (int i = 0; i < 4; i++) {
        int c2 = c0 + ty * 4 + i;
        float bv = bo[c2];
        size_t base = (size_t)b * Cn * Ln + (size_t)c2 * Ln + l0 + tx * 4;
        float4 xv = *reinterpret_cast<const float4*>(&x[base]);
        float4 v;
        v.x = acc[i][0] + bv; v.y = acc[i][1] + bv;
        v.z = acc[i][2] + bv; v.w = acc[i][3] + bv;
        *reinterpret_cast<float4*>(&out2[base]) = v;
        float4 o1;
        o1.x = (1.f - alpha) * xv.x + alpha * v.x;
        o1.y = (1.f - alpha) * xv.y + alpha * v.y;
        o1.z = (1.f - alpha) * xv.z + alpha * v.z;
        o1.w = (1.f - alpha) * xv.w + alpha * v.w;
        *reinterpret_cast<float4*>(&out1[base]) = o1;
    }
}

extern "C" void kernel_launch(void* const* d_in, const int* in_sizes, int n_in,
                              void* d_out, int out_size) {
    const float* x     = (const float*)d_in[0];
    const float* Wt    = (const float*)d_in[1];
    const float* bt    = (const float*)d_in[2];
    const float* Wp    = (const float*)d_in[3];
    const float* bp    = (const float*)d_in[4];
    const float* Wg    = (const float*)d_in[5];
    const float* bg    = (const float*)d_in[6];
    const float* Wo    = (const float*)d_in[7];
    const float* bo    = (const float*)d_in[8];
    const float* gamma = (const float*)d_in[9];
    float* out = (float*)d_out;

    cudaFuncSetAttribute(softstats_kernel, cudaFuncAttributeMaxDynamicSharedMemorySize, S_SMEM);
    cudaFuncSetAttribute(attn_fused, cudaFuncAttributeMaxDynamicSharedMemorySize, AT_SMEM);

    proj_kernel<<<dim3(Ln / 64, 6, Bn), 256>>>(x, Wt, bt, Wp, bp, Wg, bg);
    softstats_kernel<<<dim3(Ln / 128, Bn), 256, S_SMEM>>>();
    transpose_scale_kernel<<<dim3(Ln / 32, CGn / 32, Bn), dim3(32, 8)>>>();
    attn_fused<<<dim3(2, Ln / 128, Bn), 256, AT_SMEM>>>();
    final_kernel<<<dim3(Ln / 64, Cn / 64, Bn), 256>>>(x, Wo, bo, gamma, out);
}

// round 6
// speedup vs baseline: 3.2786x; 1.0370x over previous
#include <cuda_runtime.h>
#include <cuda_bf16.h>
#include <math.h>
#include <stdint.h>

#define Bn 4
#define Cn 512
#define Ln 4096
#define CKn 64
#define CGn 256

// Scratch (allocation-free rule: static __device__ arrays)
__device__ __nv_bfloat16 g_th_hi[Bn * Ln * CKn];
__device__ __nv_bfloat16 g_th_lo[Bn * Ln * CKn];
__device__ __nv_bfloat16 g_ph_hi[Bn * Ln * CKn];
__device__ __nv_bfloat16 g_ph_lo[Bn * Ln * CKn];
__device__ float g_gv[Bn * Ln * CGn];
__device__ __nv_bfloat16 g_gt_hi[Bn * CGn * Ln];
__device__ __nv_bfloat16 g_gt_lo[Bn * CGn * Ln];
__device__ float g_colinv[Bn * Ln];
__device__ float g_ag[Bn * Ln * CGn];

__device__ __forceinline__ uint32_t smem_u32(const void* p) {
    uint32_t a;
    asm("{ .reg .u64 t; cvta.to.shared.u64 t, %1; cvt.u32.u64 %0, t; }" : "=r"(a) : "l"(p));
    return a;
}

#define LDSM_X4(r0, r1, r2, r3, addr) \
    asm volatile("ldmatrix.sync.aligned.m8n8.x4.shared.b16 {%0,%1,%2,%3}, [%4];" \
                 : "=r"(r0), "=r"(r1), "=r"(r2), "=r"(r3) : "r"(addr))

#define MMA_BF16(d, a, b0, b1) \
    asm volatile("mma.sync.aligned.m16n8k16.row.col.f32.bf16.bf16.f32 " \
                 "{%0,%1,%2,%3},{%4,%5,%6,%7},{%8,%9},{%0,%1,%2,%3};" \
                 : "+f"((d)[0]), "+f"((d)[1]), "+f"((d)[2]), "+f"((d)[3]) \
                 : "r"((a)[0]), "r"((a)[1]), "r"((a)[2]), "r"((a)[3]), "r"(b0), "r"(b1))

#define CP_ASYNC16(smem, gptr) \
    asm volatile("cp.async.cg.shared.global [%0], [%1], 16;" :: "r"(smem), "l"(gptr))
#define CP_COMMIT() asm volatile("cp.async.commit_group;")
#define CP_WAIT0()  asm volatile("cp.async.wait_group 0;")
#define CP_WAIT1()  asm volatile("cp.async.wait_group 1;")

__device__ __forceinline__ void split_bf16(float f, __nv_bfloat16& hi, __nv_bfloat16& lo) {
    hi = __float2bfloat16(f);
    lo = __float2bfloat16(f - __bfloat162float(hi));
}
__device__ __forceinline__ uint32_t packbf(__nv_bfloat16 a, __nv_bfloat16 b) {
    return ((uint32_t)__bfloat16_as_ushort(b) << 16) | __bfloat16_as_ushort(a);
}

// ===========================================================================
// K1: fused theta/phi/g projections. theta/phi -> bf16 hi/lo, g -> fp32.
// ===========================================================================
__global__ void proj_kernel(const float* __restrict__ x,
                            const float* __restrict__ Wt, const float* __restrict__ bt,
                            const float* __restrict__ Wp, const float* __restrict__ bp,
                            const float* __restrict__ Wg, const float* __restrict__ bg) {
    int m0 = blockIdx.x * 64;
    int grp = blockIdx.y;
    int b = blockIdx.z;
    int tid = threadIdx.x;
    int tx = tid & 15, ty = tid >> 4;

    const float* W; const float* bias;
    if (grp == 0)      { W = Wt; bias = bt; }
    else if (grp == 1) { W = Wp; bias = bp; }
    else { W = Wg + (size_t)(grp - 2) * 64 * Cn; bias = bg + (grp - 2) * 64; }

    __shared__ float xs[32][64];
    __shared__ float ws[64][33];

    float acc[4][4];
#pragma unroll
    for (int i = 0; i < 4; i++)
#pragma unroll
        for (int j = 0; j < 4; j++) acc[i][j] = 0.f;

    const float* xb = x + (size_t)b * Cn * Ln;

    for (int k0 = 0; k0 < Cn; k0 += 32) {
#pragma unroll
        for (int i = 0; i < 8; i++) {
            int idx = tid + i * 256;
            int r = idx >> 6, c = idx & 63;
            xs[r][c] = xb[(size_t)(k0 + r) * Ln + m0 + c];
        }
#pragma unroll
        for (int i = 0; i < 8; i++) {
            int idx = tid + i * 256;
            int r = idx >> 5, c = idx & 31;
            ws[r][c] = W[(size_t)r * Cn + k0 + c];
        }
        __syncthreads();
#pragma unroll
        for (int kk = 0; kk < 32; kk++) {
            float a[4], w[4];
#pragma unroll
            for (int i = 0; i < 4; i++) a[i] = xs[kk][ty * 4 + i];
#pragma unroll
            for (int j = 0; j < 4; j++) w[j] = ws[tx * 4 + j][kk];
#pragma unroll
            for (int i = 0; i < 4; i++)
#pragma unroll
                for (int j = 0; j < 4; j++) acc[i][j] += a[i] * w[j];
        }
        __syncthreads();
    }

    if (grp <= 1) {
        __nv_bfloat16* ohi = (grp == 0 ? g_th_hi : g_ph_hi) + (size_t)b * Ln * CKn;
        __nv_bfloat16* olo = (grp == 0 ? g_th_lo : g_ph_lo) + (size_t)b * Ln * CKn;
#pragma unroll
        for (int j = 0; j < 4; j++) {
            float bv = bias[tx * 4 + j];
#pragma unroll
            for (int i = 0; i < 4; i++) {
                float v = tanhf(acc[i][j] + bv);
                __nv_bfloat16 hi, lo;
                split_bf16(v, hi, lo);
                size_t o = (size_t)(m0 + ty * 4 + i) * CKn + tx * 4 + j;
                ohi[o] = hi; olo[o] = lo;
            }
        }
    } else {
        float* outp = g_gv + (size_t)b * Ln * CGn;
        int ob = (grp - 2) * 64;
#pragma unroll
        for (int j = 0; j < 4; j++) {
            float bv = bias[tx * 4 + j];
#pragma unroll
            for (int i = 0; i < 4; i++)
                outp[(size_t)(m0 + ty * 4 + i) * CGn + ob + tx * 4 + j] = acc[i][j] + bv;
        }
    }
}

// ===========================================================================
// K2: softstats — per-column (m) sum of exp(S) over all l (no max needed:
// |S| < 64 since theta/phi in (-1,1)).
// ===========================================================================
#define S_PH_HI 0
#define S_PH_LO 16384
#define S_TH(s) (32768 + (s) * 32768)
#define S_WSM   98304
#define S_SMEM  100352

__global__ void __launch_bounds__(256, 1) softstats_kernel() {
    extern __shared__ char sm[];
    uint32_t sb = smem_u32(sm);
    int tid = threadIdx.x;
    int lane = tid & 31, wid = tid >> 5;
    int warp_m = wid & 3, warp_n = wid >> 2;
    int m0 = blockIdx.x * 128, b = blockIdx.y;

    const __nv_bfloat16* thh = g_th_hi + (size_t)b * Ln * CKn;
    const __nv_bfloat16* thl = g_th_lo + (size_t)b * Ln * CKn;
    const __nv_bfloat16* phh = g_ph_hi + (size_t)b * Ln * CKn;
    const __nv_bfloat16* phl = g_ph_lo + (size_t)b * Ln * CKn;

#pragma unroll
    for (int s = 0; s < 2; s++) {
#pragma unroll
        for (int t = 0; t < 4; t++) {
            int idx = tid + t * 256;
            int r = idx >> 3, q = idx & 7;
            uint32_t so = r * 128 + ((q * 16) ^ ((r & 7) << 4));
            CP_ASYNC16(sb + S_TH(s) + so, thh + ((size_t)(s * 128 + r)) * CKn + q * 8);
            CP_ASYNC16(sb + S_TH(s) + 16384 + so, thl + ((size_t)(s * 128 + r)) * CKn + q * 8);
        }
        CP_COMMIT();
    }
#pragma unroll
    for (int t = 0; t < 4; t++) {
        int idx = tid + t * 256;
        int r = idx >> 3, q = idx & 7;
        uint32_t so = r * 128 + ((q * 16) ^ ((r & 7) << 4));
        *(uint4*)(sm + S_PH_HI + so) = *(const uint4*)(phh + ((size_t)(m0 + r)) * CKn + q * 8);
        *(uint4*)(sm + S_PH_LO + so) = *(const uint4*)(phl + ((size_t)(m0 + r)) * CKn + q * 8);
    }
    CP_WAIT1();
    __syncthreads();

    float sum[16];
#pragma unroll
    for (int i = 0; i < 16; i++) sum[i] = 0.f;

    int a_row_off = ((lane >> 3) & 1) * 8 + (lane & 7);
    int a_half = (lane >> 4) * 16;
    int b_row_off = (lane >> 4) * 8 + (lane & 7);
    int b_half = ((lane >> 3) & 1) * 16;
    uint32_t swl = (uint32_t)(lane & 7) << 4;

    for (int lc = 0; lc < 32; lc++) {
        uint32_t thb = sb + S_TH(lc & 1);
        float acc[2][8][4];
#pragma unroll
        for (int mt = 0; mt < 2; mt++)
#pragma unroll
            for (int nt = 0; nt < 8; nt++)
#pragma unroll
                for (int j = 0; j < 4; j++) acc[mt][nt][j] = 0.f;

#pragma unroll
        for (int ks = 0; ks < 4; ks++) {
            int koff = ks * 32;
            uint32_t ah[2][4], al[2][4], bh[4][4], bl[4][4];
#pragma unroll
            for (int mt = 0; mt < 2; mt++) {
                uint32_t row = warp_m * 32 + mt * 16 + a_row_off;
                uint32_t ad = thb + row * 128 + (((uint32_t)(koff + a_half)) ^ swl);
                LDSM_X4(ah[mt][0], ah[mt][1], ah[mt][2], ah[mt][3], ad);
                LDSM_X4(al[mt][0], al[mt][1], al[mt][2], al[mt][3], ad + 16384);
            }
#pragma unroll
            for (int np = 0; np < 4; np++) {
                uint32_t row = warp_n * 64 + np * 16 + b_row_off;
                uint32_t ad = sb + S_PH_HI + row * 128 + (((uint32_t)(koff + b_half)) ^ swl);
                LDSM_X4(bh[np][0], bh[np][1], bh[np][2], bh[np][3], ad);
                LDSM_X4(bl[np][0], bl[np][1], bl[np][2], bl[np][3], ad + 16384);
            }
#pragma unroll
            for (int mt = 0; mt < 2; mt++)
#pragma unroll
                for (int np = 0; np < 4; np++) {
                    MMA_BF16(acc[mt][2 * np],     ah[mt], bh[np][0], bh[np][1]);
                    MMA_BF16(acc[mt][2 * np],     ah[mt], bl[np][0], bl[np][1]);
                    MMA_BF16(acc[mt][2 * np],     al[mt], bh[np][0], bh[np][1]);
                    MMA_BF16(acc[mt][2 * np + 1], ah[mt], bh[np][2], bh[np][3]);
                    MMA_BF16(acc[mt][2 * np + 1], ah[mt], bl[np][2], bl[np][3]);
                    MMA_BF16(acc[mt][2 * np + 1], al[mt], bh[np][2], bh[np][3]);
                }
        }
#pragma unroll
        for (int nt = 0; nt < 8; nt++)
#pragma unroll
            for (int j = 0; j < 2; j++) {
                int ix = nt * 2 + j;
                sum[ix] += __expf(acc[0][nt][j]) + __expf(acc[0][nt][j + 2])
                         + __expf(acc[1][nt][j]) + __expf(acc[1][nt][j + 2]);
            }

        if (lc < 31) {
            __syncthreads();
            if (lc + 2 < 32) {
                int l0 = (lc + 2) * 128;
#pragma unroll
                for (int t = 0; t < 4; t++) {
                    int idx = tid + t * 256;
                    int r = idx >> 3, q = idx & 7;
                    uint32_t so = r * 128 + ((q * 16) ^ ((r & 7) << 4));
                    CP_ASYNC16(sb + S_TH(lc & 1) + so, thh + ((size_t)(l0 + r)) * CKn + q * 8);
                    CP_ASYNC16(sb + S_TH(lc & 1) + 16384 + so, thl + ((size_t)(l0 + r)) * CKn + q * 8);
                }
                CP_COMMIT();
                CP_WAIT1();
            } else {
                CP_WAIT0();
            }
            __syncthreads();
        }
    }

#pragma unroll
    for (int s = 4; s <= 16; s <<= 1)
#pragma unroll
        for (int i = 0; i < 16; i++)
            sum[i] += __shfl_xor_sync(0xffffffffu, sum[i], s);

    float* wsm = (float*)(sm + S_WSM);
    if (lane < 4) {
#pragma unroll
        for (int nt = 0; nt < 8; nt++)
#pragma unroll
            for (int j = 0; j < 2; j++) {
                int c = warp_n * 64 + nt * 8 + 2 * lane + j;
                wsm[warp_m * 128 + c] = sum[nt * 2 + j];
            }
    }
    __syncthreads();
    if (tid < 128) {
        float S = 0.f;
#pragma unroll
        for (int w = 0; w < 4; w++) S += wsm[w * 128 + tid];
        g_colinv[b * Ln + m0 + tid] = 1.0f / S;
    }
}

// ===========================================================================
// K3: gT[c][m] = g[m][c] * colinv[m], split to bf16 hi/lo.
// ===========================================================================
__global__ void transpose_scale_kernel() {
    __shared__ float t[32][33];
    int m0 = blockIdx.x * 32, c0 = blockIdx.y * 32, b = blockIdx.z;
    int tx = threadIdx.x, ty = threadIdx.y;
#pragma unroll
    for (int i = 0; i < 32; i += 8) {
        int m = m0 + ty + i;
        t[ty + i][tx] = g_gv[((size_t)b * Ln + m) * CGn + c0 + tx] * g_colinv[b * Ln + m];
    }
    __syncthreads();
#pragma unroll
    for (int i = 0; i < 32; i += 8) {
        float v = t[tx][ty + i];
        __nv_bfloat16 hi, lo;
        split_bf16(v, hi, lo);
        size_t o = ((size_t)b * CGn + c0 + ty + i) * Ln + m0 + tx;
        g_gt_hi[o] = hi;
        g_gt_lo[o] = lo;
    }
}

// ===========================================================================
// K4: fused attention with register-resident P.
// Per (l-tile 128, c-half 128), loop 32 m-chunks of 128:
//   GEMM1 S (warp: 32l x 64m) -> exp+split to A-fragments IN REGISTERS ->
//   GEMM2 AG += P @ gT^T (warp: 32l x 128c, K=its 64m). No PE smem, no
//   barriers between phases. Warp pairs (warp_m, 0/1) reduce at the end.
// SMEM: TH 0(hi)/16384(lo); PH stage s at 32768+s*32768 (hi+0,lo+16384);
//       GT stage s at 98304+s*65536 (hi+0,lo+32768). Total 229376.
// ===========================================================================
#define AT_TH_HI 0
#define AT_PH(s) (32768 + (s) * 32768)
#define AT_GT(s) (98304 + (s) * 65536)
#define AT_RED   98304
#define AT_SMEM  229376

__global__ void __launch_bounds__(256, 1) attn_fused() {
    extern __shared__ char sm[];
    uint32_t sb = smem_u32(sm);
    int tid = threadIdx.x;
    int lane = tid & 31, wid = tid >> 5;
    int warp_m = wid & 3, warp_n = wid >> 2;
    int c0 = blockIdx.x * 128, l0 = blockIdx.y * 128, b = blockIdx.z;

    const __nv_bfloat16* thh = g_th_hi + (size_t)b * Ln * CKn;
    const __nv_bfloat16* thl = g_th_lo + (size_t)b * Ln * CKn;
    const __nv_bfloat16* phh = g_ph_hi + (size_t)b * Ln * CKn;
    const __nv_bfloat16* phl = g_ph_lo + (size_t)b * Ln * CKn;
    const __nv_bfloat16* Gh = g_gt_hi + ((size_t)b * CGn + c0) * Ln;
    const __nv_bfloat16* Gl = g_gt_lo + ((size_t)b * CGn + c0) * Ln;

    // prologue: chunk0 (PH+GT) one group; chunk1 second group; theta via LDG.
#pragma unroll
    for (int s = 0; s < 2; s++) {
#pragma unroll
        for (int t = 0; t < 4; t++) {
            int idx = tid + t * 256;
            int r = idx >> 3, q = idx & 7;
            uint32_t so = r * 128 + ((q * 16) ^ ((r & 7) << 4));
            CP_ASYNC16(sb + AT_PH(s) + so, phh + (size_t)(s * 128 + r) * CKn + q * 8);
            CP_ASYNC16(sb + AT_PH(s) + 16384 + so, phl + (size_t)(s * 128 + r) * CKn + q * 8);
        }
#pragma unroll
        for (int t = 0; t < 8; t++) {
            int idx = tid + t * 256;
            int r = idx >> 4, q = idx & 15;
            uint32_t so = r * 256 + ((q * 16) ^ ((r & 7) << 4));
            CP_ASYNC16(sb + AT_GT(s) + so, Gh + (size_t)r * Ln + s * 128 + q * 8);
            CP_ASYNC16(sb + AT_GT(s) + 32768 + so, Gl + (size_t)r * Ln + s * 128 + q * 8);
        }
        CP_COMMIT();
    }
#pragma unroll
    for (int t = 0; t < 4; t++) {
        int idx = tid + t * 256;
        int r = idx >> 3, q = idx & 7;
        uint32_t so = r * 128 + ((q * 16) ^ ((r & 7) << 4));
        *(uint4*)(sm + AT_TH_HI + so) = *(const uint4*)(thh + (size_t)(l0 + r) * CKn + q * 8);
        *(uint4*)(sm + AT_TH_HI + 16384 + so) = *(const uint4*)(thl + (size_t)(l0 + r) * CKn + q * 8);
    }
    CP_WAIT1();
    __syncthreads();

    float acc2[2][16][4];
#pragma unroll
    for (int mt = 0; mt < 2; mt++)
#pragma unroll
        for (int nt = 0; nt < 16; nt++)
#pragma unroll
            for (int j = 0; j < 4; j++) acc2[mt][nt][j] = 0.f;

    int a_row_off = ((lane >> 3) & 1) * 8 + (lane & 7);
    int a_half = (lane >> 4) * 16;
    int b_row_off = (lane >> 4) * 8 + (lane & 7);
    int b_half = ((lane >> 3) & 1) * 16;
    uint32_t swl = (uint32_t)(lane & 7) << 4;

    for (int k = 0; k < 32; k++) {
        uint32_t phb = sb + AT_PH(k & 1);
        uint32_t gtb = sb + AT_GT(k & 1);

        // GEMM1: S (32l x 64m for this warp), K=64
        float acc1[2][8][4];
#pragma unroll
        for (int mt = 0; mt < 2; mt++)
#pragma unroll
            for (int nt = 0; nt < 8; nt++)
#pragma unroll
                for (int j = 0; j < 4; j++) acc1[mt][nt][j] = 0.f;

#pragma unroll
        for (int ks = 0; ks < 4; ks++) {
            int koff = ks * 32;
            uint32_t ah[2][4], al[2][4], bh[4][4], bl[4][4];
#pragma unroll
            for (int mt = 0; mt < 2; mt++) {
                uint32_t row = warp_m * 32 + mt * 16 + a_row_off;
                uint32_t ad = sb + AT_TH_HI + row * 128 + (((uint32_t)(koff + a_half)) ^ swl);
                LDSM_X4(ah[mt][0], ah[mt][1], ah[mt][2], ah[mt][3], ad);
                LDSM_X4(al[mt][0], al[mt][1], al[mt][2], al[mt][3], ad + 16384);
            }
#pragma unroll
            for (int np = 0; np < 4; np++) {
                uint32_t row = warp_n * 64 + np * 16 + b_row_off;
                uint32_t ad = phb + row * 128 + (((uint32_t)(koff + b_half)) ^ swl);
                LDSM_X4(bh[np][0], bh[np][1], bh[np][2], bh[np][3], ad);
                LDSM_X4(bl[np][0], bl[np][1], bl[np][2], bl[np][3], ad + 16384);
            }
#pragma unroll
            for (int mt = 0; mt < 2; mt++)
#pragma unroll
                for (int np = 0; np < 4; np++) {
                    MMA_BF16(acc1[mt][2 * np],     ah[mt], bh[np][0], bh[np][1]);
                    MMA_BF16(acc1[mt][2 * np],     ah[mt], bl[np][0], bl[np][1]);
                    MMA_BF16(acc1[mt][2 * np],     al[mt], bh[np][0], bh[np][1]);
                    MMA_BF16(acc1[mt][2 * np + 1], ah[mt], bh[np][2], bh[np][3]);
                    MMA_BF16(acc1[mt][2 * np + 1], ah[mt], bl[np][2], bl[np][3]);
                    MMA_BF16(acc1[mt][2 * np + 1], al[mt], bh[np][2], bh[np][3]);
                }
        }

        // GEMM2: per k16-step, convert that slice of acc1 to A-fragments
        // (exp + bf16 hi/lo split) in registers, then MMA against gT.
#pragma unroll
        for (int ks = 0; ks < 4; ks++) {
            uint32_t afh[2][4], afl[2][4];
#pragma unroll
            for (int mt = 0; mt < 2; mt++)
#pragma unroll
                for (int h = 0; h < 2; h++) {
                    int nt = 2 * ks + h;
#pragma unroll
                    for (int p = 0; p < 2; p++) {
                        float e0 = __expf(acc1[mt][nt][2 * p]);
                        float e1 = __expf(acc1[mt][nt][2 * p + 1]);
                        __nv_bfloat16 h0, l0_, h1, l1;
                        split_bf16(e0, h0, l0_);
                        split_bf16(e1, h1, l1);
                        afh[mt][h * 2 + p] = packbf(h0, h1);
                        afl[mt][h * 2 + p] = packbf(l0_, l1);
                    }
                }
            uint32_t koff = (uint32_t)(warp_n * 128 + ks * 32);
#pragma unroll
            for (int np = 0; np < 8; np++) {
                uint32_t row = np * 16 + b_row_off;
                uint32_t ad = gtb + row * 256 + ((koff + (uint32_t)b_half) ^ swl);
                uint32_t bh[4], bl[4];
                LDSM_X4(bh[0], bh[1], bh[2], bh[3], ad);
                LDSM_X4(bl[0], bl[1], bl[2], bl[3], ad + 32768);
#pragma unroll
                for (int mt = 0; mt < 2; mt++) {
                    MMA_BF16(acc2[mt][2 * np],     afh[mt], bh[0], bh[1]);
                    MMA_BF16(acc2[mt][2 * np],     afh[mt], bl[0], bl[1]);
                    MMA_BF16(acc2[mt][2 * np],     afl[mt], bh[0], bh[1]);
                    MMA_BF16(acc2[mt][2 * np + 1], afh[mt], bh[2], bh[3]);
                    MMA_BF16(acc2[mt][2 * np + 1], afh[mt], bl[2], bl[3]);
                    MMA_BF16(acc2[mt][2 * np + 1], afl[mt], bh[2], bh[3]);
                }
            }
        }

        if (k < 31) {
            __syncthreads();   // all warps done reading stage k&1
            if (k + 2 < 32) {
                int m0 = (k + 2) * 128;
#pragma unroll
                for (int t = 0; t < 4; t++) {
                    int idx = tid + t * 256;
                    int r = idx >> 3, q = idx & 7;
                    uint32_t so = r * 128 + ((q * 16) ^ ((r & 7) << 4));
                    CP_ASYNC16(sb + AT_PH(k & 1) + so, phh + (size_t)(m0 + r) * CKn + q * 8);
                    CP_ASYNC16(sb + AT_PH(k & 1) + 16384 + so, phl + (size_t)(m0 + r) * CKn + q * 8);
                }
#pragma unroll
                for (int t = 0; t < 8; t++) {
                    int idx = tid + t * 256;
                    int r = idx >> 4, q = idx & 15;
                    uint32_t so = r * 256 + ((q * 16) ^ ((r & 7) << 4));
                    CP_ASYNC16(sb + AT_GT(k & 1) + so, Gh + (size_t)r * Ln + m0 + q * 8);
                    CP_ASYNC16(sb + AT_GT(k & 1) + 32768 + so, Gl + (size_t)r * Ln + m0 + q * 8);
                }
                CP_COMMIT();
                CP_WAIT1();
            } else {
                CP_WAIT0();
            }
            __syncthreads();
        }
    }

    // Cross-warp_n reduction: warp_n==1 stores partial AG to smem; warp_n==0
    // adds and writes the final AG.
    __syncthreads();
    float* red = (float*)(sm + AT_RED);
    if (warp_n == 1) {
#pragma unroll
        for (int mt = 0; mt < 2; mt++)
#pragma unroll
            for (int nt = 0; nt < 16; nt++) {
                int r = warp_m * 32 + mt * 16 + (lane >> 2);
                int c = nt * 8 + 2 * (lane & 3);
                red[r * 132 + c] = acc2[mt][nt][0];
                red[r * 132 + c + 1] = acc2[mt][nt][1];
                red[(r + 8) * 132 + c] = acc2[mt][nt][2];
                red[(r + 8) * 132 + c + 1] = acc2[mt][nt][3];
            }
    }
    __syncthreads();
    if (warp_n == 0) {
        float* ag = g_ag + (size_t)b * Ln * CGn;
#pragma unroll
        for (int mt = 0; mt < 2; mt++)
#pragma unroll
            for (int nt = 0; nt < 16; nt++) {
                int rr = warp_m * 32 + mt * 16 + (lane >> 2);
                int cc = nt * 8 + 2 * (lane & 3);
                float2 v0 = make_float2(acc2[mt][nt][0] + red[rr * 132 + cc],
                                        acc2[mt][nt][1] + red[rr * 132 + cc + 1]);
                float2 v1 = make_float2(acc2[mt][nt][2] + red[(rr + 8) * 132 + cc],
                                        acc2[mt][nt][3] + red[(rr + 8) * 132 + cc + 1]);
                *(float2*)&ag[(size_t)(l0 + rr) * CGn + c0 + cc] = v0;
                *(float2*)&ag[(size_t)(l0 + rr + 8) * CGn + c0 + cc] = v1;
            }
    }
}

// ===========================================================================
// K5: out-projection + residual blend (SIMT)
// ===========================================================================
__global__ void final_kernel(const float* __restrict__ x,
                             const float* __restrict__ Wo, const float* __restrict__ bo,
                             const float* __restrict__ gamma, float* __restrict__ out) {
    int l0 = blockIdx.x * 64;
    int c0 = blockIdx.y * 64;
    int b = blockIdx.z;
    int tid = threadIdx.x;
    int tx = tid & 15, ty = tid >> 4;

    __shared__ float as_[64][65];
    __shared__ float ws[64][65];

    const float* ag = g_ag + (size_t)b * Ln * CGn;
    float acc[4][4] = {};
    for (int k0 = 0; k0 < CGn; k0 += 64) {
#pragma unroll
        for (int i = 0; i < 16; i++) {
            int idx = tid + i * 256;
            int r = idx >> 6, k = idx & 63;
            as_[r][k] = ag[(size_t)(l0 + r) * CGn + k0 + k];
            ws[r][k] = Wo[(size_t)(c0 + r) * CGn + k0 + k];
        }
        __syncthreads();
#pragma unroll
        for (int kk = 0; kk < 64; kk++) {
            float av[4], wv[4];
#pragma unroll
            for (int j = 0; j < 4; j++) av[j] = as_[tx * 4 + j][kk];
#pragma unroll
            for (int i = 0; i < 4; i++) wv[i] = ws[ty * 4 + i][kk];
#pragma unroll
            for (int i = 0; i < 4; i++)
#pragma unroll
                for (int j = 0; j < 4; j++) acc[i][j] += wv[i] * av[j];
        }
        __syncthreads();
    }
    float gv = gamma[0];
    float alpha = 1.0f / (1.0f + __expf(-gv));
    float* out1 = out;
    float* out2 = out + (size_t)Bn * Cn * Ln;
#pragma unroll
    for (int i = 0; i < 4; i++) {
        int c2 = c0 + ty * 4 + i;
        float bv = bo[c2];
        size_t base = (size_t)b * Cn * Ln + (size_t)c2 * Ln + l0 + tx * 4;
        float4 xv = *reinterpret_cast<const float4*>(&x[base]);
        float4 v;
        v.x = acc[i][0] + bv; v.y = acc[i][1] + bv;
        v.z = acc[i][2] + bv; v.w = acc[i][3] + bv;
        *reinterpret_cast<float4*>(&out2[base]) = v;
        float4 o1;
        o1.x = (1.f - alpha) * xv.x + alpha * v.x;
        o1.y = (1.f - alpha) * xv.y + alpha * v.y;
        o1.z = (1.f - alpha) * xv.z + alpha * v.z;
        o1.w = (1.f - alpha) * xv.w + alpha * v.w;
        *reinterpret_cast<float4*>(&out1[base]) = o1;
    }
}

extern "C" void kernel_launch(void* const* d_in, const int* in_sizes, int n_in,
                              void* d_out, int out_size) {
    const float* x     = (const float*)d_in[0];
    const float* Wt    = (const float*)d_in[1];
    const float* bt    = (const float*)d_in[2];
    const float* Wp    = (const float*)d_in[3];
    const float* bp    = (const float*)d_in[4];
    const float* Wg    = (const float*)d_in[5];
    const float* bg    = (const float*)d_in[6];
    const float* Wo    = (const float*)d_in[7];
    const float* bo    = (const float*)d_in[8];
    const float* gamma = (const float*)d_in[9];
    float* out = (float*)d_out;

    cudaFuncSetAttribute(softstats_kernel, cudaFuncAttributeMaxDynamicSharedMemorySize, S_SMEM);
    cudaFuncSetAttribute(attn_fused, cudaFuncAttributeMaxDynamicSharedMemorySize, AT_SMEM);

    proj_kernel<<<dim3(Ln / 64, 6, Bn), 256>>>(x, Wt, bt, Wp, bp, Wg, bg);
    softstats_kernel<<<dim3(Ln / 128, Bn), 256, S_SMEM>>>();
    transpose_scale_kernel<<<dim3(Ln / 32, CGn / 32, Bn), dim3(32, 8)>>>();
    attn_fused<<<dim3(2, Ln / 128, Bn), 256, AT_SMEM>>>();
    final_kernel<<<dim3(Ln / 64, Cn / 64, Bn), 256>>>(x, Wo, bo, gamma, out);
}

// round 7
// speedup vs baseline: 4.3325x; 1.3214x over previous
#include <cuda_runtime.h>
#include <cuda_bf16.h>
#include <math.h>
#include <stdint.h>

#define Bn 4
#define Cn 512
#define Ln 4096
#define CKn 64
#define CGn 256

// Scratch (allocation-free rule: static __device__ arrays)
__device__ __nv_bfloat16 g_th_hi[Bn * Ln * CKn];
__device__ __nv_bfloat16 g_th_lo[Bn * Ln * CKn];
__device__ __nv_bfloat16 g_ph_hi[Bn * Ln * CKn];
__device__ __nv_bfloat16 g_ph_lo[Bn * Ln * CKn];
__device__ float g_gv[Bn * Ln * CGn];
__device__ __nv_bfloat16 g_gt_hi[Bn * CGn * Ln];
__device__ __nv_bfloat16 g_gt_lo[Bn * CGn * Ln];
__device__ float g_colinv[Bn * Ln];
__device__ __nv_bfloat16 g_ag_hi[Bn * Ln * CGn];
__device__ __nv_bfloat16 g_ag_lo[Bn * Ln * CGn];

__device__ __forceinline__ uint32_t smem_u32(const void* p) {
    uint32_t a;
    asm("{ .reg .u64 t; cvta.to.shared.u64 t, %1; cvt.u32.u64 %0, t; }" : "=r"(a) : "l"(p));
    return a;
}

#define LDSM_X4(r0, r1, r2, r3, addr) \
    asm volatile("ldmatrix.sync.aligned.m8n8.x4.shared.b16 {%0,%1,%2,%3}, [%4];" \
                 : "=r"(r0), "=r"(r1), "=r"(r2), "=r"(r3) : "r"(addr))

#define LDSM_X4_T(r0, r1, r2, r3, addr) \
    asm volatile("ldmatrix.sync.aligned.m8n8.x4.trans.shared.b16 {%0,%1,%2,%3}, [%4];" \
                 : "=r"(r0), "=r"(r1), "=r"(r2), "=r"(r3) : "r"(addr))

#define MMA_BF16(d, a, b0, b1) \
    asm volatile("mma.sync.aligned.m16n8k16.row.col.f32.bf16.bf16.f32 " \
                 "{%0,%1,%2,%3},{%4,%5,%6,%7},{%8,%9},{%0,%1,%2,%3};" \
                 : "+f"((d)[0]), "+f"((d)[1]), "+f"((d)[2]), "+f"((d)[3]) \
                 : "r"((a)[0]), "r"((a)[1]), "r"((a)[2]), "r"((a)[3]), "r"(b0), "r"(b1))

#define CP_ASYNC16(smem, gptr) \
    asm volatile("cp.async.cg.shared.global [%0], [%1], 16;" :: "r"(smem), "l"(gptr))
#define CP_COMMIT() asm volatile("cp.async.commit_group;")
#define CP_WAIT0()  asm volatile("cp.async.wait_group 0;")
#define CP_WAIT1()  asm volatile("cp.async.wait_group 1;")

__device__ __forceinline__ void split_bf16(float f, __nv_bfloat16& hi, __nv_bfloat16& lo) {
    hi = __float2bfloat16(f);
    lo = __float2bfloat16(f - __bfloat162float(hi));
}
__device__ __forceinline__ uint32_t packbf(__nv_bfloat16 a, __nv_bfloat16 b) {
    return ((uint32_t)__bfloat16_as_ushort(b) << 16) | __bfloat16_as_ushort(a);
}

// ===========================================================================
// K1: projections via bf16x3 mma. A = x^T (trans-ldmatrix from [c][l]),
// B = W ([o][c] row-major). Grid (32 l-tiles, 3 groups, B):
//   grp0: theta(o 0-63)+phi(o 64-127) w/ tanh -> bf16 hi/lo
//   grp1/2: g channels 0-127 / 128-255 -> fp32 g_gv
// SMEM: XA stage s at s*32768 (hi+0, lo+16384), rows k (stride 256B, 128 l);
//       WB stage s at 65536+s*32768 (hi/lo), rows o (stride 128B, 64 k).
// ===========================================================================
#define P_SMEM 131072

__global__ void __launch_bounds__(256, 1) proj_mma(const float* __restrict__ x,
                            const float* __restrict__ Wt, const float* __restrict__ bt,
                            const float* __restrict__ Wp, const float* __restrict__ bp,
                            const float* __restrict__ Wg, const float* __restrict__ bg) {
    extern __shared__ char sm[];
    uint32_t sb = smem_u32(sm);
    int tid = threadIdx.x, lane = tid & 31, wid = tid >> 5;
    int warp_m = wid & 3, warp_n = wid >> 2;
    int l0 = blockIdx.x * 128, grp = blockIdx.y, b = blockIdx.z;
    const float* xb = x + (size_t)b * Cn * Ln;

    float4 rx[8], rw[8];
    // LDG chunk 0
#pragma unroll
    for (int t = 0; t < 8; t++) {
        int idx = tid + t * 256, r = idx >> 5, q = idx & 31;
        rx[t] = *(const float4*)&xb[(size_t)r * Ln + l0 + q * 4];
    }
#pragma unroll
    for (int t = 0; t < 8; t++) {
        int idx = tid + t * 256, r = idx >> 4, q = idx & 15;
        const float* Wrow;
        if (grp == 0) Wrow = (r < 64) ? Wt + (size_t)r * Cn : Wp + (size_t)(r - 64) * Cn;
        else          Wrow = Wg + (size_t)((grp - 1) * 128 + r) * Cn;
        rw[t] = *(const float4*)&Wrow[q * 4];
    }

    float acc[2][8][4];
#pragma unroll
    for (int mt = 0; mt < 2; mt++)
#pragma unroll
        for (int nt = 0; nt < 8; nt++)
#pragma unroll
            for (int j = 0; j < 4; j++) acc[mt][nt][j] = 0.f;

    int b_row_off = (lane >> 4) * 8 + (lane & 7);
    int b_half = ((lane >> 3) & 1) * 16;
    uint32_t swl = (uint32_t)(lane & 7) << 4;

    for (int kc = 0; kc < 8; kc++) {
        uint32_t xa = sb + (uint32_t)(kc & 1) * 32768;
        uint32_t wb = sb + 65536 + (uint32_t)(kc & 1) * 32768;
        // convert regs -> smem
#pragma unroll
        for (int t = 0; t < 8; t++) {
            int idx = tid + t * 256, r = idx >> 5, q = idx & 31;
            __nv_bfloat16 h0, e0, h1, e1, h2, e2, h3, e3;
            split_bf16(rx[t].x, h0, e0); split_bf16(rx[t].y, h1, e1);
            split_bf16(rx[t].z, h2, e2); split_bf16(rx[t].w, h3, e3);
            uint32_t so = r * 256 + ((q * 8) ^ ((r & 7) << 4));
            *(uint2*)(sm + (xa - sb) + so) = make_uint2(packbf(h0, h1), packbf(h2, h3));
            *(uint2*)(sm + (xa - sb) + 16384 + so) = make_uint2(packbf(e0, e1), packbf(e2, e3));
        }
#pragma unroll
        for (int t = 0; t < 8; t++) {
            int idx = tid + t * 256, r = idx >> 4, q = idx & 15;
            __nv_bfloat16 h0, e0, h1, e1, h2, e2, h3, e3;
            split_bf16(rw[t].x, h0, e0); split_bf16(rw[t].y, h1, e1);
            split_bf16(rw[t].z, h2, e2); split_bf16(rw[t].w, h3, e3);
            uint32_t so = r * 128 + ((q * 8) ^ ((r & 7) << 4));
            *(uint2*)(sm + (wb - sb) + so) = make_uint2(packbf(h0, h1), packbf(h2, h3));
            *(uint2*)(sm + (wb - sb) + 16384 + so) = make_uint2(packbf(e0, e1), packbf(e2, e3));
        }
        __syncthreads();
        if (kc < 7) {
            int k0n = (kc + 1) * 64;
#pragma unroll
            for (int t = 0; t < 8; t++) {
                int idx = tid + t * 256, r = idx >> 5, q = idx & 31;
                rx[t] = *(const float4*)&xb[(size_t)(k0n + r) * Ln + l0 + q * 4];
            }
#pragma unroll
            for (int t = 0; t < 8; t++) {
                int idx = tid + t * 256, r = idx >> 4, q = idx & 15;
                const float* Wrow;
                if (grp == 0) Wrow = (r < 64) ? Wt + (size_t)r * Cn : Wp + (size_t)(r - 64) * Cn;
                else          Wrow = Wg + (size_t)((grp - 1) * 128 + r) * Cn;
                rw[t] = *(const float4*)&Wrow[k0n + q * 4];
            }
        }
#pragma unroll
        for (int ks = 0; ks < 4; ks++) {
            uint32_t ah[2][4], al[2][4], bh[4][4], bl[4][4];
            uint32_t srow = (uint32_t)(ks * 16 + (lane & 7) + ((lane >> 4) & 1) * 8);
#pragma unroll
            for (int mt = 0; mt < 2; mt++) {
                uint32_t mb = (uint32_t)(warp_m * 32 + mt * 16 + ((lane >> 3) & 1) * 8) * 2;
                uint32_t ad = xa + srow * 256 + (mb ^ swl);
                LDSM_X4_T(ah[mt][0], ah[mt][1], ah[mt][2], ah[mt][3], ad);
                LDSM_X4_T(al[mt][0], al[mt][1], al[mt][2], al[mt][3], ad + 16384);
            }
#pragma unroll
            for (int np = 0; np < 4; np++) {
                uint32_t row = (uint32_t)(warp_n * 64 + np * 16 + b_row_off);
                uint32_t ad = wb + row * 128 + (((uint32_t)(ks * 32 + b_half)) ^ swl);
                LDSM_X4(bh[np][0], bh[np][1], bh[np][2], bh[np][3], ad);
                LDSM_X4(bl[np][0], bl[np][1], bl[np][2], bl[np][3], ad + 16384);
            }
#pragma unroll
            for (int mt = 0; mt < 2; mt++)
#pragma unroll
                for (int np = 0; np < 4; np++) {
                    MMA_BF16(acc[mt][2 * np],     ah[mt], bh[np][0], bh[np][1]);
                    MMA_BF16(acc[mt][2 * np],     ah[mt], bl[np][0], bl[np][1]);
                    MMA_BF16(acc[mt][2 * np],     al[mt], bh[np][0], bh[np][1]);
                    MMA_BF16(acc[mt][2 * np + 1], ah[mt], bh[np][2], bh[np][3]);
                    MMA_BF16(acc[mt][2 * np + 1], ah[mt], bl[np][2], bl[np][3]);
                    MMA_BF16(acc[mt][2 * np + 1], al[mt], bh[np][2], bh[np][3]);
                }
        }
        __syncthreads();
    }

    if (grp == 0) {
        __nv_bfloat16* ohi = (warp_n == 0 ? g_th_hi : g_ph_hi) + (size_t)b * Ln * CKn;
        __nv_bfloat16* olo = (warp_n == 0 ? g_th_lo : g_ph_lo) + (size_t)b * Ln * CKn;
        const float* bias = (warp_n == 0 ? bt : bp);
#pragma unroll
        for (int mt = 0; mt < 2; mt++)
#pragma unroll
            for (int nt = 0; nt < 8; nt++) {
                int r = warp_m * 32 + mt * 16 + (lane >> 2);
                int cl = nt * 8 + 2 * (lane & 3);
                float bv0 = bias[cl], bv1 = bias[cl + 1];
                float v00 = tanhf(acc[mt][nt][0] + bv0);
                float v01 = tanhf(acc[mt][nt][1] + bv1);
                float v10 = tanhf(acc[mt][nt][2] + bv0);
                float v11 = tanhf(acc[mt][nt][3] + bv1);
                __nv_bfloat16 h0, e0, h1, e1;
                split_bf16(v00, h0, e0); split_bf16(v01, h1, e1);
                size_t o = (size_t)(l0 + r) * CKn + cl;
                *(uint32_t*)((char*)ohi + o * 2) = packbf(h0, h1);
                *(uint32_t*)((char*)olo + o * 2) = packbf(e0, e1);
                split_bf16(v10, h0, e0); split_bf16(v11, h1, e1);
                o = (size_t)(l0 + r + 8) * CKn + cl;
                *(uint32_t*)((char*)ohi + o * 2) = packbf(h0, h1);
                *(uint32_t*)((char*)olo + o * 2) = packbf(e0, e1);
            }
    } else {
        float* outp = g_gv + (size_t)b * Ln * CGn;
        int goff = (grp - 1) * 128 + warp_n * 64;
#pragma unroll
        for (int mt = 0; mt < 2; mt++)
#pragma unroll
            for (int nt = 0; nt < 8; nt++) {
                int r = warp_m * 32 + mt * 16 + (lane >> 2);
                int cl = nt * 8 + 2 * (lane & 3);
                int c = goff + cl;
                float bv0 = bg[c], bv1 = bg[c + 1];
                float2 v0 = make_float2(acc[mt][nt][0] + bv0, acc[mt][nt][1] + bv1);
                float2 v1 = make_float2(acc[mt][nt][2] + bv0, acc[mt][nt][3] + bv1);
                *(float2*)&outp[(size_t)(l0 + r) * CGn + c] = v0;
                *(float2*)&outp[(size_t)(l0 + r + 8) * CGn + c] = v1;
            }
    }
}

// ===========================================================================
// K2: softstats — per-column (m) sum of exp(S) over all l.
// ===========================================================================
#define S_PH_HI 0
#define S_PH_LO 16384
#define S_TH(s) (32768 + (s) * 32768)
#define S_WSM   98304
#define S_SMEM  100352

__global__ void __launch_bounds__(256, 1) softstats_kernel() {
    extern __shared__ char sm[];
    uint32_t sb = smem_u32(sm);
    int tid = threadIdx.x;
    int lane = tid & 31, wid = tid >> 5;
    int warp_m = wid & 3, warp_n = wid >> 2;
    int m0 = blockIdx.x * 128, b = blockIdx.y;

    const __nv_bfloat16* thh = g_th_hi + (size_t)b * Ln * CKn;
    const __nv_bfloat16* thl = g_th_lo + (size_t)b * Ln * CKn;
    const __nv_bfloat16* phh = g_ph_hi + (size_t)b * Ln * CKn;
    const __nv_bfloat16* phl = g_ph_lo + (size_t)b * Ln * CKn;

#pragma unroll
    for (int s = 0; s < 2; s++) {
#pragma unroll
        for (int t = 0; t < 4; t++) {
            int idx = tid + t * 256;
            int r = idx >> 3, q = idx & 7;
            uint32_t so = r * 128 + ((q * 16) ^ ((r & 7) << 4));
            CP_ASYNC16(sb + S_TH(s) + so, thh + ((size_t)(s * 128 + r)) * CKn + q * 8);
            CP_ASYNC16(sb + S_TH(s) + 16384 + so, thl + ((size_t)(s * 128 + r)) * CKn + q * 8);
        }
        CP_COMMIT();
    }
#pragma unroll
    for (int t = 0; t < 4; t++) {
        int idx = tid + t * 256;
        int r = idx >> 3, q = idx & 7;
        uint32_t so = r * 128 + ((q * 16) ^ ((r & 7) << 4));
        *(uint4*)(sm + S_PH_HI + so) = *(const uint4*)(phh + ((size_t)(m0 + r)) * CKn + q * 8);
        *(uint4*)(sm + S_PH_LO + so) = *(const uint4*)(phl + ((size_t)(m0 + r)) * CKn + q * 8);
    }
    CP_WAIT1();
    __syncthreads();

    float sum[16];
#pragma unroll
    for (int i = 0; i < 16; i++) sum[i] = 0.f;

    int a_row_off = ((lane >> 3) & 1) * 8 + (lane & 7);
    int a_half = (lane >> 4) * 16;
    int b_row_off = (lane >> 4) * 8 + (lane & 7);
    int b_half = ((lane >> 3) & 1) * 16;
    uint32_t swl = (uint32_t)(lane & 7) << 4;

    for (int lc = 0; lc < 32; lc++) {
        uint32_t thb = sb + S_TH(lc & 1);
        float acc[2][8][4];
#pragma unroll
        for (int mt = 0; mt < 2; mt++)
#pragma unroll
            for (int nt = 0; nt < 8; nt++)
#pragma unroll
                for (int j = 0; j < 4; j++) acc[mt][nt][j] = 0.f;

#pragma unroll
        for (int ks = 0; ks < 4; ks++) {
            int koff = ks * 32;
            uint32_t ah[2][4], al[2][4], bh[4][4], bl[4][4];
#pragma unroll
            for (int mt = 0; mt < 2; mt++) {
                uint32_t row = warp_m * 32 + mt * 16 + a_row_off;
                uint32_t ad = thb + row * 128 + (((uint32_t)(koff + a_half)) ^ swl);
                LDSM_X4(ah[mt][0], ah[mt][1], ah[mt][2], ah[mt][3], ad);
                LDSM_X4(al[mt][0], al[mt][1], al[mt][2], al[mt][3], ad + 16384);
            }
#pragma unroll
            for (int np = 0; np < 4; np++) {
                uint32_t row = warp_n * 64 + np * 16 + b_row_off;
                uint32_t ad = sb + S_PH_HI + row * 128 + (((uint32_t)(koff + b_half)) ^ swl);
                LDSM_X4(bh[np][0], bh[np][1], bh[np][2], bh[np][3], ad);
                LDSM_X4(bl[np][0], bl[np][1], bl[np][2], bl[np][3], ad + 16384);
            }
#pragma unroll
            for (int mt = 0; mt < 2; mt++)
#pragma unroll
                for (int np = 0; np < 4; np++) {
                    MMA_BF16(acc[mt][2 * np],     ah[mt], bh[np][0], bh[np][1]);
                    MMA_BF16(acc[mt][2 * np],     ah[mt], bl[np][0], bl[np][1]);
                    MMA_BF16(acc[mt][2 * np],     al[mt], bh[np][0], bh[np][1]);
                    MMA_BF16(acc[mt][2 * np + 1], ah[mt], bh[np][2], bh[np][3]);
                    MMA_BF16(acc[mt][2 * np + 1], ah[mt], bl[np][2], bl[np][3]);
                    MMA_BF16(acc[mt][2 * np + 1], al[mt], bh[np][2], bh[np][3]);
                }
        }
#pragma unroll
        for (int nt = 0; nt < 8; nt++)
#pragma unroll
            for (int j = 0; j < 2; j++) {
                int ix = nt * 2 + j;
                sum[ix] += __expf(acc[0][nt][j]) + __expf(acc[0][nt][j + 2])
                         + __expf(acc[1][nt][j]) + __expf(acc[1][nt][j + 2]);
            }

        if (lc < 31) {
            __syncthreads();
            if (lc + 2 < 32) {
                int l0 = (lc + 2) * 128;
#pragma unroll
                for (int t = 0; t < 4; t++) {
                    int idx = tid + t * 256;
                    int r = idx >> 3, q = idx & 7;
                    uint32_t so = r * 128 + ((q * 16) ^ ((r & 7) << 4));
                    CP_ASYNC16(sb + S_TH(lc & 1) + so, thh + ((size_t)(l0 + r)) * CKn + q * 8);
                    CP_ASYNC16(sb + S_TH(lc & 1) + 16384 + so, thl + ((size_t)(l0 + r)) * CKn + q * 8);
                }
                CP_COMMIT();
                CP_WAIT1();
            } else {
                CP_WAIT0();
            }
            __syncthreads();
        }
    }

#pragma unroll
    for (int s = 4; s <= 16; s <<= 1)
#pragma unroll
        for (int i = 0; i < 16; i++)
            sum[i] += __shfl_xor_sync(0xffffffffu, sum[i], s);

    float* wsm = (float*)(sm + S_WSM);
    if (lane < 4) {
#pragma unroll
        for (int nt = 0; nt < 8; nt++)
#pragma unroll
            for (int j = 0; j < 2; j++) {
                int c = warp_n * 64 + nt * 8 + 2 * lane + j;
                wsm[warp_m * 128 + c] = sum[nt * 2 + j];
            }
    }
    __syncthreads();
    if (tid < 128) {
        float S = 0.f;
#pragma unroll
        for (int w = 0; w < 4; w++) S += wsm[w * 128 + tid];
        g_colinv[b * Ln + m0 + tid] = 1.0f / S;
    }
}

// ===========================================================================
// K3: gT[c][m] = g[m][c] * colinv[m], split to bf16 hi/lo.
// ===========================================================================
__global__ void transpose_scale_kernel() {
    __shared__ float t[32][33];
    int m0 = blockIdx.x * 32, c0 = blockIdx.y * 32, b = blockIdx.z;
    int tx = threadIdx.x, ty = threadIdx.y;
#pragma unroll
    for (int i = 0; i < 32; i += 8) {
        int m = m0 + ty + i;
        t[ty + i][tx] = g_gv[((size_t)b * Ln + m) * CGn + c0 + tx] * g_colinv[b * Ln + m];
    }
    __syncthreads();
#pragma unroll
    for (int i = 0; i < 32; i += 8) {
        float v = t[tx][ty + i];
        __nv_bfloat16 hi, lo;
        split_bf16(v, hi, lo);
        size_t o = ((size_t)b * CGn + c0 + ty + i) * Ln + m0 + tx;
        g_gt_hi[o] = hi;
        g_gt_lo[o] = lo;
    }
}

// ===========================================================================
// K4: fused attention with register-resident P (as R6), AG written bf16 hi/lo.
// ===========================================================================
#define AT_TH_HI 0
#define AT_PH(s) (32768 + (s) * 32768)
#define AT_GT(s) (98304 + (s) * 65536)
#define AT_RED   98304
#define AT_SMEM  229376

__global__ void __launch_bounds__(256, 1) attn_fused() {
    extern __shared__ char sm[];
    uint32_t sb = smem_u32(sm);
    int tid = threadIdx.x;
    int lane = tid & 31, wid = tid >> 5;
    int warp_m = wid & 3, warp_n = wid >> 2;
    int c0 = blockIdx.x * 128, l0 = blockIdx.y * 128, b = blockIdx.z;

    const __nv_bfloat16* thh = g_th_hi + (size_t)b * Ln * CKn;
    const __nv_bfloat16* thl = g_th_lo + (size_t)b * Ln * CKn;
    const __nv_bfloat16* phh = g_ph_hi + (size_t)b * Ln * CKn;
    const __nv_bfloat16* phl = g_ph_lo + (size_t)b * Ln * CKn;
    const __nv_bfloat16* Gh = g_gt_hi + ((size_t)b * CGn + c0) * Ln;
    const __nv_bfloat16* Gl = g_gt_lo + ((size_t)b * CGn + c0) * Ln;

#pragma unroll
    for (int s = 0; s < 2; s++) {
#pragma unroll
        for (int t = 0; t < 4; t++) {
            int idx = tid + t * 256;
            int r = idx >> 3, q = idx & 7;
            uint32_t so = r * 128 + ((q * 16) ^ ((r & 7) << 4));
            CP_ASYNC16(sb + AT_PH(s) + so, phh + (size_t)(s * 128 + r) * CKn + q * 8);
            CP_ASYNC16(sb + AT_PH(s) + 16384 + so, phl + (size_t)(s * 128 + r) * CKn + q * 8);
        }
#pragma unroll
        for (int t = 0; t < 8; t++) {
            int idx = tid + t * 256;
            int r = idx >> 4, q = idx & 15;
            uint32_t so = r * 256 + ((q * 16) ^ ((r & 7) << 4));
            CP_ASYNC16(sb + AT_GT(s) + so, Gh + (size_t)r * Ln + s * 128 + q * 8);
            CP_ASYNC16(sb + AT_GT(s) + 32768 + so, Gl + (size_t)r * Ln + s * 128 + q * 8);
        }
        CP_COMMIT();
    }
#pragma unroll
    for (int t = 0; t < 4; t++) {
        int idx = tid + t * 256;
        int r = idx >> 3, q = idx & 7;
        uint32_t so = r * 128 + ((q * 16) ^ ((r & 7) << 4));
        *(uint4*)(sm + AT_TH_HI + so) = *(const uint4*)(thh + (size_t)(l0 + r) * CKn + q * 8);
        *(uint4*)(sm + AT_TH_HI + 16384 + so) = *(const uint4*)(thl + (size_t)(l0 + r) * CKn + q * 8);
    }
    CP_WAIT1();
    __syncthreads();

    float acc2[2][16][4];
#pragma unroll
    for (int mt = 0; mt < 2; mt++)
#pragma unroll
        for (int nt = 0; nt < 16; nt++)
#pragma unroll
            for (int j = 0; j < 4; j++) acc2[mt][nt][j] = 0.f;

    int a_row_off = ((lane >> 3) & 1) * 8 + (lane & 7);
    int a_half = (lane >> 4) * 16;
    int b_row_off = (lane >> 4) * 8 + (lane & 7);
    int b_half = ((lane >> 3) & 1) * 16;
    uint32_t swl = (uint32_t)(lane & 7) << 4;

    for (int k = 0; k < 32; k++) {
        uint32_t phb = sb + AT_PH(k & 1);
        uint32_t gtb = sb + AT_GT(k & 1);

        float acc1[2][8][4];
#pragma unroll
        for (int mt = 0; mt < 2; mt++)
#pragma unroll
            for (int nt = 0; nt < 8; nt++)
#pragma unroll
                for (int j = 0; j < 4; j++) acc1[mt][nt][j] = 0.f;

#pragma unroll
        for (int ks = 0; ks < 4; ks++) {
            int koff = ks * 32;
            uint32_t ah[2][4], al[2][4], bh[4][4], bl[4][4];
#pragma unroll
            for (int mt = 0; mt < 2; mt++) {
                uint32_t row = warp_m * 32 + mt * 16 + a_row_off;
                uint32_t ad = sb + AT_TH_HI + row * 128 + (((uint32_t)(koff + a_half)) ^ swl);
                LDSM_X4(ah[mt][0], ah[mt][1], ah[mt][2], ah[mt][3], ad);
                LDSM_X4(al[mt][0], al[mt][1], al[mt][2], al[mt][3], ad + 16384);
            }
#pragma unroll
            for (int np = 0; np < 4; np++) {
                uint32_t row = warp_n * 64 + np * 16 + b_row_off;
                uint32_t ad = phb + row * 128 + (((uint32_t)(koff + b_half)) ^ swl);
                LDSM_X4(bh[np][0], bh[np][1], bh[np][2], bh[np][3], ad);
                LDSM_X4(bl[np][0], bl[np][1], bl[np][2], bl[np][3], ad + 16384);
            }
#pragma unroll
            for (int mt = 0; mt < 2; mt++)
#pragma unroll
                for (int np = 0; np < 4; np++) {
                    MMA_BF16(acc1[mt][2 * np],     ah[mt], bh[np][0], bh[np][1]);
                    MMA_BF16(acc1[mt][2 * np],     ah[mt], bl[np][0], bl[np][1]);
                    MMA_BF16(acc1[mt][2 * np],     al[mt], bh[np][0], bh[np][1]);
                    MMA_BF16(acc1[mt][2 * np + 1], ah[mt], bh[np][2], bh[np][3]);
                    MMA_BF16(acc1[mt][2 * np + 1], ah[mt], bl[np][2], bl[np][3]);
                    MMA_BF16(acc1[mt][2 * np + 1], al[mt], bh[np][2], bh[np][3]);
                }
        }

#pragma unroll
        for (int ks = 0; ks < 4; ks++) {
            uint32_t afh[2][4], afl[2][4];
#pragma unroll
            for (int mt = 0; mt < 2; mt++)
#pragma unroll
                for (int h = 0; h < 2; h++) {
                    int nt = 2 * ks + h;
#pragma unroll
                    for (int p = 0; p < 2; p++) {
                        float e0 = __expf(acc1[mt][nt][2 * p]);
                        float e1 = __expf(acc1[mt][nt][2 * p + 1]);
                        __nv_bfloat16 h0, l0_, h1, l1;
                        split_bf16(e0, h0, l0_);
                        split_bf16(e1, h1, l1);
                        afh[mt][h * 2 + p] = packbf(h0, h1);
                        afl[mt][h * 2 + p] = packbf(l0_, l1);
                    }
                }
            uint32_t koff = (uint32_t)(warp_n * 128 + ks * 32);
#pragma unroll
            for (int np = 0; np < 8; np++) {
                uint32_t row = np * 16 + b_row_off;
                uint32_t ad = gtb + row * 256 + ((koff + (uint32_t)b_half) ^ swl);
                uint32_t bh[4], bl[4];
                LDSM_X4(bh[0], bh[1], bh[2], bh[3], ad);
                LDSM_X4(bl[0], bl[1], bl[2], bl[3], ad + 32768);
#pragma unroll
                for (int mt = 0; mt < 2; mt++) {
                    MMA_BF16(acc2[mt][2 * np],     afh[mt], bh[0], bh[1]);
                    MMA_BF16(acc2[mt][2 * np],     afh[mt], bl[0], bl[1]);
                    MMA_BF16(acc2[mt][2 * np],     afl[mt], bh[0], bh[1]);
                    MMA_BF16(acc2[mt][2 * np + 1], afh[mt], bh[2], bh[3]);
                    MMA_BF16(acc2[mt][2 * np + 1], afh[mt], bl[2], bl[3]);
                    MMA_BF16(acc2[mt][2 * np + 1], afl[mt], bh[2], bh[3]);
                }
            }
        }

        if (k < 31) {
            __syncthreads();
            if (k + 2 < 32) {
                int m0 = (k + 2) * 128;
#pragma unroll
                for (int t = 0; t < 4; t++) {
                    int idx = tid + t * 256;
                    int r = idx >> 3, q = idx & 7;
                    uint32_t so = r * 128 + ((q * 16) ^ ((r & 7) << 4));
                    CP_ASYNC16(sb + AT_PH(k & 1) + so, phh + (size_t)(m0 + r) * CKn + q * 8);
                    CP_ASYNC16(sb + AT_PH(k & 1) + 16384 + so, phl + (size_t)(m0 + r) * CKn + q * 8);
                }
#pragma unroll
                for (int t = 0; t < 8; t++) {
                    int idx = tid + t * 256;
                    int r = idx >> 4, q = idx & 15;
                    uint32_t so = r * 256 + ((q * 16) ^ ((r & 7) << 4));
                    CP_ASYNC16(sb + AT_GT(k & 1) + so, Gh + (size_t)r * Ln + m0 + q * 8);
                    CP_ASYNC16(sb + AT_GT(k & 1) + 32768 + so, Gl + (size_t)r * Ln + m0 + q * 8);
                }
                CP_COMMIT();
                CP_WAIT1();
            } else {
                CP_WAIT0();
            }
            __syncthreads();
        }
    }

    __syncthreads();
    float* red = (float*)(sm + AT_RED);
    if (warp_n == 1) {
#pragma unroll
        for (int mt = 0; mt < 2; mt++)
#pragma unroll
            for (int nt = 0; nt < 16; nt++) {
                int r = warp_m * 32 + mt * 16 + (lane >> 2);
                int c = nt * 8 + 2 * (lane & 3);
                red[r * 132 + c] = acc2[mt][nt][0];
                red[r * 132 + c + 1] = acc2[mt][nt][1];
                red[(r + 8) * 132 + c] = acc2[mt][nt][2];
                red[(r + 8) * 132 + c + 1] = acc2[mt][nt][3];
            }
    }
    __syncthreads();
    if (warp_n == 0) {
#pragma unroll
        for (int mt = 0; mt < 2; mt++)
#pragma unroll
            for (int nt = 0; nt < 16; nt++) {
                int rr = warp_m * 32 + mt * 16 + (lane >> 2);
                int cc = nt * 8 + 2 * (lane & 3);
                float v00 = acc2[mt][nt][0] + red[rr * 132 + cc];
                float v01 = acc2[mt][nt][1] + red[rr * 132 + cc + 1];
                float v10 = acc2[mt][nt][2] + red[(rr + 8) * 132 + cc];
                float v11 = acc2[mt][nt][3] + red[(rr + 8) * 132 + cc + 1];
                __nv_bfloat16 h0, e0, h1, e1;
                size_t o = ((size_t)b * Ln + l0 + rr) * CGn + c0 + cc;
                split_bf16(v00, h0, e0); split_bf16(v01, h1, e1);
                *(uint32_t*)((char*)g_ag_hi + o * 2) = packbf(h0, h1);
                *(uint32_t*)((char*)g_ag_lo + o * 2) = packbf(e0, e1);
                o = ((size_t)b * Ln + l0 + rr + 8) * CGn + c0 + cc;
                split_bf16(v10, h0, e0); split_bf16(v11, h1, e1);
                *(uint32_t*)((char*)g_ag_hi + o * 2) = packbf(h0, h1);
                *(uint32_t*)((char*)g_ag_lo + o * 2) = packbf(e0, e1);
            }
    }
}

// ===========================================================================
// K5: out-projection + blend via bf16x3 mma. D[c2][l] = Wo @ AG^T.
// A = Wo [c2][k] (LDG+split), B = AG bf16 hi/lo [l][k] (cp.async).
// Grid (4 c2-tiles, 32 l-tiles, B). K=256 in 4 chunks of 64.
// SMEM: A stage s at s*32768 (hi/lo 16K each); B stage s at 65536+s*32768.
// ===========================================================================
#define F_SMEM 131072

__global__ void __launch_bounds__(256, 1) final_mma(const float* __restrict__ x,
                             const float* __restrict__ Wo, const float* __restrict__ bo,
                             const float* __restrict__ gamma, float* __restrict__ out) {
    extern __shared__ char sm[];
    uint32_t sb = smem_u32(sm);
    int tid = threadIdx.x, lane = tid & 31, wid = tid >> 5;
    int warp_m = wid & 3, warp_n = wid >> 2;
    int c0 = blockIdx.x * 128, l0 = blockIdx.y * 128, b = blockIdx.z;

    const __nv_bfloat16* Ah = g_ag_hi + ((size_t)b * Ln + l0) * CGn;
    const __nv_bfloat16* Al = g_ag_lo + ((size_t)b * Ln + l0) * CGn;

    float4 rw[8];
#pragma unroll
    for (int t = 0; t < 8; t++) {
        int idx = tid + t * 256, r = idx >> 4, q = idx & 15;
        rw[t] = *(const float4*)&Wo[(size_t)(c0 + r) * CGn + q * 4];
    }
#pragma unroll
    for (int t = 0; t < 4; t++) {
        int idx = tid + t * 256, r = idx >> 3, q = idx & 7;
        uint32_t so = r * 128 + ((q * 16) ^ ((r & 7) << 4));
        CP_ASYNC16(sb + 65536 + so, Ah + (size_t)r * CGn + q * 8);
        CP_ASYNC16(sb + 65536 + 16384 + so, Al + (size_t)r * CGn + q * 8);
    }
    CP_COMMIT();

    float acc[2][8][4];
#pragma unroll
    for (int mt = 0; mt < 2; mt++)
#pragma unroll
        for (int nt = 0; nt < 8; nt++)
#pragma unroll
            for (int j = 0; j < 4; j++) acc[mt][nt][j] = 0.f;

    int a_row_off = ((lane >> 3) & 1) * 8 + (lane & 7);
    int a_half = (lane >> 4) * 16;
    int b_row_off = (lane >> 4) * 8 + (lane & 7);
    int b_half = ((lane >> 3) & 1) * 16;
    uint32_t swl = (uint32_t)(lane & 7) << 4;

    for (int kc = 0; kc < 4; kc++) {
        uint32_t wa = sb + (uint32_t)(kc & 1) * 32768;
        uint32_t ba = sb + 65536 + (uint32_t)(kc & 1) * 32768;
        // convert Wo regs -> smem
#pragma unroll
        for (int t = 0; t < 8; t++) {
            int idx = tid + t * 256, r = idx >> 4, q = idx & 15;
            __nv_bfloat16 h0, e0, h1, e1, h2, e2, h3, e3;
            split_bf16(rw[t].x, h0, e0); split_bf16(rw[t].y, h1, e1);
            split_bf16(rw[t].z, h2, e2); split_bf16(rw[t].w, h3, e3);
            uint32_t so = r * 128 + ((q * 8) ^ ((r & 7) << 4));
            *(uint2*)(sm + (wa - sb) + so) = make_uint2(packbf(h0, h1), packbf(h2, h3));
            *(uint2*)(sm + (wa - sb) + 16384 + so) = make_uint2(packbf(e0, e1), packbf(e2, e3));
        }
        // issue next B chunk
        if (kc < 3) {
            int k0n = (kc + 1) * 64;
            uint32_t bn = 65536 + (uint32_t)((kc + 1) & 1) * 32768;
#pragma unroll
            for (int t = 0; t < 4; t++) {
                int idx = tid + t * 256, r = idx >> 3, q = idx & 7;
                uint32_t so = r * 128 + ((q * 16) ^ ((r & 7) << 4));
                CP_ASYNC16(sb + bn + so, Ah + (size_t)r * CGn + k0n + q * 8);
                CP_ASYNC16(sb + bn + 16384 + so, Al + (size_t)r * CGn + k0n + q * 8);
            }
            CP_COMMIT();
            CP_WAIT1();
        } else {
            CP_WAIT0();
        }
        __syncthreads();
        if (kc < 3) {
            int k0n = (kc + 1) * 64;
#pragma unroll
            for (int t = 0; t < 8; t++) {
                int idx = tid + t * 256, r = idx >> 4, q = idx & 15;
                rw[t] = *(const float4*)&Wo[(size_t)(c0 + r) * CGn + k0n + q * 4];
            }
        }
#pragma unroll
        for (int ks = 0; ks < 4; ks++) {
            int koff = ks * 32;
            uint32_t ah[2][4], al[2][4], bh[4][4], bl[4][4];
#pragma unroll
            for (int mt = 0; mt < 2; mt++) {
                uint32_t row = warp_m * 32 + mt * 16 + a_row_off;
                uint32_t ad = wa + row * 128 + (((uint32_t)(koff + a_half)) ^ swl);
                LDSM_X4(ah[mt][0], ah[mt][1], ah[mt][2], ah[mt][3], ad);
                LDSM_X4(al[mt][0], al[mt][1], al[mt][2], al[mt][3], ad + 16384);
            }
#pragma unroll
            for (int np = 0; np < 4; np++) {
                uint32_t row = warp_n * 64 + np * 16 + b_row_off;
                uint32_t ad = ba + row * 128 + (((uint32_t)(koff + b_half)) ^ swl);
                LDSM_X4(bh[np][0], bh[np][1], bh[np][2], bh[np][3], ad);
                LDSM_X4(bl[np][0], bl[np][1], bl[np][2], bl[np][3], ad + 16384);
            }
#pragma unroll
            for (int mt = 0; mt < 2; mt++)
#pragma unroll
                for (int np = 0; np < 4; np++) {
                    MMA_BF16(acc[mt][2 * np],     ah[mt], bh[np][0], bh[np][1]);
                    MMA_BF16(acc[mt][2 * np],     ah[mt], bl[np][0], bl[np][1]);
                    MMA_BF16(acc[mt][2 * np],     al[mt], bh[np][0], bh[np][1]);
                    MMA_BF16(acc[mt][2 * np + 1], ah[mt], bh[np][2], bh[np][3]);
                    MMA_BF16(acc[mt][2 * np + 1], ah[mt], bl[np][2], bl[np][3]);
                    MMA_BF16(acc[mt][2 * np + 1], al[mt], bh[np][2], bh[np][3]);
                }
        }
        __syncthreads();
    }

    float gv = gamma[0];
    float alpha = 1.0f / (1.0f + __expf(-gv));
    float* out1 = out;
    float* out2 = out + (size_t)Bn * Cn * Ln;
#pragma unroll
    for (int mt = 0; mt < 2; mt++)
#pragma unroll
        for (int nt = 0; nt < 8; nt++) {
            int rc = c0 + warp_m * 32 + mt * 16 + (lane >> 2);
            int cl = l0 + warp_n * 64 + nt * 8 + 2 * (lane & 3);
            float bv0 = bo[rc], bv1 = bo[rc + 8];
            size_t base0 = (size_t)b * Cn * Ln + (size_t)rc * Ln + cl;
            size_t base1 = (size_t)b * Cn * Ln + (size_t)(rc + 8) * Ln + cl;
            float2 v0 = make_float2(acc[mt][nt][0] + bv0, acc[mt][nt][1] + bv0);
            float2 v1 = make_float2(acc[mt][nt][2] + bv1, acc[mt][nt][3] + bv1);
            float2 x0 = *(const float2*)&x[base0];
            float2 x1 = *(const float2*)&x[base1];
            *(float2*)&out2[base0] = v0;
            *(float2*)&out2[base1] = v1;
            float2 o0 = make_float2((1.f - alpha) * x0.x + alpha * v0.x,
                                    (1.f - alpha) * x0.y + alpha * v0.y);
            float2 o1 = make_float2((1.f - alpha) * x1.x + alpha * v1.x,
                                    (1.f - alpha) * x1.y + alpha * v1.y);
            *(float2*)&out1[base0] = o0;
            *(float2*)&out1[base1] = o1;
        }
}

extern "C" void kernel_launch(void* const* d_in, const int* in_sizes, int n_in,
                              void* d_out, int out_size) {
    const float* x     = (const float*)d_in[0];
    const float* Wt    = (const float*)d_in[1];
    const float* bt    = (const float*)d_in[2];
    const float* Wp    = (const float*)d_in[3];
    const float* bp    = (const float*)d_in[4];
    const float* Wg    = (const float*)d_in[5];
    const float* bg    = (const float*)d_in[6];
    const float* Wo    = (const float*)d_in[7];
    const float* bo    = (const float*)d_in[8];
    const float* gamma = (const float*)d_in[9];
    float* out = (float*)d_out;

    cudaFuncSetAttribute(proj_mma, cudaFuncAttributeMaxDynamicSharedMemorySize, P_SMEM);
    cudaFuncSetAttribute(softstats_kernel, cudaFuncAttributeMaxDynamicSharedMemorySize, S_SMEM);
    cudaFuncSetAttribute(attn_fused, cudaFuncAttributeMaxDynamicSharedMemorySize, AT_SMEM);
    cudaFuncSetAttribute(final_mma, cudaFuncAttributeMaxDynamicSharedMemorySize, F_SMEM);

    proj_mma<<<dim3(Ln / 128, 3, Bn), 256, P_SMEM>>>(x, Wt, bt, Wp, bp, Wg, bg);
    softstats_kernel<<<dim3(Ln / 128, Bn), 256, S_SMEM>>>();
    transpose_scale_kernel<<<dim3(Ln / 32, CGn / 32, Bn), dim3(32, 8)>>>();
    attn_fused<<<dim3(2, Ln / 128, Bn), 256, AT_SMEM>>>();
    final_mma<<<dim3(Cn / 128, Ln / 128, Bn), 256, F_SMEM>>>(x, Wo, bo, gamma, out);
}

// round 8
// speedup vs baseline: 4.8000x; 1.1079x over previous
#include <cuda_runtime.h>
#include <cuda_bf16.h>
#include <math.h>
#include <stdint.h>

#define Bn 4
#define Cn 512
#define Ln 4096
#define CKn 64
#define CGn 256

// Scratch (allocation-free rule: static __device__ arrays)
__device__ __nv_bfloat16 g_th_hi[Bn * Ln * CKn];
__device__ __nv_bfloat16 g_th_lo[Bn * Ln * CKn];
__device__ __nv_bfloat16 g_ph_hi[Bn * Ln * CKn];
__device__ __nv_bfloat16 g_ph_lo[Bn * Ln * CKn];
__device__ float g_gv[Bn * Ln * CGn];
__device__ __nv_bfloat16 g_gt_hi[Bn * CGn * Ln];
__device__ __nv_bfloat16 g_gt_lo[Bn * CGn * Ln];
__device__ float g_colinv[Bn * Ln];
__device__ __nv_bfloat16 g_ag_hi[Bn * Ln * CGn];
__device__ __nv_bfloat16 g_ag_lo[Bn * Ln * CGn];

__device__ __forceinline__ uint32_t smem_u32(const void* p) {
    uint32_t a;
    asm("{ .reg .u64 t; cvta.to.shared.u64 t, %1; cvt.u32.u64 %0, t; }" : "=r"(a) : "l"(p));
    return a;
}

#define LDSM_X4(r0, r1, r2, r3, addr) \
    asm volatile("ldmatrix.sync.aligned.m8n8.x4.shared.b16 {%0,%1,%2,%3}, [%4];" \
                 : "=r"(r0), "=r"(r1), "=r"(r2), "=r"(r3) : "r"(addr))

#define LDSM_X4_T(r0, r1, r2, r3, addr) \
    asm volatile("ldmatrix.sync.aligned.m8n8.x4.trans.shared.b16 {%0,%1,%2,%3}, [%4];" \
                 : "=r"(r0), "=r"(r1), "=r"(r2), "=r"(r3) : "r"(addr))

#define MMA_BF16(d, a, b0, b1) \
    asm volatile("mma.sync.aligned.m16n8k16.row.col.f32.bf16.bf16.f32 " \
                 "{%0,%1,%2,%3},{%4,%5,%6,%7},{%8,%9},{%0,%1,%2,%3};" \
                 : "+f"((d)[0]), "+f"((d)[1]), "+f"((d)[2]), "+f"((d)[3]) \
                 : "r"((a)[0]), "r"((a)[1]), "r"((a)[2]), "r"((a)[3]), "r"(b0), "r"(b1))

#define CP_ASYNC16(smem, gptr) \
    asm volatile("cp.async.cg.shared.global [%0], [%1], 16;" :: "r"(smem), "l"(gptr))
#define CP_COMMIT() asm volatile("cp.async.commit_group;")
#define CP_WAIT0()  asm volatile("cp.async.wait_group 0;")
#define CP_WAIT1()  asm volatile("cp.async.wait_group 1;")
#define CP_WAIT2()  asm volatile("cp.async.wait_group 2;")

__device__ __forceinline__ void split_bf16(float f, __nv_bfloat16& hi, __nv_bfloat16& lo) {
    hi = __float2bfloat16(f);
    lo = __float2bfloat16(f - __bfloat162float(hi));
}
__device__ __forceinline__ uint32_t packbf(__nv_bfloat16 a, __nv_bfloat16 b) {
    return ((uint32_t)__bfloat16_as_ushort(b) << 16) | __bfloat16_as_ushort(a);
}

// ===========================================================================
// K1: projections via bf16x3 mma (unchanged from R7).
// ===========================================================================
#define P_SMEM 131072

__global__ void __launch_bounds__(256, 1) proj_mma(const float* __restrict__ x,
                            const float* __restrict__ Wt, const float* __restrict__ bt,
                            const float* __restrict__ Wp, const float* __restrict__ bp,
                            const float* __restrict__ Wg, const float* __restrict__ bg) {
    extern __shared__ char sm[];
    uint32_t sb = smem_u32(sm);
    int tid = threadIdx.x, lane = tid & 31, wid = tid >> 5;
    int warp_m = wid & 3, warp_n = wid >> 2;
    int l0 = blockIdx.x * 128, grp = blockIdx.y, b = blockIdx.z;
    const float* xb = x + (size_t)b * Cn * Ln;

    float4 rx[8], rw[8];
#pragma unroll
    for (int t = 0; t < 8; t++) {
        int idx = tid + t * 256, r = idx >> 5, q = idx & 31;
        rx[t] = *(const float4*)&xb[(size_t)r * Ln + l0 + q * 4];
    }
#pragma unroll
    for (int t = 0; t < 8; t++) {
        int idx = tid + t * 256, r = idx >> 4, q = idx & 15;
        const float* Wrow;
        if (grp == 0) Wrow = (r < 64) ? Wt + (size_t)r * Cn : Wp + (size_t)(r - 64) * Cn;
        else          Wrow = Wg + (size_t)((grp - 1) * 128 + r) * Cn;
        rw[t] = *(const float4*)&Wrow[q * 4];
    }

    float acc[2][8][4];
#pragma unroll
    for (int mt = 0; mt < 2; mt++)
#pragma unroll
        for (int nt = 0; nt < 8; nt++)
#pragma unroll
            for (int j = 0; j < 4; j++) acc[mt][nt][j] = 0.f;

    int b_row_off = (lane >> 4) * 8 + (lane & 7);
    int b_half = ((lane >> 3) & 1) * 16;
    uint32_t swl = (uint32_t)(lane & 7) << 4;

    for (int kc = 0; kc < 8; kc++) {
        uint32_t xa = sb + (uint32_t)(kc & 1) * 32768;
        uint32_t wb = sb + 65536 + (uint32_t)(kc & 1) * 32768;
#pragma unroll
        for (int t = 0; t < 8; t++) {
            int idx = tid + t * 256, r = idx >> 5, q = idx & 31;
            __nv_bfloat16 h0, e0, h1, e1, h2, e2, h3, e3;
            split_bf16(rx[t].x, h0, e0); split_bf16(rx[t].y, h1, e1);
            split_bf16(rx[t].z, h2, e2); split_bf16(rx[t].w, h3, e3);
            uint32_t so = r * 256 + ((q * 8) ^ ((r & 7) << 4));
            *(uint2*)(sm + (xa - sb) + so) = make_uint2(packbf(h0, h1), packbf(h2, h3));
            *(uint2*)(sm + (xa - sb) + 16384 + so) = make_uint2(packbf(e0, e1), packbf(e2, e3));
        }
#pragma unroll
        for (int t = 0; t < 8; t++) {
            int idx = tid + t * 256, r = idx >> 4, q = idx & 15;
            __nv_bfloat16 h0, e0, h1, e1, h2, e2, h3, e3;
            split_bf16(rw[t].x, h0, e0); split_bf16(rw[t].y, h1, e1);
            split_bf16(rw[t].z, h2, e2); split_bf16(rw[t].w, h3, e3);
            uint32_t so = r * 128 + ((q * 8) ^ ((r & 7) << 4));
            *(uint2*)(sm + (wb - sb) + so) = make_uint2(packbf(h0, h1), packbf(h2, h3));
            *(uint2*)(sm + (wb - sb) + 16384 + so) = make_uint2(packbf(e0, e1), packbf(e2, e3));
        }
        __syncthreads();
        if (kc < 7) {
            int k0n = (kc + 1) * 64;
#pragma unroll
            for (int t = 0; t < 8; t++) {
                int idx = tid + t * 256, r = idx >> 5, q = idx & 31;
                rx[t] = *(const float4*)&xb[(size_t)(k0n + r) * Ln + l0 + q * 4];
            }
#pragma unroll
            for (int t = 0; t < 8; t++) {
                int idx = tid + t * 256, r = idx >> 4, q = idx & 15;
                const float* Wrow;
                if (grp == 0) Wrow = (r < 64) ? Wt + (size_t)r * Cn : Wp + (size_t)(r - 64) * Cn;
                else          Wrow = Wg + (size_t)((grp - 1) * 128 + r) * Cn;
                rw[t] = *(const float4*)&Wrow[k0n + q * 4];
            }
        }
#pragma unroll
        for (int ks = 0; ks < 4; ks++) {
            uint32_t ah[2][4], al[2][4], bh[4][4], bl[4][4];
            uint32_t srow = (uint32_t)(ks * 16 + (lane & 7) + ((lane >> 4) & 1) * 8);
#pragma unroll
            for (int mt = 0; mt < 2; mt++) {
                uint32_t mb = (uint32_t)(warp_m * 32 + mt * 16 + ((lane >> 3) & 1) * 8) * 2;
                uint32_t ad = xa + srow * 256 + (mb ^ swl);
                LDSM_X4_T(ah[mt][0], ah[mt][1], ah[mt][2], ah[mt][3], ad);
                LDSM_X4_T(al[mt][0], al[mt][1], al[mt][2], al[mt][3], ad + 16384);
            }
#pragma unroll
            for (int np = 0; np < 4; np++) {
                uint32_t row = (uint32_t)(warp_n * 64 + np * 16 + b_row_off);
                uint32_t ad = wb + row * 128 + (((uint32_t)(ks * 32 + b_half)) ^ swl);
                LDSM_X4(bh[np][0], bh[np][1], bh[np][2], bh[np][3], ad);
                LDSM_X4(bl[np][0], bl[np][1], bl[np][2], bl[np][3], ad + 16384);
            }
#pragma unroll
            for (int mt = 0; mt < 2; mt++)
#pragma unroll
                for (int np = 0; np < 4; np++) {
                    MMA_BF16(acc[mt][2 * np],     ah[mt], bh[np][0], bh[np][1]);
                    MMA_BF16(acc[mt][2 * np],     ah[mt], bl[np][0], bl[np][1]);
                    MMA_BF16(acc[mt][2 * np],     al[mt], bh[np][0], bh[np][1]);
                    MMA_BF16(acc[mt][2 * np + 1], ah[mt], bh[np][2], bh[np][3]);
                    MMA_BF16(acc[mt][2 * np + 1], ah[mt], bl[np][2], bl[np][3]);
                    MMA_BF16(acc[mt][2 * np + 1], al[mt], bh[np][2], bh[np][3]);
                }
        }
        __syncthreads();
    }

    if (grp == 0) {
        __nv_bfloat16* ohi = (warp_n == 0 ? g_th_hi : g_ph_hi) + (size_t)b * Ln * CKn;
        __nv_bfloat16* olo = (warp_n == 0 ? g_th_lo : g_ph_lo) + (size_t)b * Ln * CKn;
        const float* bias = (warp_n == 0 ? bt : bp);
#pragma unroll
        for (int mt = 0; mt < 2; mt++)
#pragma unroll
            for (int nt = 0; nt < 8; nt++) {
                int r = warp_m * 32 + mt * 16 + (lane >> 2);
                int cl = nt * 8 + 2 * (lane & 3);
                float bv0 = bias[cl], bv1 = bias[cl + 1];
                float v00 = tanhf(acc[mt][nt][0] + bv0);
                float v01 = tanhf(acc[mt][nt][1] + bv1);
                float v10 = tanhf(acc[mt][nt][2] + bv0);
                float v11 = tanhf(acc[mt][nt][3] + bv1);
                __nv_bfloat16 h0, e0, h1, e1;
                split_bf16(v00, h0, e0); split_bf16(v01, h1, e1);
                size_t o = (size_t)(l0 + r) * CKn + cl;
                *(uint32_t*)((char*)ohi + o * 2) = packbf(h0, h1);
                *(uint32_t*)((char*)olo + o * 2) = packbf(e0, e1);
                split_bf16(v10, h0, e0); split_bf16(v11, h1, e1);
                o = (size_t)(l0 + r + 8) * CKn + cl;
                *(uint32_t*)((char*)ohi + o * 2) = packbf(h0, h1);
                *(uint32_t*)((char*)olo + o * 2) = packbf(e0, e1);
            }
    } else {
        float* outp = g_gv + (size_t)b * Ln * CGn;
        int goff = (grp - 1) * 128 + warp_n * 64;
#pragma unroll
        for (int mt = 0; mt < 2; mt++)
#pragma unroll
            for (int nt = 0; nt < 8; nt++) {
                int r = warp_m * 32 + mt * 16 + (lane >> 2);
                int cl = nt * 8 + 2 * (lane & 3);
                int c = goff + cl;
                float bv0 = bg[c], bv1 = bg[c + 1];
                float2 v0 = make_float2(acc[mt][nt][0] + bv0, acc[mt][nt][1] + bv1);
                float2 v1 = make_float2(acc[mt][nt][2] + bv0, acc[mt][nt][3] + bv1);
                *(float2*)&outp[(size_t)(l0 + r) * CGn + c] = v0;
                *(float2*)&outp[(size_t)(l0 + r + 8) * CGn + c] = v1;
            }
    }
}

// ===========================================================================
// K2: softstats (unchanged from R7).
// ===========================================================================
#define S_PH_HI 0
#define S_PH_LO 16384
#define S_TH(s) (32768 + (s) * 32768)
#define S_WSM   98304
#define S_SMEM  100352

__global__ void __launch_bounds__(256, 1) softstats_kernel() {
    extern __shared__ char sm[];
    uint32_t sb = smem_u32(sm);
    int tid = threadIdx.x;
    int lane = tid & 31, wid = tid >> 5;
    int warp_m = wid & 3, warp_n = wid >> 2;
    int m0 = blockIdx.x * 128, b = blockIdx.y;

    const __nv_bfloat16* thh = g_th_hi + (size_t)b * Ln * CKn;
    const __nv_bfloat16* thl = g_th_lo + (size_t)b * Ln * CKn;
    const __nv_bfloat16* phh = g_ph_hi + (size_t)b * Ln * CKn;
    const __nv_bfloat16* phl = g_ph_lo + (size_t)b * Ln * CKn;

#pragma unroll
    for (int s = 0; s < 2; s++) {
#pragma unroll
        for (int t = 0; t < 4; t++) {
            int idx = tid + t * 256;
            int r = idx >> 3, q = idx & 7;
            uint32_t so = r * 128 + ((q * 16) ^ ((r & 7) << 4));
            CP_ASYNC16(sb + S_TH(s) + so, thh + ((size_t)(s * 128 + r)) * CKn + q * 8);
            CP_ASYNC16(sb + S_TH(s) + 16384 + so, thl + ((size_t)(s * 128 + r)) * CKn + q * 8);
        }
        CP_COMMIT();
    }
#pragma unroll
    for (int t = 0; t < 4; t++) {
        int idx = tid + t * 256;
        int r = idx >> 3, q = idx & 7;
        uint32_t so = r * 128 + ((q * 16) ^ ((r & 7) << 4));
        *(uint4*)(sm + S_PH_HI + so) = *(const uint4*)(phh + ((size_t)(m0 + r)) * CKn + q * 8);
        *(uint4*)(sm + S_PH_LO + so) = *(const uint4*)(phl + ((size_t)(m0 + r)) * CKn + q * 8);
    }
    CP_WAIT1();
    __syncthreads();

    float sum[16];
#pragma unroll
    for (int i = 0; i < 16; i++) sum[i] = 0.f;

    int a_row_off = ((lane >> 3) & 1) * 8 + (lane & 7);
    int a_half = (lane >> 4) * 16;
    int b_row_off = (lane >> 4) * 8 + (lane & 7);
    int b_half = ((lane >> 3) & 1) * 16;
    uint32_t swl = (uint32_t)(lane & 7) << 4;

    for (int lc = 0; lc < 32; lc++) {
        uint32_t thb = sb + S_TH(lc & 1);
        float acc[2][8][4];
#pragma unroll
        for (int mt = 0; mt < 2; mt++)
#pragma unroll
            for (int nt = 0; nt < 8; nt++)
#pragma unroll
                for (int j = 0; j < 4; j++) acc[mt][nt][j] = 0.f;

#pragma unroll
        for (int ks = 0; ks < 4; ks++) {
            int koff = ks * 32;
            uint32_t ah[2][4], al[2][4], bh[4][4], bl[4][4];
#pragma unroll
            for (int mt = 0; mt < 2; mt++) {
                uint32_t row = warp_m * 32 + mt * 16 + a_row_off;
                uint32_t ad = thb + row * 128 + (((uint32_t)(koff + a_half)) ^ swl);
                LDSM_X4(ah[mt][0], ah[mt][1], ah[mt][2], ah[mt][3], ad);
                LDSM_X4(al[mt][0], al[mt][1], al[mt][2], al[mt][3], ad + 16384);
            }
#pragma unroll
            for (int np = 0; np < 4; np++) {
                uint32_t row = warp_n * 64 + np * 16 + b_row_off;
                uint32_t ad = sb + S_PH_HI + row * 128 + (((uint32_t)(koff + b_half)) ^ swl);
                LDSM_X4(bh[np][0], bh[np][1], bh[np][2], bh[np][3], ad);
                LDSM_X4(bl[np][0], bl[np][1], bl[np][2], bl[np][3], ad + 16384);
            }
#pragma unroll
            for (int mt = 0; mt < 2; mt++)
#pragma unroll
                for (int np = 0; np < 4; np++) {
                    MMA_BF16(acc[mt][2 * np],     ah[mt], bh[np][0], bh[np][1]);
                    MMA_BF16(acc[mt][2 * np],     ah[mt], bl[np][0], bl[np][1]);
                    MMA_BF16(acc[mt][2 * np],     al[mt], bh[np][0], bh[np][1]);
                    MMA_BF16(acc[mt][2 * np + 1], ah[mt], bh[np][2], bh[np][3]);
                    MMA_BF16(acc[mt][2 * np + 1], ah[mt], bl[np][2], bl[np][3]);
                    MMA_BF16(acc[mt][2 * np + 1], al[mt], bh[np][2], bh[np][3]);
                }
        }
#pragma unroll
        for (int nt = 0; nt < 8; nt++)
#pragma unroll
            for (int j = 0; j < 2; j++) {
                int ix = nt * 2 + j;
                sum[ix] += __expf(acc[0][nt][j]) + __expf(acc[0][nt][j + 2])
                         + __expf(acc[1][nt][j]) + __expf(acc[1][nt][j + 2]);
            }

        if (lc < 31) {
            __syncthreads();
            if (lc + 2 < 32) {
                int l0 = (lc + 2) * 128;
#pragma unroll
                for (int t = 0; t < 4; t++) {
                    int idx = tid + t * 256;
                    int r = idx >> 3, q = idx & 7;
                    uint32_t so = r * 128 + ((q * 16) ^ ((r & 7) << 4));
                    CP_ASYNC16(sb + S_TH(lc & 1) + so, thh + ((size_t)(l0 + r)) * CKn + q * 8);
                    CP_ASYNC16(sb + S_TH(lc & 1) + 16384 + so, thl + ((size_t)(l0 + r)) * CKn + q * 8);
                }
                CP_COMMIT();
                CP_WAIT1();
            } else {
                CP_WAIT0();
            }
            __syncthreads();
        }
    }

#pragma unroll
    for (int s = 4; s <= 16; s <<= 1)
#pragma unroll
        for (int i = 0; i < 16; i++)
            sum[i] += __shfl_xor_sync(0xffffffffu, sum[i], s);

    float* wsm = (float*)(sm + S_WSM);
    if (lane < 4) {
#pragma unroll
        for (int nt = 0; nt < 8; nt++)
#pragma unroll
            for (int j = 0; j < 2; j++) {
                int c = warp_n * 64 + nt * 8 + 2 * lane + j;
                wsm[warp_m * 128 + c] = sum[nt * 2 + j];
            }
    }
    __syncthreads();
    if (tid < 128) {
        float S = 0.f;
#pragma unroll
        for (int w = 0; w < 4; w++) S += wsm[w * 128 + tid];
        g_colinv[b * Ln + m0 + tid] = 1.0f / S;
    }
}

// ===========================================================================
// K3: gT transpose+scale (unchanged).
// ===========================================================================
__global__ void transpose_scale_kernel() {
    __shared__ float t[32][33];
    int m0 = blockIdx.x * 32, c0 = blockIdx.y * 32, b = blockIdx.z;
    int tx = threadIdx.x, ty = threadIdx.y;
#pragma unroll
    for (int i = 0; i < 32; i += 8) {
        int m = m0 + ty + i;
        t[ty + i][tx] = g_gv[((size_t)b * Ln + m) * CGn + c0 + tx] * g_colinv[b * Ln + m];
    }
    __syncthreads();
#pragma unroll
    for (int i = 0; i < 32; i += 8) {
        float v = t[tx][ty + i];
        __nv_bfloat16 hi, lo;
        split_bf16(v, hi, lo);
        size_t o = ((size_t)b * CGn + c0 + ty + i) * Ln + m0 + tx;
        g_gt_hi[o] = hi;
        g_gt_lo[o] = lo;
    }
}

// ===========================================================================
// K4: fused attention, CTA = 64 l x 256 c, warp_n splits the m (K) axis.
// GEMM1 computed ONCE per S entry; exp/split once; register-resident P.
// gT streamed as 2-buffer ring of 64KB c-halves.
// SMEM: TH 0 (hi/lo 8K each); PH stage s at 16384+s*32768 (hi/lo 16K);
//       GT half h at 81920+h*65536 (hi/lo 32K). Total 212992.
// Grid (Ln/64, Bn).
// ===========================================================================
#define AT_TH    0
#define AT_PH(s) (16384 + (s) * 32768)
#define AT_GT(h) (81920 + (h) * 65536)
#define AT_RED   81920
#define AT_SMEM  212992

__global__ void __launch_bounds__(256, 1) attn_fused() {
    extern __shared__ char sm[];
    uint32_t sb = smem_u32(sm);
    int tid = threadIdx.x;
    int lane = tid & 31, wid = tid >> 5;
    int warp_m = wid & 3, warp_n = wid >> 2;
    int l0 = blockIdx.x * 64, b = blockIdx.y;

    const __nv_bfloat16* thh = g_th_hi + (size_t)b * Ln * CKn;
    const __nv_bfloat16* thl = g_th_lo + (size_t)b * Ln * CKn;
    const __nv_bfloat16* phh = g_ph_hi + (size_t)b * Ln * CKn;
    const __nv_bfloat16* phl = g_ph_lo + (size_t)b * Ln * CKn;
    const __nv_bfloat16* Gh = g_gt_hi + (size_t)b * CGn * Ln;
    const __nv_bfloat16* Gl = g_gt_lo + (size_t)b * CGn * Ln;

    // prologue groups: [PH(0)], [GT(0,h0)], [GT(0,h1)+PH(1)]
#pragma unroll
    for (int t = 0; t < 4; t++) {
        int idx = tid + t * 256, r = idx >> 3, q = idx & 7;
        uint32_t so = r * 128 + ((q * 16) ^ ((r & 7) << 4));
        CP_ASYNC16(sb + AT_PH(0) + so, phh + (size_t)r * CKn + q * 8);
        CP_ASYNC16(sb + AT_PH(0) + 16384 + so, phl + (size_t)r * CKn + q * 8);
    }
    CP_COMMIT();
#pragma unroll
    for (int t = 0; t < 8; t++) {
        int idx = tid + t * 256, r = idx >> 4, q = idx & 15;
        uint32_t so = r * 256 + ((q * 16) ^ ((r & 7) << 4));
        CP_ASYNC16(sb + AT_GT(0) + so, Gh + (size_t)r * Ln + q * 8);
        CP_ASYNC16(sb + AT_GT(0) + 32768 + so, Gl + (size_t)r * Ln + q * 8);
    }
    CP_COMMIT();
#pragma unroll
    for (int t = 0; t < 8; t++) {
        int idx = tid + t * 256, r = idx >> 4, q = idx & 15;
        uint32_t so = r * 256 + ((q * 16) ^ ((r & 7) << 4));
        CP_ASYNC16(sb + AT_GT(1) + so, Gh + (size_t)(128 + r) * Ln + q * 8);
        CP_ASYNC16(sb + AT_GT(1) + 32768 + so, Gl + (size_t)(128 + r) * Ln + q * 8);
    }
#pragma unroll
    for (int t = 0; t < 4; t++) {
        int idx = tid + t * 256, r = idx >> 3, q = idx & 7;
        uint32_t so = r * 128 + ((q * 16) ^ ((r & 7) << 4));
        CP_ASYNC16(sb + AT_PH(1) + so, phh + (size_t)(128 + r) * CKn + q * 8);
        CP_ASYNC16(sb + AT_PH(1) + 16384 + so, phl + (size_t)(128 + r) * CKn + q * 8);
    }
    CP_COMMIT();
    // theta l-tile (64 rows) via LDG
#pragma unroll
    for (int t = 0; t < 2; t++) {
        int idx = tid + t * 256, r = idx >> 3, q = idx & 7;
        uint32_t so = r * 128 + ((q * 16) ^ ((r & 7) << 4));
        *(uint4*)(sm + AT_TH + so) = *(const uint4*)(thh + (size_t)(l0 + r) * CKn + q * 8);
        *(uint4*)(sm + AT_TH + 8192 + so) = *(const uint4*)(thl + (size_t)(l0 + r) * CKn + q * 8);
    }
    CP_WAIT2();
    __syncthreads();

    float acc2[2][16][4];
#pragma unroll
    for (int h = 0; h < 2; h++)
#pragma unroll
        for (int nt = 0; nt < 16; nt++)
#pragma unroll
            for (int j = 0; j < 4; j++) acc2[h][nt][j] = 0.f;

    int a_row_off = ((lane >> 3) & 1) * 8 + (lane & 7);
    int a_half = (lane >> 4) * 16;
    int b_row_off = (lane >> 4) * 8 + (lane & 7);
    int b_half = ((lane >> 3) & 1) * 16;
    uint32_t swl = (uint32_t)(lane & 7) << 4;

    for (int k = 0; k < 32; k++) {
        uint32_t phb = sb + AT_PH(k & 1);

        // GEMM1: S (16l x 64m per warp), K=64
        float acc1[8][4];
#pragma unroll
        for (int nt = 0; nt < 8; nt++)
#pragma unroll
            for (int j = 0; j < 4; j++) acc1[nt][j] = 0.f;

#pragma unroll
        for (int ks = 0; ks < 4; ks++) {
            int koff = ks * 32;
            uint32_t ah[4], al[4], bh[4][4], bl[4][4];
            {
                uint32_t row = warp_m * 16 + a_row_off;
                uint32_t ad = sb + AT_TH + row * 128 + (((uint32_t)(koff + a_half)) ^ swl);
                LDSM_X4(ah[0], ah[1], ah[2], ah[3], ad);
                LDSM_X4(al[0], al[1], al[2], al[3], ad + 8192);
            }
#pragma unroll
            for (int np = 0; np < 4; np++) {
                uint32_t row = warp_n * 64 + np * 16 + b_row_off;
                uint32_t ad = phb + row * 128 + (((uint32_t)(koff + b_half)) ^ swl);
                LDSM_X4(bh[np][0], bh[np][1], bh[np][2], bh[np][3], ad);
                LDSM_X4(bl[np][0], bl[np][1], bl[np][2], bl[np][3], ad + 16384);
            }
#pragma unroll
            for (int np = 0; np < 4; np++) {
                MMA_BF16(acc1[2 * np],     ah, bh[np][0], bh[np][1]);
                MMA_BF16(acc1[2 * np],     ah, bl[np][0], bl[np][1]);
                MMA_BF16(acc1[2 * np],     al, bh[np][0], bh[np][1]);
                MMA_BF16(acc1[2 * np + 1], ah, bh[np][2], bh[np][3]);
                MMA_BF16(acc1[2 * np + 1], ah, bl[np][2], bl[np][3]);
                MMA_BF16(acc1[2 * np + 1], al, bh[np][2], bh[np][3]);
            }
        }

        // exp + split to A-fragments (register-resident P), once per S entry
        uint32_t afh[4][4], afl[4][4];
#pragma unroll
        for (int ks = 0; ks < 4; ks++)
#pragma unroll
            for (int h01 = 0; h01 < 2; h01++) {
                int nt = 2 * ks + h01;
#pragma unroll
                for (int p = 0; p < 2; p++) {
                    float e0 = __expf(acc1[nt][2 * p]);
                    float e1 = __expf(acc1[nt][2 * p + 1]);
                    __nv_bfloat16 h0, l0_, h1, l1;
                    split_bf16(e0, h0, l0_);
                    split_bf16(e1, h1, l1);
                    afh[ks][h01 * 2 + p] = packbf(h0, h1);
                    afl[ks][h01 * 2 + p] = packbf(l0_, l1);
                }
            }

        // GEMM2 over two gT c-halves (ring-buffered)
#pragma unroll
        for (int h = 0; h < 2; h++) {
            if (h == 1 && k == 31) { CP_WAIT0(); } else { CP_WAIT1(); }
            __syncthreads();
            uint32_t gtb = sb + AT_GT(h);
#pragma unroll
            for (int ks = 0; ks < 4; ks++) {
                uint32_t koff = (uint32_t)(warp_n * 128 + ks * 32);
#pragma unroll
                for (int np = 0; np < 8; np++) {
                    uint32_t row = np * 16 + b_row_off;
                    uint32_t ad = gtb + row * 256 + ((koff + (uint32_t)b_half) ^ swl);
                    uint32_t bh[4], bl[4];
                    LDSM_X4(bh[0], bh[1], bh[2], bh[3], ad);
                    LDSM_X4(bl[0], bl[1], bl[2], bl[3], ad + 32768);
                    MMA_BF16(acc2[h][2 * np],     afh[ks], bh[0], bh[1]);
                    MMA_BF16(acc2[h][2 * np],     afh[ks], bl[0], bl[1]);
                    MMA_BF16(acc2[h][2 * np],     afl[ks], bh[0], bh[1]);
                    MMA_BF16(acc2[h][2 * np + 1], afh[ks], bh[2], bh[3]);
                    MMA_BF16(acc2[h][2 * np + 1], afh[ks], bl[2], bl[3]);
                    MMA_BF16(acc2[h][2 * np + 1], afl[ks], bh[2], bh[3]);
                }
            }
            __syncthreads();
            if (k < 31) {
                int m0n = (k + 1) * 128;
#pragma unroll
                for (int t = 0; t < 8; t++) {
                    int idx = tid + t * 256, r = idx >> 4, q = idx & 15;
                    uint32_t so = r * 256 + ((q * 16) ^ ((r & 7) << 4));
                    CP_ASYNC16(sb + AT_GT(h) + so, Gh + (size_t)(h * 128 + r) * Ln + m0n + q * 8);
                    CP_ASYNC16(sb + AT_GT(h) + 32768 + so, Gl + (size_t)(h * 128 + r) * Ln + m0n + q * 8);
                }
                if (h == 1 && k + 2 < 32) {
                    int m0p = (k + 2) * 128;
#pragma unroll
                    for (int t = 0; t < 4; t++) {
                        int idx = tid + t * 256, r = idx >> 3, q = idx & 7;
                        uint32_t so = r * 128 + ((q * 16) ^ ((r & 7) << 4));
                        CP_ASYNC16(sb + AT_PH(k & 1) + so, phh + (size_t)(m0p + r) * CKn + q * 8);
                        CP_ASYNC16(sb + AT_PH(k & 1) + 16384 + so, phl + (size_t)(m0p + r) * CKn + q * 8);
                    }
                }
                CP_COMMIT();
            }
        }
    }

    // cross-warp_n (m-split) reduction; then write AG as bf16 hi/lo
    __syncthreads();
    float* red = (float*)(sm + AT_RED);
    if (warp_n == 1) {
#pragma unroll
        for (int h = 0; h < 2; h++)
#pragma unroll
            for (int nt = 0; nt < 16; nt++) {
                int r = warp_m * 16 + (lane >> 2);
                int c = h * 128 + nt * 8 + 2 * (lane & 3);
                red[r * 260 + c] = acc2[h][nt][0];
                red[r * 260 + c + 1] = acc2[h][nt][1];
                red[(r + 8) * 260 + c] = acc2[h][nt][2];
                red[(r + 8) * 260 + c + 1] = acc2[h][nt][3];
            }
    }
    __syncthreads();
    if (warp_n == 0) {
#pragma unroll
        for (int h = 0; h < 2; h++)
#pragma unroll
            for (int nt = 0; nt < 16; nt++) {
                int rr = warp_m * 16 + (lane >> 2);
                int cc = h * 128 + nt * 8 + 2 * (lane & 3);
                float v00 = acc2[h][nt][0] + red[rr * 260 + cc];
                float v01 = acc2[h][nt][1] + red[rr * 260 + cc + 1];
                float v10 = acc2[h][nt][2] + red[(rr + 8) * 260 + cc];
                float v11 = acc2[h][nt][3] + red[(rr + 8) * 260 + cc + 1];
                __nv_bfloat16 h0, e0, h1, e1;
                size_t o = ((size_t)b * Ln + l0 + rr) * CGn + cc;
                split_bf16(v00, h0, e0); split_bf16(v01, h1, e1);
                *(uint32_t*)((char*)g_ag_hi + o * 2) = packbf(h0, h1);
                *(uint32_t*)((char*)g_ag_lo + o * 2) = packbf(e0, e1);
                o = ((size_t)b * Ln + l0 + rr + 8) * CGn + cc;
                split_bf16(v10, h0, e0); split_bf16(v11, h1, e1);
                *(uint32_t*)((char*)g_ag_hi + o * 2) = packbf(h0, h1);
                *(uint32_t*)((char*)g_ag_lo + o * 2) = packbf(e0, e1);
            }
    }
}

// ===========================================================================
// K5: out-projection + blend via bf16x3 mma (unchanged from R7).
// ===========================================================================
#define F_SMEM 131072

__global__ void __launch_bounds__(256, 1) final_mma(const float* __restrict__ x,
                             const float* __restrict__ Wo, const float* __restrict__ bo,
                             const float* __restrict__ gamma, float* __restrict__ out) {
    extern __shared__ char sm[];
    uint32_t sb = smem_u32(sm);
    int tid = threadIdx.x, lane = tid & 31, wid = tid >> 5;
    int warp_m = wid & 3, warp_n = wid >> 2;
    int c0 = blockIdx.x * 128, l0 = blockIdx.y * 128, b = blockIdx.z;

    const __nv_bfloat16* Ah = g_ag_hi + ((size_t)b * Ln + l0) * CGn;
    const __nv_bfloat16* Al = g_ag_lo + ((size_t)b * Ln + l0) * CGn;

    float4 rw[8];
#pragma unroll
    for (int t = 0; t < 8; t++) {
        int idx = tid + t * 256, r = idx >> 4, q = idx & 15;
        rw[t] = *(const float4*)&Wo[(size_t)(c0 + r) * CGn + q * 4];
    }
#pragma unroll
    for (int t = 0; t < 4; t++) {
        int idx = tid + t * 256, r = idx >> 3, q = idx & 7;
        uint32_t so = r * 128 + ((q * 16) ^ ((r & 7) << 4));
        CP_ASYNC16(sb + 65536 + so, Ah + (size_t)r * CGn + q * 8);
        CP_ASYNC16(sb + 65536 + 16384 + so, Al + (size_t)r * CGn + q * 8);
    }
    CP_COMMIT();

    float acc[2][8][4];
#pragma unroll
    for (int mt = 0; mt < 2; mt++)
#pragma unroll
        for (int nt = 0; nt < 8; nt++)
#pragma unroll
            for (int j = 0; j < 4; j++) acc[mt][nt][j] = 0.f;

    int a_row_off = ((lane >> 3) & 1) * 8 + (lane & 7);
    int a_half = (lane >> 4) * 16;
    int b_row_off = (lane >> 4) * 8 + (lane & 7);
    int b_half = ((lane >> 3) & 1) * 16;
    uint32_t swl = (uint32_t)(lane & 7) << 4;

    for (int kc = 0; kc < 4; kc++) {
        uint32_t wa = sb + (uint32_t)(kc & 1) * 32768;
        uint32_t ba = sb + 65536 + (uint32_t)(kc & 1) * 32768;
#pragma unroll
        for (int t = 0; t < 8; t++) {
            int idx = tid + t * 256, r = idx >> 4, q = idx & 15;
            __nv_bfloat16 h0, e0, h1, e1, h2, e2, h3, e3;
            split_bf16(rw[t].x, h0, e0); split_bf16(rw[t].y, h1, e1);
            split_bf16(rw[t].z, h2, e2); split_bf16(rw[t].w, h3, e3);
            uint32_t so = r * 128 + ((q * 8) ^ ((r & 7) << 4));
            *(uint2*)(sm + (wa - sb) + so) = make_uint2(packbf(h0, h1), packbf(h2, h3));
            *(uint2*)(sm + (wa - sb) + 16384 + so) = make_uint2(packbf(e0, e1), packbf(e2, e3));
        }
        if (kc < 3) {
            int k0n = (kc + 1) * 64;
            uint32_t bn = 65536 + (uint32_t)((kc + 1) & 1) * 32768;
#pragma unroll
            for (int t = 0; t < 4; t++) {
                int idx = tid + t * 256, r = idx >> 3, q = idx & 7;
                uint32_t so = r * 128 + ((q * 16) ^ ((r & 7) << 4));
                CP_ASYNC16(sb + bn + so, Ah + (size_t)r * CGn + k0n + q * 8);
                CP_ASYNC16(sb + bn + 16384 + so, Al + (size_t)r * CGn + k0n + q * 8);
            }
            CP_COMMIT();
            CP_WAIT1();
        } else {
            CP_WAIT0();
        }
        __syncthreads();
        if (kc < 3) {
            int k0n = (kc + 1) * 64;
#pragma unroll
            for (int t = 0; t < 8; t++) {
                int idx = tid + t * 256, r = idx >> 4, q = idx & 15;
                rw[t] = *(const float4*)&Wo[(size_t)(c0 + r) * CGn + k0n + q * 4];
            }
        }
#pragma unroll
        for (int ks = 0; ks < 4; ks++) {
            int koff = ks * 32;
            uint32_t ah[2][4], al[2][4], bh[4][4], bl[4][4];
#pragma unroll
            for (int mt = 0; mt < 2; mt++) {
                uint32_t row = warp_m * 32 + mt * 16 + a_row_off;
                uint32_t ad = wa + row * 128 + (((uint32_t)(koff + a_half)) ^ swl);
                LDSM_X4(ah[mt][0], ah[mt][1], ah[mt][2], ah[mt][3], ad);
                LDSM_X4(al[mt][0], al[mt][1], al[mt][2], al[mt][3], ad + 16384);
            }
#pragma unroll
            for (int np = 0; np < 4; np++) {
                uint32_t row = warp_n * 64 + np * 16 + b_row_off;
                uint32_t ad = ba + row * 128 + (((uint32_t)(koff + b_half)) ^ swl);
                LDSM_X4(bh[np][0], bh[np][1], bh[np][2], bh[np][3], ad);
                LDSM_X4(bl[np][0], bl[np][1], bl[np][2], bl[np][3], ad + 16384);
            }
#pragma unroll
            for (int mt = 0; mt < 2; mt++)
#pragma unroll
                for (int np = 0; np < 4; np++) {
                    MMA_BF16(acc[mt][2 * np],     ah[mt], bh[np][0], bh[np][1]);
                    MMA_BF16(acc[mt][2 * np],     ah[mt], bl[np][0], bl[np][1]);
                    MMA_BF16(acc[mt][2 * np],     al[mt], bh[np][0], bh[np][1]);
                    MMA_BF16(acc[mt][2 * np + 1], ah[mt], bh[np][2], bh[np][3]);
                    MMA_BF16(acc[mt][2 * np + 1], ah[mt], bl[np][2], bl[np][3]);
                    MMA_BF16(acc[mt][2 * np + 1], al[mt], bh[np][2], bh[np][3]);
                }
        }
        __syncthreads();
    }

    float gv = gamma[0];
    float alpha = 1.0f / (1.0f + __expf(-gv));
    float* out1 = out;
    float* out2 = out + (size_t)Bn * Cn * Ln;
#pragma unroll
    for (int mt = 0; mt < 2; mt++)
#pragma unroll
        for (int nt = 0; nt < 8; nt++) {
            int rc = c0 + warp_m * 32 + mt * 16 + (lane >> 2);
            int cl = l0 + warp_n * 64 + nt * 8 + 2 * (lane & 3);
            float bv0 = bo[rc], bv1 = bo[rc + 8];
            size_t base0 = (size_t)b * Cn * Ln + (size_t)rc * Ln + cl;
            size_t base1 = (size_t)b * Cn * Ln + (size_t)(rc + 8) * Ln + cl;
            float2 v0 = make_float2(acc[mt][nt][0] + bv0, acc[mt][nt][1] + bv0);
            float2 v1 = make_float2(acc[mt][nt][2] + bv1, acc[mt][nt][3] + bv1);
            float2 x0 = *(const float2*)&x[base0];
            float2 x1 = *(const float2*)&x[base1];
            *(float2*)&out2[base0] = v0;
            *(float2*)&out2[base1] = v1;
            float2 o0 = make_float2((1.f - alpha) * x0.x + alpha * v0.x,
                                    (1.f - alpha) * x0.y + alpha * v0.y);
            float2 o1 = make_float2((1.f - alpha) * x1.x + alpha * v1.x,
                                    (1.f - alpha) * x1.y + alpha * v1.y);
            *(float2*)&out1[base0] = o0;
            *(float2*)&out1[base1] = o1;
        }
}

extern "C" void kernel_launch(void* const* d_in, const int* in_sizes, int n_in,
                              void* d_out, int out_size) {
    const float* x     = (const float*)d_in[0];
    const float* Wt    = (const float*)d_in[1];
    const float* bt    = (const float*)d_in[2];
    const float* Wp    = (const float*)d_in[3];
    const float* bp    = (const float*)d_in[4];
    const float* Wg    = (const float*)d_in[5];
    const float* bg    = (const float*)d_in[6];
    const float* Wo    = (const float*)d_in[7];
    const float* bo    = (const float*)d_in[8];
    const float* gamma = (const float*)d_in[9];
    float* out = (float*)d_out;

    cudaFuncSetAttribute(proj_mma, cudaFuncAttributeMaxDynamicSharedMemorySize, P_SMEM);
    cudaFuncSetAttribute(softstats_kernel, cudaFuncAttributeMaxDynamicSharedMemorySize, S_SMEM);
    cudaFuncSetAttribute(attn_fused, cudaFuncAttributeMaxDynamicSharedMemorySize, AT_SMEM);
    cudaFuncSetAttribute(final_mma, cudaFuncAttributeMaxDynamicSharedMemorySize, F_SMEM);

    proj_mma<<<dim3(Ln / 128, 3, Bn), 256, P_SMEM>>>(x, Wt, bt, Wp, bp, Wg, bg);
    softstats_kernel<<<dim3(Ln / 128, Bn), 256, S_SMEM>>>();
    transpose_scale_kernel<<<dim3(Ln / 32, CGn / 32, Bn), dim3(32, 8)>>>();
    attn_fused<<<dim3(Ln / 64, Bn), 256, AT_SMEM>>>();
    final_mma<<<dim3(Cn / 128, Ln / 128, Bn), 256, F_SMEM>>>(x, Wo, bo, gamma, out);
}

// round 9
// speedup vs baseline: 4.9585x; 1.0330x over previous
#include <cuda_runtime.h>
#include <cuda_bf16.h>
#include <math.h>
#include <stdint.h>

#define Bn 4
#define Cn 512
#define Ln 4096
#define CKn 64
#define CGn 256

// Scratch (allocation-free rule: static __device__ arrays)
__device__ __nv_bfloat16 g_th_hi[Bn * Ln * CKn];   // theta pre-scaled by log2(e)
__device__ __nv_bfloat16 g_th_lo[Bn * Ln * CKn];
__device__ __nv_bfloat16 g_ph_hi[Bn * Ln * CKn];
__device__ __nv_bfloat16 g_ph_lo[Bn * Ln * CKn];
__device__ float g_gv[Bn * Ln * CGn];
__device__ __nv_bfloat16 g_gt_hi[Bn * CGn * Ln];
__device__ __nv_bfloat16 g_gt_lo[Bn * CGn * Ln];
__device__ float g_colinv[Bn * Ln];
__device__ __nv_bfloat16 g_ag_hi[Bn * Ln * CGn];
__device__ __nv_bfloat16 g_ag_lo[Bn * Ln * CGn];

__device__ __forceinline__ uint32_t smem_u32(const void* p) {
    uint32_t a;
    asm("{ .reg .u64 t; cvta.to.shared.u64 t, %1; cvt.u32.u64 %0, t; }" : "=r"(a) : "l"(p));
    return a;
}

#define LDSM_X4(r0, r1, r2, r3, addr) \
    asm volatile("ldmatrix.sync.aligned.m8n8.x4.shared.b16 {%0,%1,%2,%3}, [%4];" \
                 : "=r"(r0), "=r"(r1), "=r"(r2), "=r"(r3) : "r"(addr))

#define LDSM_X4_T(r0, r1, r2, r3, addr) \
    asm volatile("ldmatrix.sync.aligned.m8n8.x4.trans.shared.b16 {%0,%1,%2,%3}, [%4];" \
                 : "=r"(r0), "=r"(r1), "=r"(r2), "=r"(r3) : "r"(addr))

#define MMA_BF16(d, a, b0, b1) \
    asm volatile("mma.sync.aligned.m16n8k16.row.col.f32.bf16.bf16.f32 " \
                 "{%0,%1,%2,%3},{%4,%5,%6,%7},{%8,%9},{%0,%1,%2,%3};" \
                 : "+f"((d)[0]), "+f"((d)[1]), "+f"((d)[2]), "+f"((d)[3]) \
                 : "r"((a)[0]), "r"((a)[1]), "r"((a)[2]), "r"((a)[3]), "r"(b0), "r"(b1))

#define CP_ASYNC16(smem, gptr) \
    asm volatile("cp.async.cg.shared.global [%0], [%1], 16;" :: "r"(smem), "l"(gptr))
#define CP_COMMIT() asm volatile("cp.async.commit_group;")
#define CP_WAIT0()  asm volatile("cp.async.wait_group 0;")
#define CP_WAIT1()  asm volatile("cp.async.wait_group 1;")
#define CP_WAIT2()  asm volatile("cp.async.wait_group 2;")

__device__ __forceinline__ void split_bf16(float f, __nv_bfloat16& hi, __nv_bfloat16& lo) {
    hi = __float2bfloat16(f);
    lo = __float2bfloat16(f - __bfloat162float(hi));
}
__device__ __forceinline__ uint32_t packbf(__nv_bfloat16 a, __nv_bfloat16 b) {
    return ((uint32_t)__bfloat16_as_ushort(b) << 16) | __bfloat16_as_ushort(a);
}
__device__ __forceinline__ float ex2f(float x) {
    float r;
    asm("ex2.approx.f32 %0, %1;" : "=f"(r) : "f"(x));
    return r;
}

// ===========================================================================
// K1: projections via bf16x3 mma. theta scaled by log2(e) (ex2 softmax).
// ===========================================================================
#define P_SMEM 131072

__global__ void __launch_bounds__(256, 1) proj_mma(const float* __restrict__ x,
                            const float* __restrict__ Wt, const float* __restrict__ bt,
                            const float* __restrict__ Wp, const float* __restrict__ bp,
                            const float* __restrict__ Wg, const float* __restrict__ bg) {
    extern __shared__ char sm[];
    uint32_t sb = smem_u32(sm);
    int tid = threadIdx.x, lane = tid & 31, wid = tid >> 5;
    int warp_m = wid & 3, warp_n = wid >> 2;
    int l0 = blockIdx.x * 128, grp = blockIdx.y, b = blockIdx.z;
    const float* xb = x + (size_t)b * Cn * Ln;

    float4 rx[8], rw[8];
#pragma unroll
    for (int t = 0; t < 8; t++) {
        int idx = tid + t * 256, r = idx >> 5, q = idx & 31;
        rx[t] = *(const float4*)&xb[(size_t)r * Ln + l0 + q * 4];
    }
#pragma unroll
    for (int t = 0; t < 8; t++) {
        int idx = tid + t * 256, r = idx >> 4, q = idx & 15;
        const float* Wrow;
        if (grp == 0) Wrow = (r < 64) ? Wt + (size_t)r * Cn : Wp + (size_t)(r - 64) * Cn;
        else          Wrow = Wg + (size_t)((grp - 1) * 128 + r) * Cn;
        rw[t] = *(const float4*)&Wrow[q * 4];
    }

    float acc[2][8][4];
#pragma unroll
    for (int mt = 0; mt < 2; mt++)
#pragma unroll
        for (int nt = 0; nt < 8; nt++)
#pragma unroll
            for (int j = 0; j < 4; j++) acc[mt][nt][j] = 0.f;

    int b_row_off = (lane >> 4) * 8 + (lane & 7);
    int b_half = ((lane >> 3) & 1) * 16;
    uint32_t swl = (uint32_t)(lane & 7) << 4;

    for (int kc = 0; kc < 8; kc++) {
        uint32_t xa = sb + (uint32_t)(kc & 1) * 32768;
        uint32_t wb = sb + 65536 + (uint32_t)(kc & 1) * 32768;
#pragma unroll
        for (int t = 0; t < 8; t++) {
            int idx = tid + t * 256, r = idx >> 5, q = idx & 31;
            __nv_bfloat16 h0, e0, h1, e1, h2, e2, h3, e3;
            split_bf16(rx[t].x, h0, e0); split_bf16(rx[t].y, h1, e1);
            split_bf16(rx[t].z, h2, e2); split_bf16(rx[t].w, h3, e3);
            uint32_t so = r * 256 + ((q * 8) ^ ((r & 7) << 4));
            *(uint2*)(sm + (xa - sb) + so) = make_uint2(packbf(h0, h1), packbf(h2, h3));
            *(uint2*)(sm + (xa - sb) + 16384 + so) = make_uint2(packbf(e0, e1), packbf(e2, e3));
        }
#pragma unroll
        for (int t = 0; t < 8; t++) {
            int idx = tid + t * 256, r = idx >> 4, q = idx & 15;
            __nv_bfloat16 h0, e0, h1, e1, h2, e2, h3, e3;
            split_bf16(rw[t].x, h0, e0); split_bf16(rw[t].y, h1, e1);
            split_bf16(rw[t].z, h2, e2); split_bf16(rw[t].w, h3, e3);
            uint32_t so = r * 128 + ((q * 8) ^ ((r & 7) << 4));
            *(uint2*)(sm + (wb - sb) + so) = make_uint2(packbf(h0, h1), packbf(h2, h3));
            *(uint2*)(sm + (wb - sb) + 16384 + so) = make_uint2(packbf(e0, e1), packbf(e2, e3));
        }
        __syncthreads();
        if (kc < 7) {
            int k0n = (kc + 1) * 64;
#pragma unroll
            for (int t = 0; t < 8; t++) {
                int idx = tid + t * 256, r = idx >> 5, q = idx & 31;
                rx[t] = *(const float4*)&xb[(size_t)(k0n + r) * Ln + l0 + q * 4];
            }
#pragma unroll
            for (int t = 0; t < 8; t++) {
                int idx = tid + t * 256, r = idx >> 4, q = idx & 15;
                const float* Wrow;
                if (grp == 0) Wrow = (r < 64) ? Wt + (size_t)r * Cn : Wp + (size_t)(r - 64) * Cn;
                else          Wrow = Wg + (size_t)((grp - 1) * 128 + r) * Cn;
                rw[t] = *(const float4*)&Wrow[k0n + q * 4];
            }
        }
#pragma unroll
        for (int ks = 0; ks < 4; ks++) {
            uint32_t ah[2][4], al[2][4], bh[4][4], bl[4][4];
            uint32_t srow = (uint32_t)(ks * 16 + (lane & 7) + ((lane >> 4) & 1) * 8);
#pragma unroll
            for (int mt = 0; mt < 2; mt++) {
                uint32_t mb = (uint32_t)(warp_m * 32 + mt * 16 + ((lane >> 3) & 1) * 8) * 2;
                uint32_t ad = xa + srow * 256 + (mb ^ swl);
                LDSM_X4_T(ah[mt][0], ah[mt][1], ah[mt][2], ah[mt][3], ad);
                LDSM_X4_T(al[mt][0], al[mt][1], al[mt][2], al[mt][3], ad + 16384);
            }
#pragma unroll
            for (int np = 0; np < 4; np++) {
                uint32_t row = (uint32_t)(warp_n * 64 + np * 16 + b_row_off);
                uint32_t ad = wb + row * 128 + (((uint32_t)(ks * 32 + b_half)) ^ swl);
                LDSM_X4(bh[np][0], bh[np][1], bh[np][2], bh[np][3], ad);
                LDSM_X4(bl[np][0], bl[np][1], bl[np][2], bl[np][3], ad + 16384);
            }
#pragma unroll
            for (int mt = 0; mt < 2; mt++)
#pragma unroll
                for (int np = 0; np < 4; np++) {
                    MMA_BF16(acc[mt][2 * np],     ah[mt], bh[np][0], bh[np][1]);
                    MMA_BF16(acc[mt][2 * np],     ah[mt], bl[np][0], bl[np][1]);
                    MMA_BF16(acc[mt][2 * np],     al[mt], bh[np][0], bh[np][1]);
                    MMA_BF16(acc[mt][2 * np + 1], ah[mt], bh[np][2], bh[np][3]);
                    MMA_BF16(acc[mt][2 * np + 1], ah[mt], bl[np][2], bl[np][3]);
                    MMA_BF16(acc[mt][2 * np + 1], al[mt], bh[np][2], bh[np][3]);
                }
        }
        __syncthreads();
    }

    if (grp == 0) {
        __nv_bfloat16* ohi = (warp_n == 0 ? g_th_hi : g_ph_hi) + (size_t)b * Ln * CKn;
        __nv_bfloat16* olo = (warp_n == 0 ? g_th_lo : g_ph_lo) + (size_t)b * Ln * CKn;
        const float* bias = (warp_n == 0 ? bt : bp);
        float sc = (warp_n == 0) ? 1.4426950408889634f : 1.0f;  // log2(e) for theta
#pragma unroll
        for (int mt = 0; mt < 2; mt++)
#pragma unroll
            for (int nt = 0; nt < 8; nt++) {
                int r = warp_m * 32 + mt * 16 + (lane >> 2);
                int cl = nt * 8 + 2 * (lane & 3);
                float bv0 = bias[cl], bv1 = bias[cl + 1];
                float v00 = tanhf(acc[mt][nt][0] + bv0) * sc;
                float v01 = tanhf(acc[mt][nt][1] + bv1) * sc;
                float v10 = tanhf(acc[mt][nt][2] + bv0) * sc;
                float v11 = tanhf(acc[mt][nt][3] + bv1) * sc;
                __nv_bfloat16 h0, e0, h1, e1;
                split_bf16(v00, h0, e0); split_bf16(v01, h1, e1);
                size_t o = (size_t)(l0 + r) * CKn + cl;
                *(uint32_t*)((char*)ohi + o * 2) = packbf(h0, h1);
                *(uint32_t*)((char*)olo + o * 2) = packbf(e0, e1);
                split_bf16(v10, h0, e0); split_bf16(v11, h1, e1);
                o = (size_t)(l0 + r + 8) * CKn + cl;
                *(uint32_t*)((char*)ohi + o * 2) = packbf(h0, h1);
                *(uint32_t*)((char*)olo + o * 2) = packbf(e0, e1);
            }
    } else {
        float* outp = g_gv + (size_t)b * Ln * CGn;
        int goff = (grp - 1) * 128 + warp_n * 64;
#pragma unroll
        for (int mt = 0; mt < 2; mt++)
#pragma unroll
            for (int nt = 0; nt < 8; nt++) {
                int r = warp_m * 32 + mt * 16 + (lane >> 2);
                int cl = nt * 8 + 2 * (lane & 3);
                int c = goff + cl;
                float bv0 = bg[c], bv1 = bg[c + 1];
                float2 v0 = make_float2(acc[mt][nt][0] + bv0, acc[mt][nt][1] + bv1);
                float2 v1 = make_float2(acc[mt][nt][2] + bv0, acc[mt][nt][3] + bv1);
                *(float2*)&outp[(size_t)(l0 + r) * CGn + c] = v0;
                *(float2*)&outp[(size_t)(l0 + r + 8) * CGn + c] = v1;
            }
    }
}

// ===========================================================================
// K2: softstats — per-column (m) sum of exp2(S') over all l.
// 4-deep theta ring: one sync per chunk.
// SMEM: PH @0 (hi/lo 16K); TH buf s at 32768+s*32768 (hi/lo 16K); WSM 163840.
// ===========================================================================
#define S_PH 0
#define S_TH(s) (32768 + (s) * 32768)
#define S_WSM   163840
#define S_SMEM  165888

__global__ void __launch_bounds__(256, 1) softstats_kernel() {
    extern __shared__ char sm[];
    uint32_t sb = smem_u32(sm);
    int tid = threadIdx.x;
    int lane = tid & 31, wid = tid >> 5;
    int warp_m = wid & 3, warp_n = wid >> 2;
    int m0 = blockIdx.x * 128, b = blockIdx.y;

    const __nv_bfloat16* thh = g_th_hi + (size_t)b * Ln * CKn;
    const __nv_bfloat16* thl = g_th_lo + (size_t)b * Ln * CKn;
    const __nv_bfloat16* phh = g_ph_hi + (size_t)b * Ln * CKn;
    const __nv_bfloat16* phl = g_ph_lo + (size_t)b * Ln * CKn;

    // prologue: theta chunks 0,1,2 as 3 groups; phi tile via LDG
#pragma unroll
    for (int s = 0; s < 3; s++) {
#pragma unroll
        for (int t = 0; t < 4; t++) {
            int idx = tid + t * 256;
            int r = idx >> 3, q = idx & 7;
            uint32_t so = r * 128 + ((q * 16) ^ ((r & 7) << 4));
            CP_ASYNC16(sb + S_TH(s) + so, thh + ((size_t)(s * 128 + r)) * CKn + q * 8);
            CP_ASYNC16(sb + S_TH(s) + 16384 + so, thl + ((size_t)(s * 128 + r)) * CKn + q * 8);
        }
        CP_COMMIT();
    }
#pragma unroll
    for (int t = 0; t < 4; t++) {
        int idx = tid + t * 256;
        int r = idx >> 3, q = idx & 7;
        uint32_t so = r * 128 + ((q * 16) ^ ((r & 7) << 4));
        *(uint4*)(sm + S_PH + so) = *(const uint4*)(phh + ((size_t)(m0 + r)) * CKn + q * 8);
        *(uint4*)(sm + S_PH + 16384 + so) = *(const uint4*)(phl + ((size_t)(m0 + r)) * CKn + q * 8);
    }

    float sum[16];
#pragma unroll
    for (int i = 0; i < 16; i++) sum[i] = 0.f;

    int a_row_off = ((lane >> 3) & 1) * 8 + (lane & 7);
    int a_half = (lane >> 4) * 16;
    int b_row_off = (lane >> 4) * 8 + (lane & 7);
    int b_half = ((lane >> 3) & 1) * 16;
    uint32_t swl = (uint32_t)(lane & 7) << 4;

    for (int lc = 0; lc < 32; lc++) {
        CP_WAIT2();
        __syncthreads();
        // refill theta chunk lc+3 into buffer (lc+3)&3 (safe: last used chunk lc-1)
        {
            int ln = (lc + 3) & 31;
            uint32_t bufo = S_TH((lc + 3) & 3);
#pragma unroll
            for (int t = 0; t < 4; t++) {
                int idx = tid + t * 256;
                int r = idx >> 3, q = idx & 7;
                uint32_t so = r * 128 + ((q * 16) ^ ((r & 7) << 4));
                CP_ASYNC16(sb + bufo + so, thh + ((size_t)(ln * 128 + r)) * CKn + q * 8);
                CP_ASYNC16(sb + bufo + 16384 + so, thl + ((size_t)(ln * 128 + r)) * CKn + q * 8);
            }
            CP_COMMIT();
        }
        uint32_t thb = sb + S_TH(lc & 3);
        float acc[2][8][4];
#pragma unroll
        for (int mt = 0; mt < 2; mt++)
#pragma unroll
            for (int nt = 0; nt < 8; nt++)
#pragma unroll
                for (int j = 0; j < 4; j++) acc[mt][nt][j] = 0.f;

#pragma unroll
        for (int ks = 0; ks < 4; ks++) {
            int koff = ks * 32;
            uint32_t ah[2][4], al[2][4], bh[4][4], bl[4][4];
#pragma unroll
            for (int mt = 0; mt < 2; mt++) {
                uint32_t row = warp_m * 32 + mt * 16 + a_row_off;
                uint32_t ad = thb + row * 128 + (((uint32_t)(koff + a_half)) ^ swl);
                LDSM_X4(ah[mt][0], ah[mt][1], ah[mt][2], ah[mt][3], ad);
                LDSM_X4(al[mt][0], al[mt][1], al[mt][2], al[mt][3], ad + 16384);
            }
#pragma unroll
            for (int np = 0; np < 4; np++) {
                uint32_t row = warp_n * 64 + np * 16 + b_row_off;
                uint32_t ad = sb + S_PH + row * 128 + (((uint32_t)(koff + b_half)) ^ swl);
                LDSM_X4(bh[np][0], bh[np][1], bh[np][2], bh[np][3], ad);
                LDSM_X4(bl[np][0], bl[np][1], bl[np][2], bl[np][3], ad + 16384);
            }
#pragma unroll
            for (int mt = 0; mt < 2; mt++)
#pragma unroll
                for (int np = 0; np < 4; np++) {
                    MMA_BF16(acc[mt][2 * np],     ah[mt], bh[np][0], bh[np][1]);
                    MMA_BF16(acc[mt][2 * np],     ah[mt], bl[np][0], bl[np][1]);
                    MMA_BF16(acc[mt][2 * np],     al[mt], bh[np][0], bh[np][1]);
                    MMA_BF16(acc[mt][2 * np + 1], ah[mt], bh[np][2], bh[np][3]);
                    MMA_BF16(acc[mt][2 * np + 1], ah[mt], bl[np][2], bl[np][3]);
                    MMA_BF16(acc[mt][2 * np + 1], al[mt], bh[np][2], bh[np][3]);
                }
        }
#pragma unroll
        for (int nt = 0; nt < 8; nt++)
#pragma unroll
            for (int j = 0; j < 2; j++) {
                int ix = nt * 2 + j;
                sum[ix] += ex2f(acc[0][nt][j]) + ex2f(acc[0][nt][j + 2])
                         + ex2f(acc[1][nt][j]) + ex2f(acc[1][nt][j + 2]);
            }
    }

#pragma unroll
    for (int s = 4; s <= 16; s <<= 1)
#pragma unroll
        for (int i = 0; i < 16; i++)
            sum[i] += __shfl_xor_sync(0xffffffffu, sum[i], s);

    float* wsm = (float*)(sm + S_WSM);
    __syncthreads();
    if (lane < 4) {
#pragma unroll
        for (int nt = 0; nt < 8; nt++)
#pragma unroll
            for (int j = 0; j < 2; j++) {
                int c = warp_n * 64 + nt * 8 + 2 * lane + j;
                wsm[warp_m * 128 + c] = sum[nt * 2 + j];
            }
    }
    __syncthreads();
    if (tid < 128) {
        float S = 0.f;
#pragma unroll
        for (int w = 0; w < 4; w++) S += wsm[w * 128 + tid];
        g_colinv[b * Ln + m0 + tid] = 1.0f / S;
    }
}

// ===========================================================================
// K3: gT transpose+scale (unchanged).
// ===========================================================================
__global__ void transpose_scale_kernel() {
    __shared__ float t[32][33];
    int m0 = blockIdx.x * 32, c0 = blockIdx.y * 32, b = blockIdx.z;
    int tx = threadIdx.x, ty = threadIdx.y;
#pragma unroll
    for (int i = 0; i < 32; i += 8) {
        int m = m0 + ty + i;
        t[ty + i][tx] = g_gv[((size_t)b * Ln + m) * CGn + c0 + tx] * g_colinv[b * Ln + m];
    }
    __syncthreads();
#pragma unroll
    for (int i = 0; i < 32; i += 8) {
        float v = t[tx][ty + i];
        __nv_bfloat16 hi, lo;
        split_bf16(v, hi, lo);
        size_t o = ((size_t)b * CGn + c0 + ty + i) * Ln + m0 + tx;
        g_gt_hi[o] = hi;
        g_gt_lo[o] = lo;
    }
}

// ===========================================================================
// K4: fused attention, 64l x 256c CTA, register-resident P, 4-quarter gT
// ring (buffer q == c-quarter q) + single-stage phi. One sync per quarter.
// SMEM: TH @0 (hi 8K, lo 8K); PH @16384 (hi/lo 16K);
//       GT quarter q at 49152+q*32768 (hi/lo 16K). Total 180224.
// ===========================================================================
#define AT_TH    0
#define AT_PH    16384
#define AT_GTQ(q) (49152 + (q) * 32768)
#define AT_RED   16384
#define AT_SMEM  180224

__global__ void __launch_bounds__(256, 1) attn_fused() {
    extern __shared__ char sm[];
    uint32_t sb = smem_u32(sm);
    int tid = threadIdx.x;
    int lane = tid & 31, wid = tid >> 5;
    int warp_m = wid & 3, warp_n = wid >> 2;
    int l0 = blockIdx.x * 64, b = blockIdx.y;

    const __nv_bfloat16* thh = g_th_hi + (size_t)b * Ln * CKn;
    const __nv_bfloat16* thl = g_th_lo + (size_t)b * Ln * CKn;
    const __nv_bfloat16* phh = g_ph_hi + (size_t)b * Ln * CKn;
    const __nv_bfloat16* phl = g_ph_lo + (size_t)b * Ln * CKn;
    const __nv_bfloat16* Gh = g_gt_hi + (size_t)b * CGn * Ln;
    const __nv_bfloat16* Gl = g_gt_lo + (size_t)b * CGn * Ln;

    // --- refill helpers (inlined via macros over local lambdas) ---
    // quarter Q: c-quarter cq=Q&3 (buffer cq), m-chunk kq=(Q>>2)&31
#define REFILL_Q(Q) do { \
        int _kq = ((Q) >> 2) & 31, _cq = (Q) & 3; \
        uint32_t _bo = AT_GTQ(_cq); \
        _Pragma("unroll") \
        for (int _t = 0; _t < 4; _t++) { \
            int _idx = tid + _t * 256, _r = _idx >> 4, _q = _idx & 15; \
            uint32_t _so = _r * 256 + ((_q * 16) ^ ((_r & 7) << 4)); \
            CP_ASYNC16(sb + _bo + _so, Gh + (size_t)(_cq * 64 + _r) * Ln + _kq * 128 + _q * 8); \
            CP_ASYNC16(sb + _bo + 16384 + _so, Gl + (size_t)(_cq * 64 + _r) * Ln + _kq * 128 + _q * 8); \
        } \
    } while (0)
#define REFILL_PH(K) do { \
        int _k = (K) & 31; \
        _Pragma("unroll") \
        for (int _t = 0; _t < 4; _t++) { \
            int _idx = tid + _t * 256, _r = _idx >> 3, _q = _idx & 7; \
            uint32_t _so = _r * 128 + ((_q * 16) ^ ((_r & 7) << 4)); \
            CP_ASYNC16(sb + AT_PH + _so, phh + (size_t)(_k * 128 + _r) * CKn + _q * 8); \
            CP_ASYNC16(sb + AT_PH + 16384 + _so, phl + (size_t)(_k * 128 + _r) * CKn + _q * 8); \
        } \
    } while (0)

    // prologue: groups {Q0+phi0}, {Q1}, {Q2}; theta via LDG
    REFILL_PH(0);
    REFILL_Q(0);
    CP_COMMIT();
    REFILL_Q(1);
    CP_COMMIT();
    REFILL_Q(2);
    CP_COMMIT();
#pragma unroll
    for (int t = 0; t < 2; t++) {
        int idx = tid + t * 256, r = idx >> 3, q = idx & 7;
        uint32_t so = r * 128 + ((q * 16) ^ ((r & 7) << 4));
        *(uint4*)(sm + AT_TH + so) = *(const uint4*)(thh + (size_t)(l0 + r) * CKn + q * 8);
        *(uint4*)(sm + AT_TH + 8192 + so) = *(const uint4*)(thl + (size_t)(l0 + r) * CKn + q * 8);
    }

    float acc2[4][8][4];
#pragma unroll
    for (int q = 0; q < 4; q++)
#pragma unroll
        for (int nt = 0; nt < 8; nt++)
#pragma unroll
            for (int j = 0; j < 4; j++) acc2[q][nt][j] = 0.f;

    int a_row_off = ((lane >> 3) & 1) * 8 + (lane & 7);
    int a_half = (lane >> 4) * 16;
    int b_row_off = (lane >> 4) * 8 + (lane & 7);
    int b_half = ((lane >> 3) & 1) * 16;
    uint32_t swl = (uint32_t)(lane & 7) << 4;

    for (int k = 0; k < 32; k++) {
        CP_WAIT2();          // retires {Q(k,0), phi(k)}
        __syncthreads();
        REFILL_Q(k * 4 + 3); // buffer 3, last read in chunk k-1 quarter 3
        CP_COMMIT();

        // GEMM1: S (16l x 64m per warp), K=64
        float acc1[8][4];
#pragma unroll
        for (int nt = 0; nt < 8; nt++)
#pragma unroll
            for (int j = 0; j < 4; j++) acc1[nt][j] = 0.f;

#pragma unroll
        for (int ks = 0; ks < 4; ks++) {
            int koff = ks * 32;
            uint32_t ah[4], al[4], bh[4][4], bl[4][4];
            {
                uint32_t row = warp_m * 16 + a_row_off;
                uint32_t ad = sb + AT_TH + row * 128 + (((uint32_t)(koff + a_half)) ^ swl);
                LDSM_X4(ah[0], ah[1], ah[2], ah[3], ad);
                LDSM_X4(al[0], al[1], al[2], al[3], ad + 8192);
            }
#pragma unroll
            for (int np = 0; np < 4; np++) {
                uint32_t row = warp_n * 64 + np * 16 + b_row_off;
                uint32_t ad = sb + AT_PH + row * 128 + (((uint32_t)(koff + b_half)) ^ swl);
                LDSM_X4(bh[np][0], bh[np][1], bh[np][2], bh[np][3], ad);
                LDSM_X4(bl[np][0], bl[np][1], bl[np][2], bl[np][3], ad + 16384);
            }
#pragma unroll
            for (int np = 0; np < 4; np++) {
                MMA_BF16(acc1[2 * np],     ah, bh[np][0], bh[np][1]);
                MMA_BF16(acc1[2 * np],     ah, bl[np][0], bl[np][1]);
                MMA_BF16(acc1[2 * np],     al, bh[np][0], bh[np][1]);
                MMA_BF16(acc1[2 * np + 1], ah, bh[np][2], bh[np][3]);
                MMA_BF16(acc1[2 * np + 1], ah, bl[np][2], bl[np][3]);
                MMA_BF16(acc1[2 * np + 1], al, bh[np][2], bh[np][3]);
            }
        }

        // exp2 + split to A-fragments (register-resident P)
        uint32_t afh[4][4], afl[4][4];
#pragma unroll
        for (int ks = 0; ks < 4; ks++)
#pragma unroll
            for (int h01 = 0; h01 < 2; h01++) {
                int nt = 2 * ks + h01;
#pragma unroll
                for (int p = 0; p < 2; p++) {
                    float e0 = ex2f(acc1[nt][2 * p]);
                    float e1 = ex2f(acc1[nt][2 * p + 1]);
                    __nv_bfloat16 h0, l0_, h1, l1;
                    split_bf16(e0, h0, l0_);
                    split_bf16(e1, h1, l1);
                    afh[ks][h01 * 2 + p] = packbf(h0, h1);
                    afl[ks][h01 * 2 + p] = packbf(l0_, l1);
                }
            }

        // GEMM2 over four gT c-quarters
#pragma unroll
        for (int q = 0; q < 4; q++) {
            if (q > 0) {
                CP_WAIT2();       // retires {Q(k,q)}
                __syncthreads();  // all warps done reading buffer being refilled
                int Qn = k * 4 + q + 3;
                REFILL_Q(Qn);
                if (q == 1) REFILL_PH(k + 1);
                CP_COMMIT();
            }
            uint32_t gtb = sb + AT_GTQ(q);
#pragma unroll
            for (int ks = 0; ks < 4; ks++) {
                uint32_t koff = (uint32_t)(warp_n * 128 + ks * 32);
#pragma unroll
                for (int np = 0; np < 4; np++) {
                    uint32_t row = np * 16 + b_row_off;
                    uint32_t ad = gtb + row * 256 + ((koff + (uint32_t)b_half) ^ swl);
                    uint32_t bh[4], bl[4];
                    LDSM_X4(bh[0], bh[1], bh[2], bh[3], ad);
                    LDSM_X4(bl[0], bl[1], bl[2], bl[3], ad + 16384);
                    MMA_BF16(acc2[q][2 * np],     afh[ks], bh[0], bh[1]);
                    MMA_BF16(acc2[q][2 * np],     afh[ks], bl[0], bl[1]);
                    MMA_BF16(acc2[q][2 * np],     afl[ks], bh[0], bh[1]);
                    MMA_BF16(acc2[q][2 * np + 1], afh[ks], bh[2], bh[3]);
                    MMA_BF16(acc2[q][2 * np + 1], afh[ks], bl[2], bl[3]);
                    MMA_BF16(acc2[q][2 * np + 1], afl[ks], bh[2], bh[3]);
                }
            }
        }
    }

    // cross-warp_n (m-split) reduction; then write AG as bf16 hi/lo
    CP_WAIT0();
    __syncthreads();
    float* red = (float*)(sm + AT_RED);
    if (warp_n == 1) {
#pragma unroll
        for (int q = 0; q < 4; q++)
#pragma unroll
            for (int nt = 0; nt < 8; nt++) {
                int r = warp_m * 16 + (lane >> 2);
                int c = q * 64 + nt * 8 + 2 * (lane & 3);
                red[r * 260 + c] = acc2[q][nt][0];
                red[r * 260 + c + 1] = acc2[q][nt][1];
                red[(r + 8) * 260 + c] = acc2[q][nt][2];
                red[(r + 8) * 260 + c + 1] = acc2[q][nt][3];
            }
    }
    __syncthreads();
    if (warp_n == 0) {
#pragma unroll
        for (int q = 0; q < 4; q++)
#pragma unroll
            for (int nt = 0; nt < 8; nt++) {
                int rr = warp_m * 16 + (lane >> 2);
                int cc = q * 64 + nt * 8 + 2 * (lane & 3);
                float v00 = acc2[q][nt][0] + red[rr * 260 + cc];
                float v01 = acc2[q][nt][1] + red[rr * 260 + cc + 1];
                float v10 = acc2[q][nt][2] + red[(rr + 8) * 260 + cc];
                float v11 = acc2[q][nt][3] + red[(rr + 8) * 260 + cc + 1];
                __nv_bfloat16 h0, e0, h1, e1;
                size_t o = ((size_t)b * Ln + l0 + rr) * CGn + cc;
                split_bf16(v00, h0, e0); split_bf16(v01, h1, e1);
                *(uint32_t*)((char*)g_ag_hi + o * 2) = packbf(h0, h1);
                *(uint32_t*)((char*)g_ag_lo + o * 2) = packbf(e0, e1);
                o = ((size_t)b * Ln + l0 + rr + 8) * CGn + cc;
                split_bf16(v10, h0, e0); split_bf16(v11, h1, e1);
                *(uint32_t*)((char*)g_ag_hi + o * 2) = packbf(h0, h1);
                *(uint32_t*)((char*)g_ag_lo + o * 2) = packbf(e0, e1);
            }
    }
#undef REFILL_Q
#undef REFILL_PH
}

// ===========================================================================
// K5: out-projection + blend via bf16x3 mma (unchanged from R8).
// ===========================================================================
#define F_SMEM 131072

__global__ void __launch_bounds__(256, 1) final_mma(const float* __restrict__ x,
                             const float* __restrict__ Wo, const float* __restrict__ bo,
                             const float* __restrict__ gamma, float* __restrict__ out) {
    extern __shared__ char sm[];
    uint32_t sb = smem_u32(sm);
    int tid = threadIdx.x, lane = tid & 31, wid = tid >> 5;
    int warp_m = wid & 3, warp_n = wid >> 2;
    int c0 = blockIdx.x * 128, l0 = blockIdx.y * 128, b = blockIdx.z;

    const __nv_bfloat16* Ah = g_ag_hi + ((size_t)b * Ln + l0) * CGn;
    const __nv_bfloat16* Al = g_ag_lo + ((size_t)b * Ln + l0) * CGn;

    float4 rw[8];
#pragma unroll
    for (int t = 0; t < 8; t++) {
        int idx = tid + t * 256, r = idx >> 4, q = idx & 15;
        rw[t] = *(const float4*)&Wo[(size_t)(c0 + r) * CGn + q * 4];
    }
#pragma unroll
    for (int t = 0; t < 4; t++) {
        int idx = tid + t * 256, r = idx >> 3, q = idx & 7;
        uint32_t so = r * 128 + ((q * 16) ^ ((r & 7) << 4));
        CP_ASYNC16(sb + 65536 + so, Ah + (size_t)r * CGn + q * 8);
        CP_ASYNC16(sb + 65536 + 16384 + so, Al + (size_t)r * CGn + q * 8);
    }
    CP_COMMIT();

    float acc[2][8][4];
#pragma unroll
    for (int mt = 0; mt < 2; mt++)
#pragma unroll
        for (int nt = 0; nt < 8; nt++)
#pragma unroll
            for (int j = 0; j < 4; j++) acc[mt][nt][j] = 0.f;

    int a_row_off = ((lane >> 3) & 1) * 8 + (lane & 7);
    int a_half = (lane >> 4) * 16;
    int b_row_off = (lane >> 4) * 8 + (lane & 7);
    int b_half = ((lane >> 3) & 1) * 16;
    uint32_t swl = (uint32_t)(lane & 7) << 4;

    for (int kc = 0; kc < 4; kc++) {
        uint32_t wa = sb + (uint32_t)(kc & 1) * 32768;
        uint32_t ba = sb + 65536 + (uint32_t)(kc & 1) * 32768;
#pragma unroll
        for (int t = 0; t < 8; t++) {
            int idx = tid + t * 256, r = idx >> 4, q = idx & 15;
            __nv_bfloat16 h0, e0, h1, e1, h2, e2, h3, e3;
            split_bf16(rw[t].x, h0, e0); split_bf16(rw[t].y, h1, e1);
            split_bf16(rw[t].z, h2, e2); split_bf16(rw[t].w, h3, e3);
            uint32_t so = r * 128 + ((q * 8) ^ ((r & 7) << 4));
            *(uint2*)(sm + (wa - sb) + so) = make_uint2(packbf(h0, h1), packbf(h2, h3));
            *(uint2*)(sm + (wa - sb) + 16384 + so) = make_uint2(packbf(e0, e1), packbf(e2, e3));
        }
        if (kc < 3) {
            int k0n = (kc + 1) * 64;
            uint32_t bn = 65536 + (uint32_t)((kc + 1) & 1) * 32768;
#pragma unroll
            for (int t = 0; t < 4; t++) {
                int idx = tid + t * 256, r = idx >> 3, q = idx & 7;
                uint32_t so = r * 128 + ((q * 16) ^ ((r & 7) << 4));
                CP_ASYNC16(sb + bn + so, Ah + (size_t)r * CGn + k0n + q * 8);
                CP_ASYNC16(sb + bn + 16384 + so, Al + (size_t)r * CGn + k0n + q * 8);
            }
            CP_COMMIT();
            CP_WAIT1();
        } else {
            CP_WAIT0();
        }
        __syncthreads();
        if (kc < 3) {
            int k0n = (kc + 1) * 64;
#pragma unroll
            for (int t = 0; t < 8; t++) {
                int idx = tid + t * 256, r = idx >> 4, q = idx & 15;
                rw[t] = *(const float4*)&Wo[(size_t)(c0 + r) * CGn + k0n + q * 4];
            }
        }
#pragma unroll
        for (int ks = 0; ks < 4; ks++) {
            int koff = ks * 32;
            uint32_t ah[2][4], al[2][4], bh[4][4], bl[4][4];
#pragma unroll
            for (int mt = 0; mt < 2; mt++) {
                uint32_t row = warp_m * 32 + mt * 16 + a_row_off;
                uint32_t ad = wa + row * 128 + (((uint32_t)(koff + a_half)) ^ swl);
                LDSM_X4(ah[mt][0], ah[mt][1], ah[mt][2], ah[mt][3], ad);
                LDSM_X4(al[mt][0], al[mt][1], al[mt][2], al[mt][3], ad + 16384);
            }
#pragma unroll
            for (int np = 0; np < 4; np++) {
                uint32_t row = warp_n * 64 + np * 16 + b_row_off;
                uint32_t ad = ba + row * 128 + (((uint32_t)(koff + b_half)) ^ swl);
                LDSM_X4(bh[np][0], bh[np][1], bh[np][2], bh[np][3], ad);
                LDSM_X4(bl[np][0], bl[np][1], bl[np][2], bl[np][3], ad + 16384);
            }
#pragma unroll
            for (int mt = 0; mt < 2; mt++)
#pragma unroll
                for (int np = 0; np < 4; np++) {
                    MMA_BF16(acc[mt][2 * np],     ah[mt], bh[np][0], bh[np][1]);
                    MMA_BF16(acc[mt][2 * np],     ah[mt], bl[np][0], bl[np][1]);
                    MMA_BF16(acc[mt][2 * np],     al[mt], bh[np][0], bh[np][1]);
                    MMA_BF16(acc[mt][2 * np + 1], ah[mt], bh[np][2], bh[np][3]);
                    MMA_BF16(acc[mt][2 * np + 1], ah[mt], bl[np][2], bl[np][3]);
                    MMA_BF16(acc[mt][2 * np + 1], al[mt], bh[np][2], bh[np][3]);
                }
        }
        __syncthreads();
    }

    float gv = gamma[0];
    float alpha = 1.0f / (1.0f + __expf(-gv));
    float* out1 = out;
    float* out2 = out + (size_t)Bn * Cn * Ln;
#pragma unroll
    for (int mt = 0; mt < 2; mt++)
#pragma unroll
        for (int nt = 0; nt < 8; nt++) {
            int rc = c0 + warp_m * 32 + mt * 16 + (lane >> 2);
            int cl = l0 + warp_n * 64 + nt * 8 + 2 * (lane & 3);
            float bv0 = bo[rc], bv1 = bo[rc + 8];
            size_t base0 = (size_t)b * Cn * Ln + (size_t)rc * Ln + cl;
            size_t base1 = (size_t)b * Cn * Ln + (size_t)(rc + 8) * Ln + cl;
            float2 v0 = make_float2(acc[mt][nt][0] + bv0, acc[mt][nt][1] + bv0);
            float2 v1 = make_float2(acc[mt][nt][2] + bv1, acc[mt][nt][3] + bv1);
            float2 x0 = *(const float2*)&x[base0];
            float2 x1 = *(const float2*)&x[base1];
            *(float2*)&out2[base0] = v0;
            *(float2*)&out2[base1] = v1;
            float2 o0 = make_float2((1.f - alpha) * x0.x + alpha * v0.x,
                                    (1.f - alpha) * x0.y + alpha * v0.y);
            float2 o1 = make_float2((1.f - alpha) * x1.x + alpha * v1.x,
                                    (1.f - alpha) * x1.y + alpha * v1.y);
            *(float2*)&out1[base0] = o0;
            *(float2*)&out1[base1] = o1;
        }
}

extern "C" void kernel_launch(void* const* d_in, const int* in_sizes, int n_in,
                              void* d_out, int out_size) {
    const float* x     = (const float*)d_in[0];
    const float* Wt    = (const float*)d_in[1];
    const float* bt    = (const float*)d_in[2];
    const float* Wp    = (const float*)d_in[3];
    const float* bp    = (const float*)d_in[4];
    const float* Wg    = (const float*)d_in[5];
    const float* bg    = (const float*)d_in[6];
    const float* Wo    = (const float*)d_in[7];
    const float* bo    = (const float*)d_in[8];
    const float* gamma = (const float*)d_in[9];
    float* out = (float*)d_out;

    cudaFuncSetAttribute(proj_mma, cudaFuncAttributeMaxDynamicSharedMemorySize, P_SMEM);
    cudaFuncSetAttribute(softstats_kernel, cudaFuncAttributeMaxDynamicSharedMemorySize, S_SMEM);
    cudaFuncSetAttribute(attn_fused, cudaFuncAttributeMaxDynamicSharedMemorySize, AT_SMEM);
    cudaFuncSetAttribute(final_mma, cudaFuncAttributeMaxDynamicSharedMemorySize, F_SMEM);

    proj_mma<<<dim3(Ln / 128, 3, Bn), 256, P_SMEM>>>(x, Wt, bt, Wp, bp, Wg, bg);
    softstats_kernel<<<dim3(Ln / 128, Bn), 256, S_SMEM>>>();
    transpose_scale_kernel<<<dim3(Ln / 32, CGn / 32, Bn), dim3(32, 8)>>>();
    attn_fused<<<dim3(Ln / 64, Bn), 256, AT_SMEM>>>();
    final_mma<<<dim3(Cn / 128, Ln / 128, Bn), 256, F_SMEM>>>(x, Wo, bo, gamma, out);
}